// round 4
// baseline (speedup 1.0000x reference)
#include <cuda_runtime.h>
#include <math.h>

#define BB 2
#define SS 2048
#define NCOND 2
#define STOK 2046
#define DD 512
#define HH 8
#define DHD 64
#define DI 2048
#define NL 6
#define VV 512
#define BS (BB*SS)   // 4096

// ---------------- scratch (device globals; no allocations allowed) ----------
__device__ float g_x[BS*DD];
__device__ float g_q[BS*DD];
__device__ float g_k[BS*DD];
__device__ float g_v[BS*DD];
__device__ float g_attn[BS*DD];
__device__ float g_res[BS*DD];
__device__ float g_out1[BS*DD];
__device__ float g_h[BS*DI];
__device__ float g_chordf[BS];
__device__ int   g_keypad[BS];

// ---------------- misc: keypad + chord factor --------------------------------
__global__ void k_misc(const int* __restrict__ toks, const float* __restrict__ ttc) {
    int idx = blockIdx.x * 256 + threadIdx.x;
    if (idx >= BS) return;
    int b = idx / SS, s = idx % SS;
    g_keypad[idx] = (s >= NCOND && toks[b*STOK + s - NCOND] == 0) ? 1 : 0;
    float t = (s < NCOND) ? ttc[b*STOK] : ttc[b*STOK + s - NCOND];
    g_chordf[idx] = 8.0f - t;
}

// ---------------- build x: cond MLP / embedding + pos ------------------------
__global__ void k_build_x(const int* __restrict__ toks, const float* __restrict__ cond,
                          const float* __restrict__ emb, const float* __restrict__ pos,
                          const float* __restrict__ W1, const float* __restrict__ b1,
                          const float* __restrict__ W2, const float* __restrict__ b2,
                          const float* __restrict__ nullc) {
    int blk = blockIdx.x;            // = b*SS + s
    int b = blk / SS, s = blk % SS;
    int t = threadIdx.x;             // 128 threads
    if (s < NCOND) {
        __shared__ float h1[256];
        float c = cond[b*NCOND + s];
        bool isn = isnan(c);
        if (!isn) {
            for (int o = t; o < 256; o += 128)
                h1[o] = fmaxf(c * W1[s*256 + o] + b1[s*256 + o], 0.f);
        }
        __syncthreads();
        for (int d = t; d < DD; d += 128) {
            float ce;
            if (isn) ce = nullc[s*DD + d];
            else {
                float acc = b2[s*DD + d];
                #pragma unroll 8
                for (int o = 0; o < 256; o++) acc += h1[o] * W2[(s*256 + o)*DD + d];
                ce = acc;
            }
            g_x[blk*DD + d] = ce + pos[s*DD + d];
        }
    } else {
        int tok = toks[b*STOK + s - NCOND];
        const float* e = emb + tok*DD;
        for (int d = t; d < DD; d += 128)
            g_x[blk*DD + d] = e[d] * 22.62741699796952f + pos[s*DD + d];
    }
}

// ---------------- generic 64x64 SGEMM with fused epilogues --------------------
// MODE 0: QKV permute store  out[((b*H+h)*S+s)*DH + d] = acc+bias
// MODE 1: out = acc + bias + res
// MODE 2: out = relu(acc+bias) + chordf[r]*ttcW[c] + ttcb[c]
// MODE 3: out = acc + bias
template<int MODE>
__global__ void gemm64(const float* __restrict__ A, const float* __restrict__ W,
                       const float* __restrict__ bias, const float* __restrict__ res,
                       float* __restrict__ out, int M, int N, int K,
                       const float* __restrict__ ttcW, const float* __restrict__ ttcb) {
    __shared__ float As[16][68];
    __shared__ float Ws[16][68];
    int t  = threadIdx.x;
    int tx = t & 15, ty = t >> 4;
    int m0 = blockIdx.y * 64, n0 = blockIdx.x * 64;
    float acc[4][4] = {};
    for (int k0 = 0; k0 < K; k0 += 16) {
        {
            int mr = t >> 2, kc = (t & 3) * 4;
            float4 av = *(const float4*)(A + (size_t)(m0 + mr)*K + k0 + kc);
            As[kc+0][mr] = av.x; As[kc+1][mr] = av.y;
            As[kc+2][mr] = av.z; As[kc+3][mr] = av.w;
            int kr = t >> 4, nc = (t & 15) * 4;
            *(float4*)(&Ws[kr][nc]) = *(const float4*)(W + (size_t)(k0 + kr)*N + n0 + nc);
        }
        __syncthreads();
        #pragma unroll
        for (int kk = 0; kk < 16; kk++) {
            float4 a = *(const float4*)(&As[kk][ty*4]);
            float4 w = *(const float4*)(&Ws[kk][tx*4]);
            float ar[4] = {a.x, a.y, a.z, a.w};
            float wr[4] = {w.x, w.y, w.z, w.w};
            #pragma unroll
            for (int ii = 0; ii < 4; ii++)
                #pragma unroll
                for (int jj = 0; jj < 4; jj++)
                    acc[ii][jj] += ar[ii] * wr[jj];
        }
        __syncthreads();
    }
    #pragma unroll
    for (int ii = 0; ii < 4; ii++) {
        int r = m0 + ty*4 + ii;
        #pragma unroll
        for (int jj = 0; jj < 4; jj++) {
            int c = n0 + tx*4 + jj;
            float v = acc[ii][jj] + bias[c];
            if (MODE == 0) {
                int b = r >> 11, s = r & 2047, h = c >> 6, d = c & 63;
                out[(((size_t)(b*HH + h))*SS + s)*DHD + d] = v;
            } else if (MODE == 1) {
                out[(size_t)r*N + c] = v + res[(size_t)r*N + c];
            } else if (MODE == 2) {
                out[(size_t)r*N + c] = fmaxf(v, 0.f) + g_chordf[r]*ttcW[c] + ttcb[c];
            } else {
                out[(size_t)r*N + c] = v;
            }
        }
    }
}

// ---------------- layernorm (one block per row of 512) ------------------------
__global__ void k_ln(const float* __restrict__ in, float* __restrict__ out,
                     const float* __restrict__ g, const float* __restrict__ bb) {
    int r = blockIdx.x, t = threadIdx.x;    // 128 threads
    float4 v = *(const float4*)(in + (size_t)r*DD + t*4);
    float s  = v.x + v.y + v.z + v.w;
    float ss = v.x*v.x + v.y*v.y + v.z*v.z + v.w*v.w;
    for (int m = 16; m; m >>= 1) {
        s  += __shfl_xor_sync(0xffffffffu, s,  m);
        ss += __shfl_xor_sync(0xffffffffu, ss, m);
    }
    __shared__ float sm[4], sm2[4];
    if ((t & 31) == 0) { sm[t>>5] = s; sm2[t>>5] = ss; }
    __syncthreads();
    s  = sm[0]  + sm[1]  + sm[2]  + sm[3];
    ss = sm2[0] + sm2[1] + sm2[2] + sm2[3];
    float mu  = s * (1.0f/DD);
    float var = ss * (1.0f/DD) - mu*mu;
    float inv = rsqrtf(var + 1e-6f);
    float4 gg = *(const float4*)(g  + t*4);
    float4 bv = *(const float4*)(bb + t*4);
    float4 o;
    o.x = (v.x - mu)*inv*gg.x + bv.x;
    o.y = (v.y - mu)*inv*gg.y + bv.y;
    o.z = (v.z - mu)*inv*gg.z + bv.z;
    o.w = (v.w - mu)*inv*gg.w + bv.w;
    *(float4*)(out + (size_t)r*DD + t*4) = o;
}

// ---------------- fused relative-position flash attention ---------------------
// grid: (S/64, H, B), 256 threads, dynamic smem 86272 B.
// Srel[i,j] (j<=i) = q_i . E[S-1+j-i]  -> in-tile Z[i,u]=q_i.E[base+u], u=jj-ii+63
#define ATT_SMEM (86272)
__global__ __launch_bounds__(256, 1)
void k_attn(const float* __restrict__ E) {
    extern __shared__ float smem[];
    float* QT = smem;                 // [64][68] q^T  : QT[d][i]
    float* KT = QT + 64*68;           // [64][68] k^T  : KT[d][j]   (alias: P^T[j][i])
    float* VS = KT + 64*68;           // [64][68] v    : VS[j][d]
    float* ET = VS + 64*68;           // [64][132] e^T : ET[d][u]   (alias: Z[i][u])
    int*   KP = (int*)(ET + 64*132);  // [64]

    int t  = threadIdx.x;
    int tx = t & 15, ty = t >> 4;
    int i0 = blockIdx.x * 64, h = blockIdx.y, b = blockIdx.z;
    const float* qg = g_q + ((size_t)(b*HH + h))*SS*DHD;
    const float* kg = g_k + ((size_t)(b*HH + h))*SS*DHD;
    const float* vg = g_v + ((size_t)(b*HH + h))*SS*DHD;

    #pragma unroll
    for (int c = 0; c < 4; c++) {
        int vid = t + 256*c; int row = vid >> 4; int d4 = (vid & 15)*4;
        float4 qv = *(const float4*)(qg + (size_t)(i0 + row)*DHD + d4);
        QT[(d4+0)*68 + row] = qv.x; QT[(d4+1)*68 + row] = qv.y;
        QT[(d4+2)*68 + row] = qv.z; QT[(d4+3)*68 + row] = qv.w;
    }

    float o[4][4] = {};
    float mrow[4] = {-1e30f, -1e30f, -1e30f, -1e30f};
    float lrow[4] = {};
    int nkt = (i0 >> 6) + 1;

    for (int kt = 0; kt < nkt; kt++) {
        int j0 = kt * 64;
        __syncthreads();   // protect previous P^T/V use before reload
        #pragma unroll
        for (int c = 0; c < 4; c++) {
            int vid = t + 256*c; int row = vid >> 4; int d4 = (vid & 15)*4;
            float4 kv = *(const float4*)(kg + (size_t)(j0 + row)*DHD + d4);
            KT[(d4+0)*68 + row] = kv.x; KT[(d4+1)*68 + row] = kv.y;
            KT[(d4+2)*68 + row] = kv.z; KT[(d4+3)*68 + row] = kv.w;
            *(float4*)(VS + row*68 + d4) = *(const float4*)(vg + (size_t)(j0 + row)*DHD + d4);
        }
        int base = (SS - 1) + j0 - i0 - 63;   // always >= 0
        #pragma unroll
        for (int c = 0; c < 8; c++) {
            int vid = t + 256*c; int u = vid >> 4; int d4 = (vid & 15)*4;
            int m = base + u;
            float4 ev = (m < SS) ? *(const float4*)(E + (size_t)m*DHD + d4)
                                 : make_float4(0.f, 0.f, 0.f, 0.f);
            ET[(d4+0)*132 + u] = ev.x; ET[(d4+1)*132 + u] = ev.y;
            ET[(d4+2)*132 + u] = ev.z; ET[(d4+3)*132 + u] = ev.w;
        }
        if (t < 64) KP[t] = g_keypad[b*SS + j0 + t];
        __syncthreads();

        // GEMM1: qk tile + Z band tile
        float aqk[4][4] = {};
        float az[4][8]  = {};
        #pragma unroll 4
        for (int d = 0; d < 64; d++) {
            float4 qf = *(const float4*)(QT + d*68 + ty*4);
            float4 kf = *(const float4*)(KT + d*68 + tx*4);
            float4 e0 = *(const float4*)(ET + d*132 + tx*8);
            float4 e1 = *(const float4*)(ET + d*132 + tx*8 + 4);
            float qa[4] = {qf.x, qf.y, qf.z, qf.w};
            float ka[4] = {kf.x, kf.y, kf.z, kf.w};
            float ea[8] = {e0.x, e0.y, e0.z, e0.w, e1.x, e1.y, e1.z, e1.w};
            #pragma unroll
            for (int ii = 0; ii < 4; ii++) {
                #pragma unroll
                for (int jj = 0; jj < 4; jj++) aqk[ii][jj] += qa[ii]*ka[jj];
                #pragma unroll
                for (int uu = 0; uu < 8; uu++) az[ii][uu] += qa[ii]*ea[uu];
            }
        }
        __syncthreads();                 // everyone done reading ET, KT
        #pragma unroll
        for (int ii = 0; ii < 4; ii++)
            #pragma unroll
            for (int uu = 0; uu < 8; uu++)
                ET[(ty*4 + ii)*132 + tx*8 + uu] = az[ii][uu];   // Z[i][u]
        __syncthreads();

        // logits + online softmax; write P^T into KT region
        #pragma unroll
        for (int ii = 0; ii < 4; ii++) {
            int il = ty*4 + ii; int i = i0 + il;
            float lg[4];
            #pragma unroll
            for (int jj = 0; jj < 4; jj++) {
                int jl = tx*4 + jj; int j = j0 + jl;
                int u = jl - il + 63;
                bool valid = (j <= i) && (KP[jl] == 0);
                lg[jj] = valid ? (aqk[ii][jj] + ET[il*132 + u]) * 0.125f : -1e30f;
            }
            float tm = fmaxf(fmaxf(lg[0], lg[1]), fmaxf(lg[2], lg[3]));
            tm = fmaxf(tm, __shfl_xor_sync(0xffffffffu, tm, 1));
            tm = fmaxf(tm, __shfl_xor_sync(0xffffffffu, tm, 2));
            tm = fmaxf(tm, __shfl_xor_sync(0xffffffffu, tm, 4));
            tm = fmaxf(tm, __shfl_xor_sync(0xffffffffu, tm, 8));
            float mn = fmaxf(mrow[ii], tm);
            float corr = __expf(mrow[ii] - mn);
            float rs = 0.f;
            #pragma unroll
            for (int jj = 0; jj < 4; jj++) {
                float p = __expf(lg[jj] - mn);
                KT[(tx*4 + jj)*68 + il] = p;       // P^T[j][i]
                rs += p;
            }
            rs += __shfl_xor_sync(0xffffffffu, rs, 1);
            rs += __shfl_xor_sync(0xffffffffu, rs, 2);
            rs += __shfl_xor_sync(0xffffffffu, rs, 4);
            rs += __shfl_xor_sync(0xffffffffu, rs, 8);
            lrow[ii] = lrow[ii]*corr + rs;
            mrow[ii] = mn;
            #pragma unroll
            for (int dd = 0; dd < 4; dd++) o[ii][dd] *= corr;
        }
        __syncthreads();

        // GEMM2: O += P V
        #pragma unroll 4
        for (int j = 0; j < 64; j++) {
            float4 pf = *(const float4*)(KT + j*68 + ty*4);
            float4 vf = *(const float4*)(VS + j*68 + tx*4);
            float pa[4] = {pf.x, pf.y, pf.z, pf.w};
            float va[4] = {vf.x, vf.y, vf.z, vf.w};
            #pragma unroll
            for (int ii = 0; ii < 4; ii++)
                #pragma unroll
                for (int dd = 0; dd < 4; dd++)
                    o[ii][dd] += pa[ii]*va[dd];
        }
    }

    #pragma unroll
    for (int ii = 0; ii < 4; ii++) {
        int i = i0 + ty*4 + ii;
        float inv = 1.0f / lrow[ii];
        #pragma unroll
        for (int dd = 0; dd < 4; dd++)
            g_attn[((size_t)(b*SS + i))*DD + h*DHD + tx*4 + dd] = o[ii][dd]*inv;
    }
}

// ---------------- host orchestration -----------------------------------------
extern "C" void kernel_launch(void* const* d_in, const int* in_sizes, int n_in,
                              void* d_out, int out_size) {
    const int*   toks   = (const int*)  d_in[0];
    const float* cond   = (const float*)d_in[1];
    const float* ttc    = (const float*)d_in[2];
    const float* emb    = (const float*)d_in[3];
    const float* pos    = (const float*)d_in[4];
    const float* cW1    = (const float*)d_in[5];
    const float* cb1    = (const float*)d_in[6];
    const float* cW2    = (const float*)d_in[7];
    const float* cb2    = (const float*)d_in[8];
    const float* nullc  = (const float*)d_in[9];
    const float* ttcW   = (const float*)d_in[10];
    const float* ttcb   = (const float*)d_in[11];
    const float* Wq     = (const float*)d_in[12];
    const float* Wk     = (const float*)d_in[13];
    const float* Wv     = (const float*)d_in[14];
    const float* Wo     = (const float*)d_in[15];
    const float* bq     = (const float*)d_in[16];
    const float* bk     = (const float*)d_in[17];
    const float* bv     = (const float*)d_in[18];
    const float* bo     = (const float*)d_in[19];
    const float* E      = (const float*)d_in[20];
    const float* fW1    = (const float*)d_in[21];
    const float* fb1    = (const float*)d_in[22];
    const float* fW2    = (const float*)d_in[23];
    const float* fb2    = (const float*)d_in[24];
    const float* ln1g   = (const float*)d_in[25];
    const float* ln1b   = (const float*)d_in[26];
    const float* ln2g   = (const float*)d_in[27];
    const float* ln2b   = (const float*)d_in[28];
    const float* fcW    = (const float*)d_in[29];
    const float* fcb    = (const float*)d_in[30];
    float* out = (float*)d_out;

    float *px, *pq, *pk, *pv, *pattn, *pres, *pout1, *ph;
    cudaGetSymbolAddress((void**)&px,    g_x);
    cudaGetSymbolAddress((void**)&pq,    g_q);
    cudaGetSymbolAddress((void**)&pk,    g_k);
    cudaGetSymbolAddress((void**)&pv,    g_v);
    cudaGetSymbolAddress((void**)&pattn, g_attn);
    cudaGetSymbolAddress((void**)&pres,  g_res);
    cudaGetSymbolAddress((void**)&pout1, g_out1);
    cudaGetSymbolAddress((void**)&ph,    g_h);

    cudaFuncSetAttribute(k_attn, cudaFuncAttributeMaxDynamicSharedMemorySize, ATT_SMEM);

    k_misc<<<(BS + 255)/256, 256>>>(toks, ttc);
    k_build_x<<<BS, 128>>>(toks, cond, emb, pos, cW1, cb1, cW2, cb2, nullc);

    dim3 gP(DD/64, BS/64);      // (8, 64)
    dim3 gF1(DI/64, BS/64);     // (32, 64)
    dim3 gA(SS/64, HH, BB);     // (32, 8, 2)

    for (int l = 0; l < NL; l++) {
        gemm64<0><<<gP, 256>>>(px, Wq + (size_t)l*DD*DD, bq + l*DD, nullptr, pq, BS, DD, DD, nullptr, nullptr);
        gemm64<0><<<gP, 256>>>(px, Wk + (size_t)l*DD*DD, bk + l*DD, nullptr, pk, BS, DD, DD, nullptr, nullptr);
        gemm64<0><<<gP, 256>>>(px, Wv + (size_t)l*DD*DD, bv + l*DD, nullptr, pv, BS, DD, DD, nullptr, nullptr);
        k_attn<<<gA, 256, ATT_SMEM>>>(E + (size_t)l*SS*DHD);
        gemm64<1><<<gP, 256>>>(pattn, Wo + (size_t)l*DD*DD, bo + l*DD, px, pres, BS, DD, DD, nullptr, nullptr);
        k_ln<<<BS, 128>>>(pres, pout1, ln1g + l*DD, ln1b + l*DD);
        gemm64<2><<<gF1, 256>>>(pout1, fW1 + (size_t)l*DD*DI, fb1 + l*DI, nullptr, ph, BS, DI, DD, ttcW, ttcb);
        gemm64<1><<<gP, 256>>>(ph, fW2 + (size_t)l*DI*DD, fb2 + l*DD, pout1, pres, BS, DD, DI, nullptr, nullptr);
        k_ln<<<BS, 128>>>(pres, px, ln2g + l*DD, ln2b + l*DD);
    }
    gemm64<3><<<dim3(VV/64, BS/64), 256>>>(px, fcW, fcb, nullptr, out, BS, VV, DD, nullptr, nullptr);
}

// round 6
// speedup vs baseline: 1.4481x; 1.4481x over previous
#include <cuda_runtime.h>
#include <cuda_bf16.h>
#include <math.h>
#include <stdint.h>

#define BB 2
#define SS 2048
#define NCOND 2
#define STOK 2046
#define DD 512
#define HH 8
#define DHD 64
#define DI 2048
#define NL 6
#define VV 512
#define BS (BB*SS)   // 4096

// ---------------- scratch (device globals) -----------------------------------
__device__ float g_x[BS*DD];
__device__ float g_q[BS*DD];
__device__ float g_k[BS*DD];
__device__ float g_v[BS*DD];
__device__ float g_res[BS*DD];
__device__ float g_out1[BS*DD];
__device__ float g_chordf[BS];
__device__ int   g_keypad[BS];

// bf16 hi/lo activations, plain row-major [rows][K]
__device__ __align__(256) __nv_bfloat16 g_xh[BS*DD],  g_xl[BS*DD];
__device__ __align__(256) __nv_bfloat16 g_o1h[BS*DD], g_o1l[BS*DD];
__device__ __align__(256) __nv_bfloat16 g_ah[BS*DD],  g_al[BS*DD];
__device__ __align__(256) __nv_bfloat16 g_hh[(size_t)BS*DI], g_hl[(size_t)BS*DI];

// bf16 hi/lo weights, row-major [N][K] (B operand of C=A*B^T)
__device__ __align__(256) __nv_bfloat16 w_qh[(size_t)NL*DD*DD], w_ql[(size_t)NL*DD*DD];
__device__ __align__(256) __nv_bfloat16 w_kh[(size_t)NL*DD*DD], w_kl[(size_t)NL*DD*DD];
__device__ __align__(256) __nv_bfloat16 w_vh[(size_t)NL*DD*DD], w_vl[(size_t)NL*DD*DD];
__device__ __align__(256) __nv_bfloat16 w_oh[(size_t)NL*DD*DD], w_ol[(size_t)NL*DD*DD];
__device__ __align__(256) __nv_bfloat16 w_f1h[(size_t)NL*DD*DI], w_f1l[(size_t)NL*DD*DI];
__device__ __align__(256) __nv_bfloat16 w_f2h[(size_t)NL*DI*DD], w_f2l[(size_t)NL*DI*DD];
__device__ __align__(256) __nv_bfloat16 w_fch[(size_t)DD*VV],    w_fcl[(size_t)DD*VV];

// ---------------- helpers -----------------------------------------------------
__device__ __forceinline__ uint32_t smem_u32(const void* p){
    uint32_t a;
    asm("{ .reg .u64 t; cvta.to.shared.u64 t, %1; cvt.u32.u64 %0, t; }" : "=r"(a) : "l"(p));
    return a;
}
__device__ __forceinline__ void cp_async16(uint32_t s, const void* g){
    asm volatile("cp.async.cg.shared.global [%0], [%1], 16;\n"
        :: "r"(s), "l"(__cvta_generic_to_global(g)) : "memory");
}
#define CP_COMMIT() asm volatile("cp.async.commit_group;\n":::"memory")
#define CP_WAIT1()  asm volatile("cp.async.wait_group 1;\n":::"memory")
#define CP_WAIT0()  asm volatile("cp.async.wait_group 0;\n":::"memory")

__device__ __forceinline__ void mma16816(float* c, uint32_t a0, uint32_t a1, uint32_t a2, uint32_t a3,
                                         uint32_t b0, uint32_t b1){
    asm volatile(
        "mma.sync.aligned.m16n8k16.row.col.f32.bf16.bf16.f32 "
        "{%0,%1,%2,%3}, {%4,%5,%6,%7}, {%8,%9}, {%0,%1,%2,%3};"
        : "+f"(c[0]), "+f"(c[1]), "+f"(c[2]), "+f"(c[3])
        : "r"(a0), "r"(a1), "r"(a2), "r"(a3), "r"(b0), "r"(b1));
}
__device__ __forceinline__ unsigned pkb(__nv_bfloat16 a, __nv_bfloat16 b){
    __nv_bfloat162 t(a, b);
    return *reinterpret_cast<unsigned*>(&t);
}
__device__ __forceinline__ void split1(float v, __nv_bfloat16& h, __nv_bfloat16& l){
    h = __float2bfloat16(v);
    l = __float2bfloat16(v - __bfloat162float(h));
}
__device__ __forceinline__ void store_split4(char* ph, char* pl, size_t boff,
                                             float v0, float v1, float v2, float v3){
    __nv_bfloat16 h0,h1,h2,h3,l0,l1,l2,l3;
    split1(v0,h0,l0); split1(v1,h1,l1); split1(v2,h2,l2); split1(v3,h3,l3);
    uint2 uh; uh.x = pkb(h0,h1); uh.y = pkb(h2,h3);
    uint2 ul; ul.x = pkb(l0,l1); ul.y = pkb(l2,l3);
    *(uint2*)(ph + boff) = uh;
    *(uint2*)(pl + boff) = ul;
}
__device__ __forceinline__ void store_split2(char* ph, char* pl, size_t boff, float v0, float v1){
    __nv_bfloat16 h0,h1,l0,l1;
    split1(v0,h0,l0); split1(v1,h1,l1);
    *(unsigned*)(ph + boff) = pkb(h0,h1);
    *(unsigned*)(pl + boff) = pkb(l0,l1);
}

// ---------------- misc --------------------------------------------------------
__global__ void k_misc(const int* __restrict__ toks, const float* __restrict__ ttc) {
    int idx = blockIdx.x * 256 + threadIdx.x;
    if (idx >= BS) return;
    int b = idx / SS, s = idx % SS;
    g_keypad[idx] = (s >= NCOND && toks[b*STOK + s - NCOND] == 0) ? 1 : 0;
    float t = (s < NCOND) ? ttc[b*STOK] : ttc[b*STOK + s - NCOND];
    g_chordf[idx] = 8.0f - t;
}

__global__ void k_build_x(const int* __restrict__ toks, const float* __restrict__ cond,
                          const float* __restrict__ emb, const float* __restrict__ pos,
                          const float* __restrict__ W1, const float* __restrict__ b1,
                          const float* __restrict__ W2, const float* __restrict__ b2,
                          const float* __restrict__ nullc) {
    int blk = blockIdx.x;            // = b*SS + s
    int b = blk / SS, s = blk % SS;
    int t = threadIdx.x;             // 128 threads; cols 4t..4t+3
    int d0 = t*4;
    float v[4];
    if (s < NCOND) {
        __shared__ float h1[256];
        float c = cond[b*NCOND + s];
        bool isn = isnan(c);
        if (!isn) {
            for (int o = t; o < 256; o += 128)
                h1[o] = fmaxf(c * W1[s*256 + o] + b1[s*256 + o], 0.f);
        }
        __syncthreads();
        #pragma unroll
        for (int j = 0; j < 4; j++) {
            int d = d0 + j;
            float ce;
            if (isn) ce = nullc[s*DD + d];
            else {
                float acc = b2[s*DD + d];
                #pragma unroll 8
                for (int o = 0; o < 256; o++) acc += h1[o] * W2[(s*256 + o)*DD + d];
                ce = acc;
            }
            v[j] = ce + pos[s*DD + d];
        }
    } else {
        int tok = toks[b*STOK + s - NCOND];
        float4 e = *(const float4*)(emb + (size_t)tok*DD + d0);
        float4 p = *(const float4*)(pos + (size_t)s*DD + d0);
        const float SC = 22.62741699796952f;
        v[0] = e.x*SC + p.x; v[1] = e.y*SC + p.y; v[2] = e.z*SC + p.z; v[3] = e.w*SC + p.w;
    }
    *(float4*)(&g_x[(size_t)blk*DD + d0]) = make_float4(v[0], v[1], v[2], v[3]);
    store_split4((char*)g_xh, (char*)g_xl, ((size_t)blk*DD + d0)*2, v[0], v[1], v[2], v[3]);
}

// fp32 weight [K][N] (used as x@W) -> row-major [N][K] hi/lo
__global__ void cvt_w(const float* __restrict__ W, __nv_bfloat16* __restrict__ Bh,
                      __nv_bfloat16* __restrict__ Bl, int K, int N) {
    int kt = blockIdx.x, nt = blockIdx.y, l = blockIdx.z;
    const float* Wl = W + (size_t)l*K*N;
    char* ph = (char*)Bh + (size_t)l*N*K*2;
    char* pl = (char*)Bl + (size_t)l*N*K*2;
    __shared__ float ts[64][129];
    int tid = threadIdx.x;            // 256
    int k0 = kt*64, n0 = nt*128;
    #pragma unroll
    for (int r = 0; r < 8; r++) {
        int i = tid + r*256;
        int kl = i >> 5, n4 = (i & 31) * 4;
        float4 x = *(const float4*)(Wl + (size_t)(k0 + kl)*N + n0 + n4);
        ts[kl][n4] = x.x; ts[kl][n4+1] = x.y; ts[kl][n4+2] = x.z; ts[kl][n4+3] = x.w;
    }
    __syncthreads();
    #pragma unroll
    for (int r = 0; r < 8; r++) {
        int i = tid + r*256;
        int nl = i >> 4, kc = (i & 15) * 4;
        size_t boff = ((size_t)(n0 + nl)*K + k0 + kc)*2;
        store_split4(ph, pl, boff, ts[kc][nl], ts[kc+1][nl], ts[kc+2][nl], ts[kc+3][nl]);
    }
}

// ---------------- mma.sync GEMM (3-term bf16 split, fp32 accum) ---------------
// C[m][n] = sum_k A[m][k]*B[n][k].
// MODE 0: QKV permute store. 1: acc+bias+res (fp32 out). 2: relu(acc+bias)+chord -> hi/lo. 3: acc+bias.
// CTA 128x128, 8 warps (warp_m = wid&3 -> 32 rows, warp_n = wid>>2 -> 64 cols).
// Smem stage: 4 matrices (Ah,Al,Bh,Bl) of 128 rows x 64 bf16, 144B padded pitch.
#define GPITCH 144
#define GMAT   18432              // 128*144
#define GSTAGE 73728              // 4*GMAT
#define GEMM_SMEM (2*GSTAGE)      // 147456

template<int MODE>
__global__ __launch_bounds__(256, 1)
void mma_gemm(const __nv_bfloat16* __restrict__ Ah, const __nv_bfloat16* __restrict__ Al,
              const __nv_bfloat16* __restrict__ Bh, const __nv_bfloat16* __restrict__ Bl,
              const float* __restrict__ bias, const float* __restrict__ res,
              float* __restrict__ out, __nv_bfloat16* __restrict__ outH,
              __nv_bfloat16* __restrict__ outL,
              int K, int Ntot, const float* __restrict__ ttcW, const float* __restrict__ ttcb)
{
    extern __shared__ char smem[];
    uint32_t sbase = smem_u32(smem);
    int tid = threadIdx.x, wid = tid >> 5, lane = tid & 31;
    int g = lane >> 2, t4 = lane & 3;
    int wm = wid & 3, wn = wid >> 2;
    int mt = blockIdx.y, nt = blockIdx.x;
    int mG = mt*128, nG = nt*128;
    int KT = K >> 6;

    // loader assignment: mat = tid>>6 (0:Ah 1:Al 2:Bh 3:Bl); fixed chunk, rows r0+8i
    int mymat = tid >> 6, sub = tid & 63;
    int lr0 = sub >> 3, lch = sub & 7;
    const char* matp = (mymat == 0) ? (const char*)Ah : (mymat == 1) ? (const char*)Al
                     : (mymat == 2) ? (const char*)Bh : (const char*)Bl;
    int rowG = (mymat < 2) ? mG : nG;
    const char* srcbase = matp + ((size_t)(rowG + lr0) * K + lch*8) * 2;
    uint32_t dstbase = sbase + mymat*GMAT + lr0*GPITCH + lch*16;
    size_t srcstep = (size_t)8*K*2;

    auto load_stage = [&](int kb){
        uint32_t d = dstbase + (kb&1)*GSTAGE;
        const char* s = srcbase + (size_t)kb*128;   // kb*64 cols * 2B
        #pragma unroll
        for (int i = 0; i < 16; i++){
            cp_async16(d, s);
            d += 8*GPITCH; s += srcstep;
        }
        CP_COMMIT();
    };

    load_stage(0);
    if (KT > 1) load_stage(1);

    float acc[2][8][4] = {};
    int ar0 = wm*32, bn0 = wn*64;

    for (int kb = 0; kb < KT; kb++){
        if (kb + 1 < KT) CP_WAIT1(); else CP_WAIT0();
        __syncthreads();
        const char* st = smem + (size_t)(kb&1)*GSTAGE;
        const char* sAh = st;
        const char* sAl = st + GMAT;
        const char* sBh = st + 2*GMAT;
        const char* sBl = st + 3*GMAT;
        #pragma unroll
        for (int ks = 0; ks < 4; ks++){
            int cw  = (ks*8 + t4)*4;    // byte offset of col-pair t4 in this k-step
            int cw4 = cw + 16;
            uint32_t bh0[8], bh1[8], bl0[8], bl1[8];
            #pragma unroll
            for (int j = 0; j < 8; j++){
                int nr = (bn0 + j*8 + g)*GPITCH;
                bh0[j] = *(const uint32_t*)(sBh + nr + cw);
                bh1[j] = *(const uint32_t*)(sBh + nr + cw4);
                bl0[j] = *(const uint32_t*)(sBl + nr + cw);
                bl1[j] = *(const uint32_t*)(sBl + nr + cw4);
            }
            #pragma unroll
            for (int mi = 0; mi < 2; mi++){
                int r0 = (ar0 + mi*16 + g)*GPITCH;
                int r8 = r0 + 8*GPITCH;
                uint32_t ah0 = *(const uint32_t*)(sAh + r0 + cw);
                uint32_t ah1 = *(const uint32_t*)(sAh + r8 + cw);
                uint32_t ah2 = *(const uint32_t*)(sAh + r0 + cw4);
                uint32_t ah3 = *(const uint32_t*)(sAh + r8 + cw4);
                uint32_t al0 = *(const uint32_t*)(sAl + r0 + cw);
                uint32_t al1 = *(const uint32_t*)(sAl + r8 + cw);
                uint32_t al2 = *(const uint32_t*)(sAl + r0 + cw4);
                uint32_t al3 = *(const uint32_t*)(sAl + r8 + cw4);
                #pragma unroll
                for (int j = 0; j < 8; j++){
                    mma16816(acc[mi][j], ah0, ah1, ah2, ah3, bh0[j], bh1[j]);
                    mma16816(acc[mi][j], ah0, ah1, ah2, ah3, bl0[j], bl1[j]);
                    mma16816(acc[mi][j], al0, al1, al2, al3, bh0[j], bh1[j]);
                }
            }
        }
        __syncthreads();
        if (kb + 2 < KT) load_stage(kb + 2);
    }

    // epilogue
    #pragma unroll
    for (int mi = 0; mi < 2; mi++){
        #pragma unroll
        for (int j = 0; j < 8; j++){
            int n = nG + bn0 + j*8 + 2*t4;
            int mA = mG + ar0 + mi*16 + g;      // rows for c0,c1
            int mB = mA + 8;                    // rows for c2,c3
            float c0 = acc[mi][j][0], c1 = acc[mi][j][1];
            float c2 = acc[mi][j][2], c3 = acc[mi][j][3];
            float bx = bias[n], by = bias[n+1];
            if (MODE == 0) {
                int hh_ = n >> 6, dd_ = n & 63;
                int bA = mA >> 11, sA = mA & 2047;
                int bB = mB >> 11, sB = mB & 2047;
                *(float2*)(out + (((size_t)(bA*HH + hh_)*SS + sA) << 6) + dd_) = make_float2(c0+bx, c1+by);
                *(float2*)(out + (((size_t)(bB*HH + hh_)*SS + sB) << 6) + dd_) = make_float2(c2+bx, c3+by);
            } else if (MODE == 1) {
                float2 rA = *(const float2*)(res + (size_t)mA*Ntot + n);
                float2 rB = *(const float2*)(res + (size_t)mB*Ntot + n);
                *(float2*)(out + (size_t)mA*Ntot + n) = make_float2(c0+bx+rA.x, c1+by+rA.y);
                *(float2*)(out + (size_t)mB*Ntot + n) = make_float2(c2+bx+rB.x, c3+by+rB.y);
            } else if (MODE == 3) {
                *(float2*)(out + (size_t)mA*Ntot + n) = make_float2(c0+bx, c1+by);
                *(float2*)(out + (size_t)mB*Ntot + n) = make_float2(c2+bx, c3+by);
            } else { // MODE 2
                float twx = ttcW[n], twy = ttcW[n+1];
                float tbx = ttcb[n], tby = ttcb[n+1];
                float cfA = g_chordf[mA], cfB = g_chordf[mB];
                float v0 = fmaxf(c0+bx, 0.f) + cfA*twx + tbx;
                float v1 = fmaxf(c1+by, 0.f) + cfA*twy + tby;
                float v2 = fmaxf(c2+bx, 0.f) + cfB*twx + tbx;
                float v3 = fmaxf(c3+by, 0.f) + cfB*twy + tby;
                store_split2((char*)outH, (char*)outL, ((size_t)mA*Ntot + n)*2, v0, v1);
                store_split2((char*)outH, (char*)outL, ((size_t)mB*Ntot + n)*2, v2, v3);
            }
        }
    }
}

// ---------------- layernorm (+ bf16 hi/lo emit) -------------------------------
__global__ void k_ln(const float* __restrict__ in, float* __restrict__ out,
                     const float* __restrict__ g, const float* __restrict__ bb,
                     __nv_bfloat16* __restrict__ oh, __nv_bfloat16* __restrict__ ol) {
    int r = blockIdx.x, t = threadIdx.x;    // 128 threads
    float4 v = *(const float4*)(in + (size_t)r*DD + t*4);
    float s  = v.x + v.y + v.z + v.w;
    float ss = v.x*v.x + v.y*v.y + v.z*v.z + v.w*v.w;
    for (int m = 16; m; m >>= 1) {
        s  += __shfl_xor_sync(0xffffffffu, s,  m);
        ss += __shfl_xor_sync(0xffffffffu, ss, m);
    }
    __shared__ float sm[4], sm2[4];
    if ((t & 31) == 0) { sm[t>>5] = s; sm2[t>>5] = ss; }
    __syncthreads();
    s  = sm[0]  + sm[1]  + sm[2]  + sm[3];
    ss = sm2[0] + sm2[1] + sm2[2] + sm2[3];
    float mu  = s * (1.0f/DD);
    float var = ss * (1.0f/DD) - mu*mu;
    float inv = rsqrtf(var + 1e-6f);
    float4 gg = *(const float4*)(g  + t*4);
    float4 bv = *(const float4*)(bb + t*4);
    float4 o;
    o.x = (v.x - mu)*inv*gg.x + bv.x;
    o.y = (v.y - mu)*inv*gg.y + bv.y;
    o.z = (v.z - mu)*inv*gg.z + bv.z;
    o.w = (v.w - mu)*inv*gg.w + bv.w;
    *(float4*)(out + (size_t)r*DD + t*4) = o;
    store_split4((char*)oh, (char*)ol, ((size_t)r*DD + t*4)*2, o.x, o.y, o.z, o.w);
}

// ---------------- fused rel-pos flash attention (fp32) ------------------------
#define ATT_SMEM (86272)
__global__ __launch_bounds__(256, 1)
void k_attn(const float* __restrict__ E) {
    extern __shared__ float fsm[];
    float* QT = fsm;                  // [64][68] q^T
    float* KT = QT + 64*68;           // [64][68] k^T (alias P^T)
    float* VS = KT + 64*68;           // [64][68] v
    float* ET = VS + 64*68;           // [64][132] e^T (alias Z)
    int*   KP = (int*)(ET + 64*132);  // [64]

    int t  = threadIdx.x;
    int tx = t & 15, ty = t >> 4;
    int i0 = blockIdx.x * 64, h = blockIdx.y, b = blockIdx.z;
    const float* qg = g_q + ((size_t)(b*HH + h))*SS*DHD;
    const float* kg = g_k + ((size_t)(b*HH + h))*SS*DHD;
    const float* vg = g_v + ((size_t)(b*HH + h))*SS*DHD;

    #pragma unroll
    for (int c = 0; c < 4; c++) {
        int vid = t + 256*c; int row = vid >> 4; int d4 = (vid & 15)*4;
        float4 qv = *(const float4*)(qg + (size_t)(i0 + row)*DHD + d4);
        QT[(d4+0)*68 + row] = qv.x; QT[(d4+1)*68 + row] = qv.y;
        QT[(d4+2)*68 + row] = qv.z; QT[(d4+3)*68 + row] = qv.w;
    }

    float o[4][4] = {};
    float mrow[4] = {-1e30f, -1e30f, -1e30f, -1e30f};
    float lrow[4] = {};
    int nkt = (i0 >> 6) + 1;

    for (int kt = 0; kt < nkt; kt++) {
        int j0 = kt * 64;
        __syncthreads();
        #pragma unroll
        for (int c = 0; c < 4; c++) {
            int vid = t + 256*c; int row = vid >> 4; int d4 = (vid & 15)*4;
            float4 kv = *(const float4*)(kg + (size_t)(j0 + row)*DHD + d4);
            KT[(d4+0)*68 + row] = kv.x; KT[(d4+1)*68 + row] = kv.y;
            KT[(d4+2)*68 + row] = kv.z; KT[(d4+3)*68 + row] = kv.w;
            *(float4*)(VS + row*68 + d4) = *(const float4*)(vg + (size_t)(j0 + row)*DHD + d4);
        }
        int base = (SS - 1) + j0 - i0 - 63;
        #pragma unroll
        for (int c = 0; c < 8; c++) {
            int vid = t + 256*c; int u = vid >> 4; int d4 = (vid & 15)*4;
            int m = base + u;
            float4 ev = (m < SS) ? *(const float4*)(E + (size_t)m*DHD + d4)
                                 : make_float4(0.f, 0.f, 0.f, 0.f);
            ET[(d4+0)*132 + u] = ev.x; ET[(d4+1)*132 + u] = ev.y;
            ET[(d4+2)*132 + u] = ev.z; ET[(d4+3)*132 + u] = ev.w;
        }
        if (t < 64) KP[t] = g_keypad[b*SS + j0 + t];
        __syncthreads();

        float aqk[4][4] = {};
        float az[4][8]  = {};
        #pragma unroll 4
        for (int d = 0; d < 64; d++) {
            float4 qf = *(const float4*)(QT + d*68 + ty*4);
            float4 kf = *(const float4*)(KT + d*68 + tx*4);
            float4 e0 = *(const float4*)(ET + d*132 + tx*8);
            float4 e1 = *(const float4*)(ET + d*132 + tx*8 + 4);
            float qa[4] = {qf.x, qf.y, qf.z, qf.w};
            float ka[4] = {kf.x, kf.y, kf.z, kf.w};
            float ea[8] = {e0.x, e0.y, e0.z, e0.w, e1.x, e1.y, e1.z, e1.w};
            #pragma unroll
            for (int ii = 0; ii < 4; ii++) {
                #pragma unroll
                for (int jj = 0; jj < 4; jj++) aqk[ii][jj] += qa[ii]*ka[jj];
                #pragma unroll
                for (int uu = 0; uu < 8; uu++) az[ii][uu] += qa[ii]*ea[uu];
            }
        }
        __syncthreads();
        #pragma unroll
        for (int ii = 0; ii < 4; ii++)
            #pragma unroll
            for (int uu = 0; uu < 8; uu++)
                ET[(ty*4 + ii)*132 + tx*8 + uu] = az[ii][uu];
        __syncthreads();

        #pragma unroll
        for (int ii = 0; ii < 4; ii++) {
            int il = ty*4 + ii; int i = i0 + il;
            float lg[4];
            #pragma unroll
            for (int jj = 0; jj < 4; jj++) {
                int jl = tx*4 + jj; int j = j0 + jl;
                int u = jl - il + 63;
                bool valid = (j <= i) && (KP[jl] == 0);
                lg[jj] = valid ? (aqk[ii][jj] + ET[il*132 + u]) * 0.125f : -1e30f;
            }
            float tm = fmaxf(fmaxf(lg[0], lg[1]), fmaxf(lg[2], lg[3]));
            tm = fmaxf(tm, __shfl_xor_sync(0xffffffffu, tm, 1));
            tm = fmaxf(tm, __shfl_xor_sync(0xffffffffu, tm, 2));
            tm = fmaxf(tm, __shfl_xor_sync(0xffffffffu, tm, 4));
            tm = fmaxf(tm, __shfl_xor_sync(0xffffffffu, tm, 8));
            float mn = fmaxf(mrow[ii], tm);
            float corr = __expf(mrow[ii] - mn);
            float rs = 0.f;
            #pragma unroll
            for (int jj = 0; jj < 4; jj++) {
                float p = __expf(lg[jj] - mn);
                KT[(tx*4 + jj)*68 + il] = p;
                rs += p;
            }
            rs += __shfl_xor_sync(0xffffffffu, rs, 1);
            rs += __shfl_xor_sync(0xffffffffu, rs, 2);
            rs += __shfl_xor_sync(0xffffffffu, rs, 4);
            rs += __shfl_xor_sync(0xffffffffu, rs, 8);
            lrow[ii] = lrow[ii]*corr + rs;
            mrow[ii] = mn;
            #pragma unroll
            for (int dd = 0; dd < 4; dd++) o[ii][dd] *= corr;
        }
        __syncthreads();

        #pragma unroll 4
        for (int j = 0; j < 64; j++) {
            float4 pf = *(const float4*)(KT + j*68 + ty*4);
            float4 vf = *(const float4*)(VS + j*68 + tx*4);
            float pa[4] = {pf.x, pf.y, pf.z, pf.w};
            float va[4] = {vf.x, vf.y, vf.z, vf.w};
            #pragma unroll
            for (int ii = 0; ii < 4; ii++)
                #pragma unroll
                for (int dd = 0; dd < 4; dd++)
                    o[ii][dd] += pa[ii]*va[dd];
        }
    }

    #pragma unroll
    for (int ii = 0; ii < 4; ii++) {
        int i = i0 + ty*4 + ii;
        float inv = 1.0f / lrow[ii];
        store_split4((char*)g_ah, (char*)g_al,
                     (((size_t)(b*SS + i))*DD + h*DHD + tx*4)*2,
                     o[ii][0]*inv, o[ii][1]*inv, o[ii][2]*inv, o[ii][3]*inv);
    }
}

// ---------------- host orchestration ------------------------------------------
extern "C" void kernel_launch(void* const* d_in, const int* in_sizes, int n_in,
                              void* d_out, int out_size) {
    const int*   toks   = (const int*)  d_in[0];
    const float* cond   = (const float*)d_in[1];
    const float* ttc    = (const float*)d_in[2];
    const float* emb    = (const float*)d_in[3];
    const float* pos    = (const float*)d_in[4];
    const float* cW1    = (const float*)d_in[5];
    const float* cb1    = (const float*)d_in[6];
    const float* cW2    = (const float*)d_in[7];
    const float* cb2    = (const float*)d_in[8];
    const float* nullc  = (const float*)d_in[9];
    const float* ttcW   = (const float*)d_in[10];
    const float* ttcb   = (const float*)d_in[11];
    const float* Wq     = (const float*)d_in[12];
    const float* Wk     = (const float*)d_in[13];
    const float* Wv     = (const float*)d_in[14];
    const float* Wo     = (const float*)d_in[15];
    const float* bq     = (const float*)d_in[16];
    const float* bk     = (const float*)d_in[17];
    const float* bv     = (const float*)d_in[18];
    const float* bo     = (const float*)d_in[19];
    const float* E      = (const float*)d_in[20];
    const float* fW1    = (const float*)d_in[21];
    const float* fb1    = (const float*)d_in[22];
    const float* fW2    = (const float*)d_in[23];
    const float* fb2    = (const float*)d_in[24];
    const float* ln1g   = (const float*)d_in[25];
    const float* ln1b   = (const float*)d_in[26];
    const float* ln2g   = (const float*)d_in[27];
    const float* ln2b   = (const float*)d_in[28];
    const float* fcW    = (const float*)d_in[29];
    const float* fcb    = (const float*)d_in[30];
    float* out = (float*)d_out;

    float *px, *pq, *pk, *pv, *pres, *pout1;
    cudaGetSymbolAddress((void**)&px,    g_x);
    cudaGetSymbolAddress((void**)&pq,    g_q);
    cudaGetSymbolAddress((void**)&pk,    g_k);
    cudaGetSymbolAddress((void**)&pv,    g_v);
    cudaGetSymbolAddress((void**)&pres,  g_res);
    cudaGetSymbolAddress((void**)&pout1, g_out1);
    __nv_bfloat16 *xh,*xl,*o1h,*o1l,*ah,*al,*hh,*hl;
    __nv_bfloat16 *qh,*ql,*kh,*kl,*vh,*vl,*oh,*ol,*f1h,*f1l,*f2h,*f2l,*fch,*fcl;
    cudaGetSymbolAddress((void**)&xh,  g_xh);  cudaGetSymbolAddress((void**)&xl,  g_xl);
    cudaGetSymbolAddress((void**)&o1h, g_o1h); cudaGetSymbolAddress((void**)&o1l, g_o1l);
    cudaGetSymbolAddress((void**)&ah,  g_ah);  cudaGetSymbolAddress((void**)&al,  g_al);
    cudaGetSymbolAddress((void**)&hh,  g_hh);  cudaGetSymbolAddress((void**)&hl,  g_hl);
    cudaGetSymbolAddress((void**)&qh,  w_qh);  cudaGetSymbolAddress((void**)&ql,  w_ql);
    cudaGetSymbolAddress((void**)&kh,  w_kh);  cudaGetSymbolAddress((void**)&kl,  w_kl);
    cudaGetSymbolAddress((void**)&vh,  w_vh);  cudaGetSymbolAddress((void**)&vl,  w_vl);
    cudaGetSymbolAddress((void**)&oh,  w_oh);  cudaGetSymbolAddress((void**)&ol,  w_ol);
    cudaGetSymbolAddress((void**)&f1h, w_f1h); cudaGetSymbolAddress((void**)&f1l, w_f1l);
    cudaGetSymbolAddress((void**)&f2h, w_f2h); cudaGetSymbolAddress((void**)&f2l, w_f2l);
    cudaGetSymbolAddress((void**)&fch, w_fch); cudaGetSymbolAddress((void**)&fcl, w_fcl);

    cudaFuncSetAttribute(k_attn, cudaFuncAttributeMaxDynamicSharedMemorySize, ATT_SMEM);
    cudaFuncSetAttribute(mma_gemm<0>, cudaFuncAttributeMaxDynamicSharedMemorySize, GEMM_SMEM);
    cudaFuncSetAttribute(mma_gemm<1>, cudaFuncAttributeMaxDynamicSharedMemorySize, GEMM_SMEM);
    cudaFuncSetAttribute(mma_gemm<2>, cudaFuncAttributeMaxDynamicSharedMemorySize, GEMM_SMEM);
    cudaFuncSetAttribute(mma_gemm<3>, cudaFuncAttributeMaxDynamicSharedMemorySize, GEMM_SMEM);

    k_misc<<<(BS + 255)/256, 256>>>(toks, ttc);
    k_build_x<<<BS, 128>>>(toks, cond, emb, pos, cW1, cb1, cW2, cb2, nullc);

    cvt_w<<<dim3(8, 4, NL),  256>>>(Wq,  qh,  ql,  DD, DD);
    cvt_w<<<dim3(8, 4, NL),  256>>>(Wk,  kh,  kl,  DD, DD);
    cvt_w<<<dim3(8, 4, NL),  256>>>(Wv,  vh,  vl,  DD, DD);
    cvt_w<<<dim3(8, 4, NL),  256>>>(Wo,  oh,  ol,  DD, DD);
    cvt_w<<<dim3(8, 16, NL), 256>>>(fW1, f1h, f1l, DD, DI);
    cvt_w<<<dim3(32, 4, NL), 256>>>(fW2, f2h, f2l, DI, DD);
    cvt_w<<<dim3(8, 4, 1),   256>>>(fcW, fch, fcl, DD, VV);

    dim3 gP(DD/128, BS/128);    // (4, 32)
    dim3 gF1(DI/128, BS/128);   // (16, 32)
    dim3 gA(SS/64, HH, BB);

    for (int l = 0; l < NL; l++) {
        size_t wo = (size_t)l*DD*DD, w1 = (size_t)l*DD*DI;
        mma_gemm<0><<<gP, 256, GEMM_SMEM>>>(xh, xl, qh+wo, ql+wo, bq+l*DD, nullptr, pq, nullptr, nullptr, DD, DD, nullptr, nullptr);
        mma_gemm<0><<<gP, 256, GEMM_SMEM>>>(xh, xl, kh+wo, kl+wo, bk+l*DD, nullptr, pk, nullptr, nullptr, DD, DD, nullptr, nullptr);
        mma_gemm<0><<<gP, 256, GEMM_SMEM>>>(xh, xl, vh+wo, vl+wo, bv+l*DD, nullptr, pv, nullptr, nullptr, DD, DD, nullptr, nullptr);
        k_attn<<<gA, 256, ATT_SMEM>>>(E + (size_t)l*SS*DHD);
        mma_gemm<1><<<gP, 256, GEMM_SMEM>>>(ah, al, oh+wo, ol+wo, bo+l*DD, px, pres, nullptr, nullptr, DD, DD, nullptr, nullptr);
        k_ln<<<BS, 128>>>(pres, pout1, ln1g + l*DD, ln1b + l*DD, o1h, o1l);
        mma_gemm<2><<<gF1, 256, GEMM_SMEM>>>(o1h, o1l, f1h+w1, f1l+w1, fb1+l*DI, nullptr, nullptr, hh, hl, DD, DI, ttcW, ttcb);
        mma_gemm<1><<<gP, 256, GEMM_SMEM>>>(hh, hl, f2h+w1, f2l+w1, fb2+l*DD, pout1, pres, nullptr, nullptr, DI, DD, nullptr, nullptr);
        k_ln<<<BS, 128>>>(pres, px, ln2g + l*DD, ln2b + l*DD, xh, xl);
    }
    mma_gemm<3><<<dim3(VV/128, BS/128), 256, GEMM_SMEM>>>(xh, xl, fch, fcl, fcb, nullptr, out, nullptr, nullptr, DD, VV, nullptr, nullptr);
}

// round 7
// speedup vs baseline: 2.8835x; 1.9913x over previous
#include <cuda_runtime.h>
#include <cuda_bf16.h>
#include <math.h>
#include <stdint.h>

#define BB 2
#define SS 2048
#define NCOND 2
#define STOK 2046
#define DD 512
#define HH 8
#define DHD 64
#define DI 2048
#define NL 6
#define VV 512
#define BS (BB*SS)   // 4096
#define NBH (BB*HH)  // 16

// ---------------- scratch (device globals) -----------------------------------
__device__ float g_x[BS*DD];
__device__ float g_res[BS*DD];
__device__ float g_out1[BS*DD];
__device__ float g_chordf[BS];
__device__ int   g_keypad[BS];

// bf16 hi/lo activations, row-major [rows][K]
__device__ __align__(256) __nv_bfloat16 g_xh[BS*DD],  g_xl[BS*DD];
__device__ __align__(256) __nv_bfloat16 g_o1h[BS*DD], g_o1l[BS*DD];
__device__ __align__(256) __nv_bfloat16 g_ah[BS*DD],  g_al[BS*DD];
__device__ __align__(256) __nv_bfloat16 g_hh[(size_t)BS*DI], g_hl[(size_t)BS*DI];

// attention operands: q,k head-major [bh][s][64]; v transposed [bh][64][s]
__device__ __align__(256) __nv_bfloat16 g_qbh[(size_t)NBH*SS*DHD], g_qbl[(size_t)NBH*SS*DHD];
__device__ __align__(256) __nv_bfloat16 g_kbh[(size_t)NBH*SS*DHD], g_kbl[(size_t)NBH*SS*DHD];
__device__ __align__(256) __nv_bfloat16 g_vbh[(size_t)NBH*SS*DHD], g_vbl[(size_t)NBH*SS*DHD];
__device__ __align__(256) __nv_bfloat16 g_eh[(size_t)NL*SS*DHD],   g_el[(size_t)NL*SS*DHD];

// bf16 hi/lo weights, row-major [N][K]
__device__ __align__(256) __nv_bfloat16 w_qh[(size_t)NL*DD*DD], w_ql[(size_t)NL*DD*DD];
__device__ __align__(256) __nv_bfloat16 w_kh[(size_t)NL*DD*DD], w_kl[(size_t)NL*DD*DD];
__device__ __align__(256) __nv_bfloat16 w_vh[(size_t)NL*DD*DD], w_vl[(size_t)NL*DD*DD];
__device__ __align__(256) __nv_bfloat16 w_oh[(size_t)NL*DD*DD], w_ol[(size_t)NL*DD*DD];
__device__ __align__(256) __nv_bfloat16 w_f1h[(size_t)NL*DD*DI], w_f1l[(size_t)NL*DD*DI];
__device__ __align__(256) __nv_bfloat16 w_f2h[(size_t)NL*DI*DD], w_f2l[(size_t)NL*DI*DD];
__device__ __align__(256) __nv_bfloat16 w_fch[(size_t)DD*VV],    w_fcl[(size_t)DD*VV];

// ---------------- helpers -----------------------------------------------------
__device__ __forceinline__ uint32_t smem_u32(const void* p){
    uint32_t a;
    asm("{ .reg .u64 t; cvta.to.shared.u64 t, %1; cvt.u32.u64 %0, t; }" : "=r"(a) : "l"(p));
    return a;
}
__device__ __forceinline__ void cp_async16(uint32_t s, const void* g){
    asm volatile("cp.async.cg.shared.global [%0], [%1], 16;\n"
        :: "r"(s), "l"(__cvta_generic_to_global(g)) : "memory");
}
#define CP_COMMIT() asm volatile("cp.async.commit_group;\n":::"memory")
#define CP_WAIT1()  asm volatile("cp.async.wait_group 1;\n":::"memory")
#define CP_WAIT0()  asm volatile("cp.async.wait_group 0;\n":::"memory")

__device__ __forceinline__ void mma16816(float* c, uint32_t a0, uint32_t a1, uint32_t a2, uint32_t a3,
                                         uint32_t b0, uint32_t b1){
    asm volatile(
        "mma.sync.aligned.m16n8k16.row.col.f32.bf16.bf16.f32 "
        "{%0,%1,%2,%3}, {%4,%5,%6,%7}, {%8,%9}, {%0,%1,%2,%3};"
        : "+f"(c[0]), "+f"(c[1]), "+f"(c[2]), "+f"(c[3])
        : "r"(a0), "r"(a1), "r"(a2), "r"(a3), "r"(b0), "r"(b1));
}
__device__ __forceinline__ unsigned pkb(__nv_bfloat16 a, __nv_bfloat16 b){
    __nv_bfloat162 t(a, b);
    return *reinterpret_cast<unsigned*>(&t);
}
__device__ __forceinline__ void split1(float v, __nv_bfloat16& h, __nv_bfloat16& l){
    h = __float2bfloat16(v);
    l = __float2bfloat16(v - __bfloat162float(h));
}
__device__ __forceinline__ void store_split4(char* ph, char* pl, size_t boff,
                                             float v0, float v1, float v2, float v3){
    __nv_bfloat16 h0,h1,h2,h3,l0,l1,l2,l3;
    split1(v0,h0,l0); split1(v1,h1,l1); split1(v2,h2,l2); split1(v3,h3,l3);
    uint2 uh; uh.x = pkb(h0,h1); uh.y = pkb(h2,h3);
    uint2 ul; ul.x = pkb(l0,l1); ul.y = pkb(l2,l3);
    *(uint2*)(ph + boff) = uh;
    *(uint2*)(pl + boff) = ul;
}
__device__ __forceinline__ void store_split2(char* ph, char* pl, size_t boff, float v0, float v1){
    __nv_bfloat16 h0,h1,l0,l1;
    split1(v0,h0,l0); split1(v1,h1,l1);
    *(unsigned*)(ph + boff) = pkb(h0,h1);
    *(unsigned*)(pl + boff) = pkb(l0,l1);
}
__device__ __forceinline__ void store_split1(__nv_bfloat16* ph, __nv_bfloat16* pl, size_t e, float v){
    __nv_bfloat16 h,l; split1(v,h,l); ph[e] = h; pl[e] = l;
}

// ---------------- misc --------------------------------------------------------
__global__ void k_misc(const int* __restrict__ toks, const float* __restrict__ ttc) {
    int idx = blockIdx.x * 256 + threadIdx.x;
    if (idx >= BS) return;
    int b = idx / SS, s = idx % SS;
    g_keypad[idx] = (s >= NCOND && toks[b*STOK + s - NCOND] == 0) ? 1 : 0;
    float t = (s < NCOND) ? ttc[b*STOK] : ttc[b*STOK + s - NCOND];
    g_chordf[idx] = 8.0f - t;
}

__global__ void k_build_x(const int* __restrict__ toks, const float* __restrict__ cond,
                          const float* __restrict__ emb, const float* __restrict__ pos,
                          const float* __restrict__ W1, const float* __restrict__ b1,
                          const float* __restrict__ W2, const float* __restrict__ b2,
                          const float* __restrict__ nullc) {
    int blk = blockIdx.x;
    int b = blk / SS, s = blk % SS;
    int t = threadIdx.x;
    int d0 = t*4;
    float v[4];
    if (s < NCOND) {
        __shared__ float h1[256];
        float c = cond[b*NCOND + s];
        bool isn = isnan(c);
        if (!isn) {
            for (int o = t; o < 256; o += 128)
                h1[o] = fmaxf(c * W1[s*256 + o] + b1[s*256 + o], 0.f);
        }
        __syncthreads();
        #pragma unroll
        for (int j = 0; j < 4; j++) {
            int d = d0 + j;
            float ce;
            if (isn) ce = nullc[s*DD + d];
            else {
                float acc = b2[s*DD + d];
                #pragma unroll 8
                for (int o = 0; o < 256; o++) acc += h1[o] * W2[(s*256 + o)*DD + d];
                ce = acc;
            }
            v[j] = ce + pos[s*DD + d];
        }
    } else {
        int tok = toks[b*STOK + s - NCOND];
        float4 e = *(const float4*)(emb + (size_t)tok*DD + d0);
        float4 p = *(const float4*)(pos + (size_t)s*DD + d0);
        const float SC = 22.62741699796952f;
        v[0] = e.x*SC + p.x; v[1] = e.y*SC + p.y; v[2] = e.z*SC + p.z; v[3] = e.w*SC + p.w;
    }
    *(float4*)(&g_x[(size_t)blk*DD + d0]) = make_float4(v[0], v[1], v[2], v[3]);
    store_split4((char*)g_xh, (char*)g_xl, ((size_t)blk*DD + d0)*2, v[0], v[1], v[2], v[3]);
}

// fp32 weight [K][N] -> row-major [N][K] hi/lo
__global__ void cvt_w(const float* __restrict__ W, __nv_bfloat16* __restrict__ Bh,
                      __nv_bfloat16* __restrict__ Bl, int K, int N) {
    int kt = blockIdx.x, nt = blockIdx.y, l = blockIdx.z;
    const float* Wl = W + (size_t)l*K*N;
    char* ph = (char*)Bh + (size_t)l*N*K*2;
    char* pl = (char*)Bl + (size_t)l*N*K*2;
    __shared__ float ts[64][129];
    int tid = threadIdx.x;
    int k0 = kt*64, n0 = nt*128;
    #pragma unroll
    for (int r = 0; r < 8; r++) {
        int i = tid + r*256;
        int kl = i >> 5, n4 = (i & 31) * 4;
        float4 x = *(const float4*)(Wl + (size_t)(k0 + kl)*N + n0 + n4);
        ts[kl][n4] = x.x; ts[kl][n4+1] = x.y; ts[kl][n4+2] = x.z; ts[kl][n4+3] = x.w;
    }
    __syncthreads();
    #pragma unroll
    for (int r = 0; r < 8; r++) {
        int i = tid + r*256;
        int nl = i >> 4, kc = (i & 15) * 4;
        size_t boff = ((size_t)(n0 + nl)*K + k0 + kc)*2;
        store_split4(ph, pl, boff, ts[kc][nl], ts[kc+1][nl], ts[kc+2][nl], ts[kc+3][nl]);
    }
}

// E fp32 [NL][2048][64] -> hi/lo elementwise
__global__ void cvt_e(const float* __restrict__ E) {
    size_t i = ((size_t)blockIdx.x*256 + threadIdx.x)*4;
    if (i >= (size_t)NL*SS*DHD) return;
    float4 v = *(const float4*)(E + i);
    store_split4((char*)g_eh, (char*)g_el, i*2, v.x, v.y, v.z, v.w);
}

// ---------------- mma.sync GEMM (3-term bf16 split) ---------------------------
// MODE 0: q/k head-major split out. 1: acc+bias+res fp32. 2: relu+chord -> split. 3: acc+bias. 4: v transposed split.
#define GPITCH 144
#define GMAT   18432
#define GSTAGE 73728
#define GEMM_SMEM (2*GSTAGE)

template<int MODE>
__global__ __launch_bounds__(256, 1)
void mma_gemm(const __nv_bfloat16* __restrict__ Ah, const __nv_bfloat16* __restrict__ Al,
              const __nv_bfloat16* __restrict__ Bh, const __nv_bfloat16* __restrict__ Bl,
              const float* __restrict__ bias, const float* __restrict__ res,
              float* __restrict__ out, __nv_bfloat16* __restrict__ outH,
              __nv_bfloat16* __restrict__ outL,
              int K, int Ntot, const float* __restrict__ ttcW, const float* __restrict__ ttcb)
{
    extern __shared__ char smem[];
    uint32_t sbase = smem_u32(smem);
    int tid = threadIdx.x, wid = tid >> 5, lane = tid & 31;
    int g = lane >> 2, t4 = lane & 3;
    int wm = wid & 3, wn = wid >> 2;
    int mt = blockIdx.y, nt = blockIdx.x;
    int mG = mt*128, nG = nt*128;
    int KT = K >> 6;

    int mymat = tid >> 6, sub = tid & 63;
    int lr0 = sub >> 3, lch = sub & 7;
    const char* matp = (mymat == 0) ? (const char*)Ah : (mymat == 1) ? (const char*)Al
                     : (mymat == 2) ? (const char*)Bh : (const char*)Bl;
    int rowG = (mymat < 2) ? mG : nG;
    const char* srcbase = matp + ((size_t)(rowG + lr0) * K + lch*8) * 2;
    uint32_t dstbase = sbase + mymat*GMAT + lr0*GPITCH + lch*16;
    size_t srcstep = (size_t)8*K*2;

    auto load_stage = [&](int kb){
        uint32_t d = dstbase + (kb&1)*GSTAGE;
        const char* s = srcbase + (size_t)kb*128;
        #pragma unroll
        for (int i = 0; i < 16; i++){
            cp_async16(d, s);
            d += 8*GPITCH; s += srcstep;
        }
        CP_COMMIT();
    };

    load_stage(0);
    if (KT > 1) load_stage(1);

    float acc[2][8][4] = {};
    int ar0 = wm*32, bn0 = wn*64;

    for (int kb = 0; kb < KT; kb++){
        if (kb + 1 < KT) CP_WAIT1(); else CP_WAIT0();
        __syncthreads();
        const char* st = smem + (size_t)(kb&1)*GSTAGE;
        const char* sAh = st;
        const char* sAl = st + GMAT;
        const char* sBh = st + 2*GMAT;
        const char* sBl = st + 3*GMAT;
        #pragma unroll
        for (int ks = 0; ks < 4; ks++){
            int cw  = (ks*8 + t4)*4;
            int cw4 = cw + 16;
            uint32_t bh0[8], bh1[8], bl0[8], bl1[8];
            #pragma unroll
            for (int j = 0; j < 8; j++){
                int nr = (bn0 + j*8 + g)*GPITCH;
                bh0[j] = *(const uint32_t*)(sBh + nr + cw);
                bh1[j] = *(const uint32_t*)(sBh + nr + cw4);
                bl0[j] = *(const uint32_t*)(sBl + nr + cw);
                bl1[j] = *(const uint32_t*)(sBl + nr + cw4);
            }
            #pragma unroll
            for (int mi = 0; mi < 2; mi++){
                int r0 = (ar0 + mi*16 + g)*GPITCH;
                int r8 = r0 + 8*GPITCH;
                uint32_t ah0 = *(const uint32_t*)(sAh + r0 + cw);
                uint32_t ah1 = *(const uint32_t*)(sAh + r8 + cw);
                uint32_t ah2 = *(const uint32_t*)(sAh + r0 + cw4);
                uint32_t ah3 = *(const uint32_t*)(sAh + r8 + cw4);
                uint32_t al0 = *(const uint32_t*)(sAl + r0 + cw);
                uint32_t al1 = *(const uint32_t*)(sAl + r8 + cw);
                uint32_t al2 = *(const uint32_t*)(sAl + r0 + cw4);
                uint32_t al3 = *(const uint32_t*)(sAl + r8 + cw4);
                #pragma unroll
                for (int j = 0; j < 8; j++){
                    mma16816(acc[mi][j], ah0, ah1, ah2, ah3, bh0[j], bh1[j]);
                    mma16816(acc[mi][j], ah0, ah1, ah2, ah3, bl0[j], bl1[j]);
                    mma16816(acc[mi][j], al0, al1, al2, al3, bh0[j], bh1[j]);
                }
            }
        }
        __syncthreads();
        if (kb + 2 < KT) load_stage(kb + 2);
    }

    #pragma unroll
    for (int mi = 0; mi < 2; mi++){
        #pragma unroll
        for (int j = 0; j < 8; j++){
            int n = nG + bn0 + j*8 + 2*t4;
            int mA = mG + ar0 + mi*16 + g;
            int mB = mA + 8;
            float c0 = acc[mi][j][0], c1 = acc[mi][j][1];
            float c2 = acc[mi][j][2], c3 = acc[mi][j][3];
            float bx = bias[n], by = bias[n+1];
            if (MODE == 0) {
                int hh_ = n >> 6, dd_ = n & 63;
                int bA = mA >> 11, sA = mA & 2047;
                int bB = mB >> 11, sB = mB & 2047;
                store_split2((char*)outH, (char*)outL,
                    ((size_t)((bA*HH + hh_)*SS + sA)*DHD + dd_)*2, c0+bx, c1+by);
                store_split2((char*)outH, (char*)outL,
                    ((size_t)((bB*HH + hh_)*SS + sB)*DHD + dd_)*2, c2+bx, c3+by);
            } else if (MODE == 4) {
                int hh_ = n >> 6, dd_ = n & 63;
                int bA = mA >> 11, sA = mA & 2047;
                int bB = mB >> 11, sB = mB & 2047;
                size_t baseA = (size_t)(bA*HH + hh_)*DHD;
                size_t baseB = (size_t)(bB*HH + hh_)*DHD;
                store_split1(outH, outL, (baseA + dd_  )*SS + sA, c0+bx);
                store_split1(outH, outL, (baseA + dd_+1)*SS + sA, c1+by);
                store_split1(outH, outL, (baseB + dd_  )*SS + sB, c2+bx);
                store_split1(outH, outL, (baseB + dd_+1)*SS + sB, c3+by);
            } else if (MODE == 1) {
                float2 rA = *(const float2*)(res + (size_t)mA*Ntot + n);
                float2 rB = *(const float2*)(res + (size_t)mB*Ntot + n);
                *(float2*)(out + (size_t)mA*Ntot + n) = make_float2(c0+bx+rA.x, c1+by+rA.y);
                *(float2*)(out + (size_t)mB*Ntot + n) = make_float2(c2+bx+rB.x, c3+by+rB.y);
            } else if (MODE == 3) {
                *(float2*)(out + (size_t)mA*Ntot + n) = make_float2(c0+bx, c1+by);
                *(float2*)(out + (size_t)mB*Ntot + n) = make_float2(c2+bx, c3+by);
            } else {
                float twx = ttcW[n], twy = ttcW[n+1];
                float tbx = ttcb[n], tby = ttcb[n+1];
                float cfA = g_chordf[mA], cfB = g_chordf[mB];
                float v0 = fmaxf(c0+bx, 0.f) + cfA*twx + tbx;
                float v1 = fmaxf(c1+by, 0.f) + cfA*twy + tby;
                float v2 = fmaxf(c2+bx, 0.f) + cfB*twx + tbx;
                float v3 = fmaxf(c3+by, 0.f) + cfB*twy + tby;
                store_split2((char*)outH, (char*)outL, ((size_t)mA*Ntot + n)*2, v0, v1);
                store_split2((char*)outH, (char*)outL, ((size_t)mB*Ntot + n)*2, v2, v3);
            }
        }
    }
}

// ---------------- layernorm ---------------------------------------------------
__global__ void k_ln(const float* __restrict__ in, float* __restrict__ out,
                     const float* __restrict__ g, const float* __restrict__ bb,
                     __nv_bfloat16* __restrict__ oh, __nv_bfloat16* __restrict__ ol) {
    int r = blockIdx.x, t = threadIdx.x;
    float4 v = *(const float4*)(in + (size_t)r*DD + t*4);
    float s  = v.x + v.y + v.z + v.w;
    float ss = v.x*v.x + v.y*v.y + v.z*v.z + v.w*v.w;
    for (int m = 16; m; m >>= 1) {
        s  += __shfl_xor_sync(0xffffffffu, s,  m);
        ss += __shfl_xor_sync(0xffffffffu, ss, m);
    }
    __shared__ float sm[4], sm2[4];
    if ((t & 31) == 0) { sm[t>>5] = s; sm2[t>>5] = ss; }
    __syncthreads();
    s  = sm[0]  + sm[1]  + sm[2]  + sm[3];
    ss = sm2[0] + sm2[1] + sm2[2] + sm2[3];
    float mu  = s * (1.0f/DD);
    float var = ss * (1.0f/DD) - mu*mu;
    float inv = rsqrtf(var + 1e-6f);
    float4 gg = *(const float4*)(g  + t*4);
    float4 bv = *(const float4*)(bb + t*4);
    float4 o;
    o.x = (v.x - mu)*inv*gg.x + bv.x;
    o.y = (v.y - mu)*inv*gg.y + bv.y;
    o.z = (v.z - mu)*inv*gg.z + bv.z;
    o.w = (v.w - mu)*inv*gg.w + bv.w;
    *(float4*)(out + (size_t)r*DD + t*4) = o;
    store_split4((char*)oh, (char*)ol, ((size_t)r*DD + t*4)*2, o.x, o.y, o.z, o.w);
}

// ---------------- tensor-core rel-pos flash attention -------------------------
// CTA: 128 q-rows x (b,h). j-tiles of 128. 8 warps x 16 rows.
// smem: K(hi/lo 128x144B x2 = 36864) | E(hi/lo 256x144B x2 = 73728, aliased by P 128x272B x2)
//       | S fp32 128x528B = 67584 | keypad 512
#define AOFF_K 0
#define AOFF_E 36864
#define AOFF_S 110592
#define AOFF_KP 178176
#define ATT_SMEM 178816

__global__ __launch_bounds__(256, 1)
void k_attn_tc(const __nv_bfloat16* __restrict__ eh, const __nv_bfloat16* __restrict__ el) {
    extern __shared__ char sm[];
    int tid = threadIdx.x, w = tid >> 5, lane = tid & 31;
    int g = lane >> 2, t4 = lane & 3;
    int itile = (int)gridDim.x - 1 - (int)blockIdx.x;   // heavy first
    int i0 = itile * 128;
    int h = blockIdx.y, b = blockIdx.z, bh = b*HH + h;
    uint32_t sA = smem_u32(sm);
    int* kps = (int*)(sm + AOFF_KP);
    int r_ = 16*w + g;

    // Q fragments in registers
    uint32_t qfh[4][4], qfl[4][4];
    {
        const char* qh_ = (const char*)g_qbh + ((size_t)bh*SS*DHD)*2;
        const char* ql_ = (const char*)g_qbl + ((size_t)bh*SS*DHD)*2;
        #pragma unroll
        for (int ks = 0; ks < 4; ks++){
            size_t o0 = ((size_t)(i0 + r_)*DHD + ks*16 + 2*t4)*2;
            qfh[ks][0] = *(const uint32_t*)(qh_ + o0);
            qfh[ks][1] = *(const uint32_t*)(qh_ + o0 + 8*DHD*2);
            qfh[ks][2] = *(const uint32_t*)(qh_ + o0 + 16);
            qfh[ks][3] = *(const uint32_t*)(qh_ + o0 + 8*DHD*2 + 16);
            qfl[ks][0] = *(const uint32_t*)(ql_ + o0);
            qfl[ks][1] = *(const uint32_t*)(ql_ + o0 + 8*DHD*2);
            qfl[ks][2] = *(const uint32_t*)(ql_ + o0 + 16);
            qfl[ks][3] = *(const uint32_t*)(ql_ + o0 + 8*DHD*2 + 16);
        }
    }

    float oac[8][4] = {};
    float mrow[2] = {-1e30f, -1e30f};
    float lrow[2] = {0.f, 0.f};

    for (int kt = 0; kt <= itile; kt++){
        int j0 = kt*128;
        __syncthreads();
        // K hi/lo loads
        #pragma unroll
        for (int i = 0; i < 8; i++){
            int idx = tid + 256*i;
            int mat = idx >> 10, r = (idx & 1023) >> 3, ch = idx & 7;
            const char* src = (const char*)(mat ? g_kbl : g_kbh)
                + ((size_t)(bh*SS + j0 + r)*DHD + ch*8)*2;
            cp_async16(sA + AOFF_K + mat*18432 + r*144 + ch*16, src);
        }
        // E band hi/lo loads
        int ebase = (SS - 1) + j0 - i0 - 127;
        #pragma unroll
        for (int i = 0; i < 16; i++){
            int idx = tid + 256*i;
            int mat = idx >> 11, r = (idx & 2047) >> 3, ch = idx & 7;
            int m = ebase + r; if (m > SS-1) m = SS-1;
            const char* src = (const char*)(mat ? el : eh) + ((size_t)m*DHD + ch*8)*2;
            cp_async16(sA + AOFF_E + mat*36864 + r*144 + ch*16, src);
        }
        CP_COMMIT();
        if (tid < 128) kps[tid] = g_keypad[b*SS + j0 + tid];
        CP_WAIT0();
        __syncthreads();

        // ---- S = Q K^T (3-term)
        float sacc[16][4] = {};
        #pragma unroll
        for (int ks = 0; ks < 4; ks++){
            int cb = (ks*16 + 2*t4)*2;
            #pragma unroll
            for (int nf = 0; nf < 16; nf++){
                const char* kb = sm + AOFF_K + (nf*8+g)*144 + cb;
                uint32_t b0 = *(const uint32_t*)kb, b1 = *(const uint32_t*)(kb+16);
                uint32_t c0 = *(const uint32_t*)(kb+18432), c1 = *(const uint32_t*)(kb+18432+16);
                mma16816(sacc[nf], qfh[ks][0], qfh[ks][1], qfh[ks][2], qfh[ks][3], b0, b1);
                mma16816(sacc[nf], qfh[ks][0], qfh[ks][1], qfh[ks][2], qfh[ks][3], c0, c1);
                mma16816(sacc[nf], qfl[ks][0], qfl[ks][1], qfl[ks][2], qfl[ks][3], b0, b1);
            }
        }
        #pragma unroll
        for (int nf = 0; nf < 16; nf++){
            *(float2*)(sm + AOFF_S + r_*528 + (nf*8 + 2*t4)*4)     = make_float2(sacc[nf][0], sacc[nf][1]);
            *(float2*)(sm + AOFF_S + (r_+8)*528 + (nf*8 + 2*t4)*4) = make_float2(sacc[nf][2], sacc[nf][3]);
        }
        __syncthreads();

        // V loads (into K region; K is dead)
        #pragma unroll
        for (int i = 0; i < 8; i++){
            int idx = tid + 256*i;
            int mat = idx >> 10, r = (idx & 1023) >> 4, ch = idx & 15;
            const char* src = (const char*)(mat ? g_vbl : g_vbh)
                + ((size_t)(bh*DHD + r)*SS + j0 + ch*8)*2;
            cp_async16(sA + AOFF_K + mat*18432 + r*272 + ch*16, src);
        }
        CP_COMMIT();

        // ---- Z = Q E^T (3-term), scatter-add into S
        #pragma unroll 1
        for (int chunk = 0; chunk < 4; chunk++){
            float zac[8][4] = {};
            #pragma unroll
            for (int ks = 0; ks < 4; ks++){
                int cb = (ks*16 + 2*t4)*2;
                #pragma unroll
                for (int jf = 0; jf < 8; jf++){
                    const char* eb = sm + AOFF_E + ((chunk*8+jf)*8+g)*144 + cb;
                    uint32_t b0 = *(const uint32_t*)eb, b1 = *(const uint32_t*)(eb+16);
                    uint32_t c0 = *(const uint32_t*)(eb+36864), c1 = *(const uint32_t*)(eb+36864+16);
                    mma16816(zac[jf], qfh[ks][0], qfh[ks][1], qfh[ks][2], qfh[ks][3], b0, b1);
                    mma16816(zac[jf], qfh[ks][0], qfh[ks][1], qfh[ks][2], qfh[ks][3], c0, c1);
                    mma16816(zac[jf], qfl[ks][0], qfl[ks][1], qfl[ks][2], qfl[ks][3], b0, b1);
                }
            }
            float* S0 = (float*)(sm + AOFF_S + r_*528);
            float* S1 = (float*)(sm + AOFF_S + (r_+8)*528);
            #pragma unroll
            for (int jf = 0; jf < 8; jf++){
                int u = (chunk*8+jf)*8 + 2*t4;
                int c0 = r_ + u - 127;
                if (c0 >= 0   && c0   < 128) S0[c0]   += zac[jf][0];
                if (c0+1 >= 0 && c0+1 < 128) S0[c0+1] += zac[jf][1];
                int c2 = r_ + 8 + u - 127;
                if (c2 >= 0   && c2   < 128) S1[c2]   += zac[jf][2];
                if (c2+1 >= 0 && c2+1 < 128) S1[c2+1] += zac[jf][3];
            }
        }
        __syncthreads();

        // ---- online softmax; write P (bf16 hi/lo) over E region
        #pragma unroll
        for (int mi = 0; mi < 2; mi++){
            int rr = r_ + 8*mi;
            int i = i0 + rr;
            float lv[32];
            float tm = -1e30f;
            #pragma unroll
            for (int k16 = 0; k16 < 16; k16++){
                int c = k16*8 + 2*t4;
                float2 sv = *(const float2*)(sm + AOFF_S + rr*528 + c*4);
                int j = j0 + c;
                float a = (j   <= i && kps[c]   == 0) ? sv.x*0.125f : -1e30f;
                float d = (j+1 <= i && kps[c+1] == 0) ? sv.y*0.125f : -1e30f;
                lv[2*k16] = a; lv[2*k16+1] = d;
                tm = fmaxf(tm, fmaxf(a, d));
            }
            tm = fmaxf(tm, __shfl_xor_sync(0xffffffffu, tm, 1));
            tm = fmaxf(tm, __shfl_xor_sync(0xffffffffu, tm, 2));
            float mn = fmaxf(mrow[mi], tm);
            float corr = __expf(mrow[mi] - mn);
            float rs = 0.f;
            #pragma unroll
            for (int k16 = 0; k16 < 16; k16++){
                int c = k16*8 + 2*t4;
                float p0 = __expf(lv[2*k16]   - mn);
                float p1 = __expf(lv[2*k16+1] - mn);
                rs += p0 + p1;
                store_split2(sm + AOFF_E, sm + AOFF_E + 36864,
                             (size_t)rr*272 + c*2, p0, p1);
            }
            rs += __shfl_xor_sync(0xffffffffu, rs, 1);
            rs += __shfl_xor_sync(0xffffffffu, rs, 2);
            lrow[mi] = lrow[mi]*corr + rs;
            mrow[mi] = mn;
            #pragma unroll
            for (int nf = 0; nf < 8; nf++){
                oac[nf][2*mi]   *= corr;
                oac[nf][2*mi+1] *= corr;
            }
        }
        CP_WAIT0();
        __syncthreads();

        // ---- O += P V (3-term)
        #pragma unroll
        for (int ks = 0; ks < 8; ks++){
            int cb = (ks*16 + 2*t4)*2;
            const char* pb = sm + AOFF_E + r_*272 + cb;
            uint32_t ph0 = *(const uint32_t*)pb;
            uint32_t ph1 = *(const uint32_t*)(pb + 8*272);
            uint32_t ph2 = *(const uint32_t*)(pb + 16);
            uint32_t ph3 = *(const uint32_t*)(pb + 8*272 + 16);
            const char* pl_ = pb + 36864;
            uint32_t pl0 = *(const uint32_t*)pl_;
            uint32_t pl1 = *(const uint32_t*)(pl_ + 8*272);
            uint32_t pl2 = *(const uint32_t*)(pl_ + 16);
            uint32_t pl3 = *(const uint32_t*)(pl_ + 8*272 + 16);
            #pragma unroll
            for (int nf = 0; nf < 8; nf++){
                const char* vb = sm + AOFF_K + (nf*8+g)*272 + cb;
                uint32_t b0 = *(const uint32_t*)vb, b1 = *(const uint32_t*)(vb+16);
                uint32_t c0 = *(const uint32_t*)(vb+18432), c1 = *(const uint32_t*)(vb+18432+16);
                mma16816(oac[nf], ph0, ph1, ph2, ph3, b0, b1);
                mma16816(oac[nf], pl0, pl1, pl2, pl3, b0, b1);
                mma16816(oac[nf], ph0, ph1, ph2, ph3, c0, c1);
            }
        }
    }

    // epilogue: normalize, emit hi/lo row-major [b*S+i][512]
    float inv0 = 1.0f / lrow[0], inv1 = 1.0f / lrow[1];
    #pragma unroll
    for (int nf = 0; nf < 8; nf++){
        int col = h*DHD + nf*8 + 2*t4;
        size_t row0 = (size_t)(b*SS + i0 + r_);
        store_split2((char*)g_ah, (char*)g_al, (row0*DD + col)*2,
                     oac[nf][0]*inv0, oac[nf][1]*inv0);
        store_split2((char*)g_ah, (char*)g_al, ((row0+8)*DD + col)*2,
                     oac[nf][2]*inv1, oac[nf][3]*inv1);
    }
}

// ---------------- host orchestration ------------------------------------------
extern "C" void kernel_launch(void* const* d_in, const int* in_sizes, int n_in,
                              void* d_out, int out_size) {
    const int*   toks   = (const int*)  d_in[0];
    const float* cond   = (const float*)d_in[1];
    const float* ttc    = (const float*)d_in[2];
    const float* emb    = (const float*)d_in[3];
    const float* pos    = (const float*)d_in[4];
    const float* cW1    = (const float*)d_in[5];
    const float* cb1    = (const float*)d_in[6];
    const float* cW2    = (const float*)d_in[7];
    const float* cb2    = (const float*)d_in[8];
    const float* nullc  = (const float*)d_in[9];
    const float* ttcW   = (const float*)d_in[10];
    const float* ttcb   = (const float*)d_in[11];
    const float* Wq     = (const float*)d_in[12];
    const float* Wk     = (const float*)d_in[13];
    const float* Wv     = (const float*)d_in[14];
    const float* Wo     = (const float*)d_in[15];
    const float* bq     = (const float*)d_in[16];
    const float* bk     = (const float*)d_in[17];
    const float* bv     = (const float*)d_in[18];
    const float* bo     = (const float*)d_in[19];
    const float* E      = (const float*)d_in[20];
    const float* fW1    = (const float*)d_in[21];
    const float* fb1    = (const float*)d_in[22];
    const float* fW2    = (const float*)d_in[23];
    const float* fb2    = (const float*)d_in[24];
    const float* ln1g   = (const float*)d_in[25];
    const float* ln1b   = (const float*)d_in[26];
    const float* ln2g   = (const float*)d_in[27];
    const float* ln2b   = (const float*)d_in[28];
    const float* fcW    = (const float*)d_in[29];
    const float* fcb    = (const float*)d_in[30];
    float* out = (float*)d_out;

    float *px, *pres, *pout1;
    cudaGetSymbolAddress((void**)&px,    g_x);
    cudaGetSymbolAddress((void**)&pres,  g_res);
    cudaGetSymbolAddress((void**)&pout1, g_out1);
    __nv_bfloat16 *xh,*xl,*o1h,*o1l,*ah,*al,*hh,*hl;
    __nv_bfloat16 *qbh,*qbl,*kbh,*kbl,*vbh,*vbl,*peh,*pel;
    __nv_bfloat16 *qh,*ql,*kh,*kl,*vh,*vl,*oh,*ol,*f1h,*f1l,*f2h,*f2l,*fch,*fcl;
    cudaGetSymbolAddress((void**)&xh,  g_xh);  cudaGetSymbolAddress((void**)&xl,  g_xl);
    cudaGetSymbolAddress((void**)&o1h, g_o1h); cudaGetSymbolAddress((void**)&o1l, g_o1l);
    cudaGetSymbolAddress((void**)&ah,  g_ah);  cudaGetSymbolAddress((void**)&al,  g_al);
    cudaGetSymbolAddress((void**)&hh,  g_hh);  cudaGetSymbolAddress((void**)&hl,  g_hl);
    cudaGetSymbolAddress((void**)&qbh, g_qbh); cudaGetSymbolAddress((void**)&qbl, g_qbl);
    cudaGetSymbolAddress((void**)&kbh, g_kbh); cudaGetSymbolAddress((void**)&kbl, g_kbl);
    cudaGetSymbolAddress((void**)&vbh, g_vbh); cudaGetSymbolAddress((void**)&vbl, g_vbl);
    cudaGetSymbolAddress((void**)&peh, g_eh);  cudaGetSymbolAddress((void**)&pel, g_el);
    cudaGetSymbolAddress((void**)&qh,  w_qh);  cudaGetSymbolAddress((void**)&ql,  w_ql);
    cudaGetSymbolAddress((void**)&kh,  w_kh);  cudaGetSymbolAddress((void**)&kl,  w_kl);
    cudaGetSymbolAddress((void**)&vh,  w_vh);  cudaGetSymbolAddress((void**)&vl,  w_vl);
    cudaGetSymbolAddress((void**)&oh,  w_oh);  cudaGetSymbolAddress((void**)&ol,  w_ol);
    cudaGetSymbolAddress((void**)&f1h, w_f1h); cudaGetSymbolAddress((void**)&f1l, w_f1l);
    cudaGetSymbolAddress((void**)&f2h, w_f2h); cudaGetSymbolAddress((void**)&f2l, w_f2l);
    cudaGetSymbolAddress((void**)&fch, w_fch); cudaGetSymbolAddress((void**)&fcl, w_fcl);

    cudaFuncSetAttribute(k_attn_tc,   cudaFuncAttributeMaxDynamicSharedMemorySize, ATT_SMEM);
    cudaFuncSetAttribute(mma_gemm<0>, cudaFuncAttributeMaxDynamicSharedMemorySize, GEMM_SMEM);
    cudaFuncSetAttribute(mma_gemm<1>, cudaFuncAttributeMaxDynamicSharedMemorySize, GEMM_SMEM);
    cudaFuncSetAttribute(mma_gemm<2>, cudaFuncAttributeMaxDynamicSharedMemorySize, GEMM_SMEM);
    cudaFuncSetAttribute(mma_gemm<3>, cudaFuncAttributeMaxDynamicSharedMemorySize, GEMM_SMEM);
    cudaFuncSetAttribute(mma_gemm<4>, cudaFuncAttributeMaxDynamicSharedMemorySize, GEMM_SMEM);

    k_misc<<<(BS + 255)/256, 256>>>(toks, ttc);
    k_build_x<<<BS, 128>>>(toks, cond, emb, pos, cW1, cb1, cW2, cb2, nullc);

    cvt_w<<<dim3(8, 4, NL),  256>>>(Wq,  qh,  ql,  DD, DD);
    cvt_w<<<dim3(8, 4, NL),  256>>>(Wk,  kh,  kl,  DD, DD);
    cvt_w<<<dim3(8, 4, NL),  256>>>(Wv,  vh,  vl,  DD, DD);
    cvt_w<<<dim3(8, 4, NL),  256>>>(Wo,  oh,  ol,  DD, DD);
    cvt_w<<<dim3(8, 16, NL), 256>>>(fW1, f1h, f1l, DD, DI);
    cvt_w<<<dim3(32, 4, NL), 256>>>(fW2, f2h, f2l, DI, DD);
    cvt_w<<<dim3(8, 4, 1),   256>>>(fcW, fch, fcl, DD, VV);
    cvt_e<<<(NL*SS*DHD/4 + 255)/256, 256>>>(E);

    dim3 gP(DD/128, BS/128);    // (4, 32)
    dim3 gF1(DI/128, BS/128);   // (16, 32)
    dim3 gA(SS/128, HH, BB);    // (16, 8, 2)

    for (int l = 0; l < NL; l++) {
        size_t wo = (size_t)l*DD*DD, w1 = (size_t)l*DD*DI;
        mma_gemm<0><<<gP, 256, GEMM_SMEM>>>(xh, xl, qh+wo, ql+wo, bq+l*DD, nullptr, nullptr, qbh, qbl, DD, DD, nullptr, nullptr);
        mma_gemm<0><<<gP, 256, GEMM_SMEM>>>(xh, xl, kh+wo, kl+wo, bk+l*DD, nullptr, nullptr, kbh, kbl, DD, DD, nullptr, nullptr);
        mma_gemm<4><<<gP, 256, GEMM_SMEM>>>(xh, xl, vh+wo, vl+wo, bv+l*DD, nullptr, nullptr, vbh, vbl, DD, DD, nullptr, nullptr);
        k_attn_tc<<<gA, 256, ATT_SMEM>>>(peh + (size_t)l*SS*DHD, pel + (size_t)l*SS*DHD);
        mma_gemm<1><<<gP, 256, GEMM_SMEM>>>(ah, al, oh+wo, ol+wo, bo+l*DD, px, pres, nullptr, nullptr, DD, DD, nullptr, nullptr);
        k_ln<<<BS, 128>>>(pres, pout1, ln1g + l*DD, ln1b + l*DD, o1h, o1l);
        mma_gemm<2><<<gF1, 256, GEMM_SMEM>>>(o1h, o1l, f1h+w1, f1l+w1, fb1+l*DI, nullptr, nullptr, hh, hl, DD, DI, ttcW, ttcb);
        mma_gemm<1><<<gP, 256, GEMM_SMEM>>>(hh, hl, f2h+w1, f2l+w1, fb2+l*DD, pout1, pres, nullptr, nullptr, DI, DD, nullptr, nullptr);
        k_ln<<<BS, 128>>>(pres, px, ln2g + l*DD, ln2b + l*DD, xh, xl);
    }
    mma_gemm<3><<<dim3(VV/128, BS/128), 256, GEMM_SMEM>>>(xh, xl, fch, fcl, fcb, nullptr, out, nullptr, nullptr, DD, VV, nullptr, nullptr);
}

// round 8
// speedup vs baseline: 3.0699x; 1.0647x over previous
#include <cuda_runtime.h>
#include <cuda_bf16.h>
#include <math.h>
#include <stdint.h>

#define BB 2
#define SS 2048
#define NCOND 2
#define STOK 2046
#define DD 512
#define HH 8
#define DHD 64
#define DI 2048
#define NL 6
#define VV 512
#define BS (BB*SS)   // 4096
#define NBH (BB*HH)  // 16

// ---------------- scratch (device globals) -----------------------------------
__device__ float g_x[BS*DD];
__device__ float g_res[BS*DD];
__device__ float g_out1[BS*DD];
__device__ float g_chordf[BS];
__device__ int   g_keypad[BS];

__device__ __align__(256) __nv_bfloat16 g_xh[BS*DD],  g_xl[BS*DD];
__device__ __align__(256) __nv_bfloat16 g_o1h[BS*DD], g_o1l[BS*DD];
__device__ __align__(256) __nv_bfloat16 g_ah[BS*DD],  g_al[BS*DD];
__device__ __align__(256) __nv_bfloat16 g_hh[(size_t)BS*DI], g_hl[(size_t)BS*DI];

// attention operands: q,k head-major [bh][s][64]; v transposed [bh][64][s]
__device__ __align__(256) __nv_bfloat16 g_qbh[(size_t)NBH*SS*DHD], g_qbl[(size_t)NBH*SS*DHD];
__device__ __align__(256) __nv_bfloat16 g_kbh[(size_t)NBH*SS*DHD], g_kbl[(size_t)NBH*SS*DHD];
__device__ __align__(256) __nv_bfloat16 g_vbh[(size_t)NBH*SS*DHD], g_vbl[(size_t)NBH*SS*DHD];
__device__ __align__(256) __nv_bfloat16 g_eh[(size_t)NL*SS*DHD],   g_el[(size_t)NL*SS*DHD];

__device__ __align__(256) __nv_bfloat16 w_qh[(size_t)NL*DD*DD], w_ql[(size_t)NL*DD*DD];
__device__ __align__(256) __nv_bfloat16 w_kh[(size_t)NL*DD*DD], w_kl[(size_t)NL*DD*DD];
__device__ __align__(256) __nv_bfloat16 w_vh[(size_t)NL*DD*DD], w_vl[(size_t)NL*DD*DD];
__device__ __align__(256) __nv_bfloat16 w_oh[(size_t)NL*DD*DD], w_ol[(size_t)NL*DD*DD];
__device__ __align__(256) __nv_bfloat16 w_f1h[(size_t)NL*DD*DI], w_f1l[(size_t)NL*DD*DI];
__device__ __align__(256) __nv_bfloat16 w_f2h[(size_t)NL*DI*DD], w_f2l[(size_t)NL*DI*DD];
__device__ __align__(256) __nv_bfloat16 w_fch[(size_t)DD*VV],    w_fcl[(size_t)DD*VV];

// ---------------- helpers -----------------------------------------------------
__device__ __forceinline__ uint32_t smem_u32(const void* p){
    uint32_t a;
    asm("{ .reg .u64 t; cvta.to.shared.u64 t, %1; cvt.u32.u64 %0, t; }" : "=r"(a) : "l"(p));
    return a;
}
__device__ __forceinline__ void cp_async16(uint32_t s, const void* g){
    asm volatile("cp.async.cg.shared.global [%0], [%1], 16;\n"
        :: "r"(s), "l"(__cvta_generic_to_global(g)) : "memory");
}
#define CP_COMMIT() asm volatile("cp.async.commit_group;\n":::"memory")
#define CP_WAIT1()  asm volatile("cp.async.wait_group 1;\n":::"memory")
#define CP_WAIT0()  asm volatile("cp.async.wait_group 0;\n":::"memory")

__device__ __forceinline__ void mma16816(float* c, uint32_t a0, uint32_t a1, uint32_t a2, uint32_t a3,
                                         uint32_t b0, uint32_t b1){
    asm volatile(
        "mma.sync.aligned.m16n8k16.row.col.f32.bf16.bf16.f32 "
        "{%0,%1,%2,%3}, {%4,%5,%6,%7}, {%8,%9}, {%0,%1,%2,%3};"
        : "+f"(c[0]), "+f"(c[1]), "+f"(c[2]), "+f"(c[3])
        : "r"(a0), "r"(a1), "r"(a2), "r"(a3), "r"(b0), "r"(b1));
}
__device__ __forceinline__ unsigned pkb(__nv_bfloat16 a, __nv_bfloat16 b){
    __nv_bfloat162 t(a, b);
    return *reinterpret_cast<unsigned*>(&t);
}
__device__ __forceinline__ void split1(float v, __nv_bfloat16& h, __nv_bfloat16& l){
    h = __float2bfloat16(v);
    l = __float2bfloat16(v - __bfloat162float(h));
}
__device__ __forceinline__ void store_split4(char* ph, char* pl, size_t boff,
                                             float v0, float v1, float v2, float v3){
    __nv_bfloat16 h0,h1,h2,h3,l0,l1,l2,l3;
    split1(v0,h0,l0); split1(v1,h1,l1); split1(v2,h2,l2); split1(v3,h3,l3);
    uint2 uh; uh.x = pkb(h0,h1); uh.y = pkb(h2,h3);
    uint2 ul; ul.x = pkb(l0,l1); ul.y = pkb(l2,l3);
    *(uint2*)(ph + boff) = uh;
    *(uint2*)(pl + boff) = ul;
}
__device__ __forceinline__ void store_split2(char* ph, char* pl, size_t boff, float v0, float v1){
    __nv_bfloat16 h0,h1,l0,l1;
    split1(v0,h0,l0); split1(v1,h1,l1);
    *(unsigned*)(ph + boff) = pkb(h0,h1);
    *(unsigned*)(pl + boff) = pkb(l0,l1);
}

// ---------------- misc --------------------------------------------------------
__global__ void k_misc(const int* __restrict__ toks, const float* __restrict__ ttc) {
    int idx = blockIdx.x * 256 + threadIdx.x;
    if (idx >= BS) return;
    int b = idx / SS, s = idx % SS;
    g_keypad[idx] = (s >= NCOND && toks[b*STOK + s - NCOND] == 0) ? 1 : 0;
    float t = (s < NCOND) ? ttc[b*STOK] : ttc[b*STOK + s - NCOND];
    g_chordf[idx] = 8.0f - t;
}

__global__ void k_build_x(const int* __restrict__ toks, const float* __restrict__ cond,
                          const float* __restrict__ emb, const float* __restrict__ pos,
                          const float* __restrict__ W1, const float* __restrict__ b1,
                          const float* __restrict__ W2, const float* __restrict__ b2,
                          const float* __restrict__ nullc) {
    int blk = blockIdx.x;
    int b = blk / SS, s = blk % SS;
    int t = threadIdx.x;
    int d0 = t*4;
    float v[4];
    if (s < NCOND) {
        __shared__ float h1[256];
        float c = cond[b*NCOND + s];
        bool isn = isnan(c);
        if (!isn) {
            for (int o = t; o < 256; o += 128)
                h1[o] = fmaxf(c * W1[s*256 + o] + b1[s*256 + o], 0.f);
        }
        __syncthreads();
        #pragma unroll
        for (int j = 0; j < 4; j++) {
            int d = d0 + j;
            float ce;
            if (isn) ce = nullc[s*DD + d];
            else {
                float acc = b2[s*DD + d];
                #pragma unroll 8
                for (int o = 0; o < 256; o++) acc += h1[o] * W2[(s*256 + o)*DD + d];
                ce = acc;
            }
            v[j] = ce + pos[s*DD + d];
        }
    } else {
        int tok = toks[b*STOK + s - NCOND];
        float4 e = *(const float4*)(emb + (size_t)tok*DD + d0);
        float4 p = *(const float4*)(pos + (size_t)s*DD + d0);
        const float SC = 22.62741699796952f;
        v[0] = e.x*SC + p.x; v[1] = e.y*SC + p.y; v[2] = e.z*SC + p.z; v[3] = e.w*SC + p.w;
    }
    *(float4*)(&g_x[(size_t)blk*DD + d0]) = make_float4(v[0], v[1], v[2], v[3]);
    store_split4((char*)g_xh, (char*)g_xl, ((size_t)blk*DD + d0)*2, v[0], v[1], v[2], v[3]);
}

// fp32 weight [K][N] -> row-major [N][K] hi/lo
__global__ void cvt_w(const float* __restrict__ W, __nv_bfloat16* __restrict__ Bh,
                      __nv_bfloat16* __restrict__ Bl, int K, int N) {
    int kt = blockIdx.x, nt = blockIdx.y, l = blockIdx.z;
    const float* Wl = W + (size_t)l*K*N;
    char* ph = (char*)Bh + (size_t)l*N*K*2;
    char* pl = (char*)Bl + (size_t)l*N*K*2;
    __shared__ float ts[64][129];
    int tid = threadIdx.x;
    int k0 = kt*64, n0 = nt*128;
    #pragma unroll
    for (int r = 0; r < 8; r++) {
        int i = tid + r*256;
        int kl = i >> 5, n4 = (i & 31) * 4;
        float4 x = *(const float4*)(Wl + (size_t)(k0 + kl)*N + n0 + n4);
        ts[kl][n4] = x.x; ts[kl][n4+1] = x.y; ts[kl][n4+2] = x.z; ts[kl][n4+3] = x.w;
    }
    __syncthreads();
    #pragma unroll
    for (int r = 0; r < 8; r++) {
        int i = tid + r*256;
        int nl = i >> 4, kc = (i & 15) * 4;
        size_t boff = ((size_t)(n0 + nl)*K + k0 + kc)*2;
        store_split4(ph, pl, boff, ts[kc][nl], ts[kc+1][nl], ts[kc+2][nl], ts[kc+3][nl]);
    }
}

// E fp32 [NL][2048][64] -> hi/lo elementwise
__global__ void cvt_e(const float* __restrict__ E) {
    size_t i = ((size_t)blockIdx.x*256 + threadIdx.x)*4;
    if (i >= (size_t)NL*SS*DHD) return;
    float4 v = *(const float4*)(E + i);
    store_split4((char*)g_eh, (char*)g_el, i*2, v.x, v.y, v.z, v.w);
}

// ---------------- mma.sync GEMM (3-term bf16 split) ---------------------------
// MODE 0: q/k head-major split. 1: acc+bias+res fp32. 2: relu+chord split. 3: acc+bias. 4: v transposed split (smem-staged).
#define GPITCH 144
#define GMAT   18432
#define GSTAGE 73728
#define GEMM_SMEM (2*GSTAGE)

template<int MODE>
__global__ __launch_bounds__(256, 1)
void mma_gemm(const __nv_bfloat16* __restrict__ Ah, const __nv_bfloat16* __restrict__ Al,
              const __nv_bfloat16* __restrict__ Bh, const __nv_bfloat16* __restrict__ Bl,
              const float* __restrict__ bias, const float* __restrict__ res,
              float* __restrict__ out, __nv_bfloat16* __restrict__ outH,
              __nv_bfloat16* __restrict__ outL,
              int K, int Ntot, const float* __restrict__ ttcW, const float* __restrict__ ttcb)
{
    extern __shared__ char smem[];
    uint32_t sbase = smem_u32(smem);
    int tid = threadIdx.x, wid = tid >> 5, lane = tid & 31;
    int g = lane >> 2, t4 = lane & 3;
    int wm = wid & 3, wn = wid >> 2;
    int mt = blockIdx.y, nt = blockIdx.x;
    int mG = mt*128, nG = nt*128;
    int KT = K >> 6;

    int mymat = tid >> 6, sub = tid & 63;
    int lr0 = sub >> 3, lch = sub & 7;
    const char* matp = (mymat == 0) ? (const char*)Ah : (mymat == 1) ? (const char*)Al
                     : (mymat == 2) ? (const char*)Bh : (const char*)Bl;
    int rowG = (mymat < 2) ? mG : nG;
    const char* srcbase = matp + ((size_t)(rowG + lr0) * K + lch*8) * 2;
    uint32_t dstbase = sbase + mymat*GMAT + lr0*GPITCH + lch*16;
    size_t srcstep = (size_t)8*K*2;

    auto load_stage = [&](int kb){
        uint32_t d = dstbase + (kb&1)*GSTAGE;
        const char* s = srcbase + (size_t)kb*128;
        #pragma unroll
        for (int i = 0; i < 16; i++){
            cp_async16(d, s);
            d += 8*GPITCH; s += srcstep;
        }
        CP_COMMIT();
    };

    load_stage(0);
    if (KT > 1) load_stage(1);

    float acc[2][8][4] = {};
    int ar0 = wm*32, bn0 = wn*64;

    for (int kb = 0; kb < KT; kb++){
        if (kb + 1 < KT) CP_WAIT1(); else CP_WAIT0();
        __syncthreads();
        const char* st = smem + (size_t)(kb&1)*GSTAGE;
        const char* sAh = st;
        const char* sAl = st + GMAT;
        const char* sBh = st + 2*GMAT;
        const char* sBl = st + 3*GMAT;
        #pragma unroll
        for (int ks = 0; ks < 4; ks++){
            int cw  = (ks*8 + t4)*4;
            int cw4 = cw + 16;
            uint32_t bh0[8], bh1[8], bl0[8], bl1[8];
            #pragma unroll
            for (int j = 0; j < 8; j++){
                int nr = (bn0 + j*8 + g)*GPITCH;
                bh0[j] = *(const uint32_t*)(sBh + nr + cw);
                bh1[j] = *(const uint32_t*)(sBh + nr + cw4);
                bl0[j] = *(const uint32_t*)(sBl + nr + cw);
                bl1[j] = *(const uint32_t*)(sBl + nr + cw4);
            }
            #pragma unroll
            for (int mi = 0; mi < 2; mi++){
                int r0 = (ar0 + mi*16 + g)*GPITCH;
                int r8 = r0 + 8*GPITCH;
                uint32_t ah0 = *(const uint32_t*)(sAh + r0 + cw);
                uint32_t ah1 = *(const uint32_t*)(sAh + r8 + cw);
                uint32_t ah2 = *(const uint32_t*)(sAh + r0 + cw4);
                uint32_t ah3 = *(const uint32_t*)(sAh + r8 + cw4);
                uint32_t al0 = *(const uint32_t*)(sAl + r0 + cw);
                uint32_t al1 = *(const uint32_t*)(sAl + r8 + cw);
                uint32_t al2 = *(const uint32_t*)(sAl + r0 + cw4);
                uint32_t al3 = *(const uint32_t*)(sAl + r8 + cw4);
                #pragma unroll
                for (int j = 0; j < 8; j++){
                    mma16816(acc[mi][j], ah0, ah1, ah2, ah3, bh0[j], bh1[j]);
                    mma16816(acc[mi][j], ah0, ah1, ah2, ah3, bl0[j], bl1[j]);
                    mma16816(acc[mi][j], al0, al1, al2, al3, bh0[j], bh1[j]);
                }
            }
        }
        __syncthreads();
        if (kb + 2 < KT) load_stage(kb + 2);
    }

    if (MODE == 4) {
        // smem-staged transpose: T[n][m] bf16, pitch 272B; then coalesced [bh][d][s] stores
        char* T = smem;
        int bA = mG >> 11;
        int sBase = mG & 2047;
        #pragma unroll 1
        for (int part = 0; part < 2; part++){
            __syncthreads();
            #pragma unroll
            for (int mi = 0; mi < 2; mi++){
                #pragma unroll
                for (int j = 0; j < 8; j++){
                    int n = bn0 + j*8 + 2*t4;
                    int mAl = ar0 + mi*16 + g, mBl = mAl + 8;
                    float bx = bias[nG + n], by = bias[nG + n + 1];
                    float v0 = acc[mi][j][0] + bx, v1 = acc[mi][j][1] + by;
                    float v2 = acc[mi][j][2] + bx, v3 = acc[mi][j][3] + by;
                    __nv_bfloat16 h, l;
                    split1(v0,h,l); *(__nv_bfloat16*)(T + n*272 + mAl*2)     = part ? l : h;
                    split1(v1,h,l); *(__nv_bfloat16*)(T + (n+1)*272 + mAl*2) = part ? l : h;
                    split1(v2,h,l); *(__nv_bfloat16*)(T + n*272 + mBl*2)     = part ? l : h;
                    split1(v3,h,l); *(__nv_bfloat16*)(T + (n+1)*272 + mBl*2) = part ? l : h;
                }
            }
            __syncthreads();
            __nv_bfloat16* dst = part ? outL : outH;
            #pragma unroll
            for (int i = 0; i < 8; i++){
                int idx = tid + 256*i;
                int row = idx >> 4, ch = idx & 15;
                int ng = nG + row;
                int head = ng >> 6, dd = ng & 63;
                uint4 val = *(const uint4*)(T + row*272 + ch*16);
                *(uint4*)((char*)dst + (((size_t)(bA*HH + head)*DHD + dd)*SS + sBase + ch*8)*2) = val;
            }
        }
        return;
    }

    #pragma unroll
    for (int mi = 0; mi < 2; mi++){
        #pragma unroll
        for (int j = 0; j < 8; j++){
            int n = nG + bn0 + j*8 + 2*t4;
            int mA = mG + ar0 + mi*16 + g;
            int mB = mA + 8;
            float c0 = acc[mi][j][0], c1 = acc[mi][j][1];
            float c2 = acc[mi][j][2], c3 = acc[mi][j][3];
            float bx = bias[n], by = bias[n+1];
            if (MODE == 0) {
                int hh_ = n >> 6, dd_ = n & 63;
                int bA = mA >> 11, sA = mA & 2047;
                int bB = mB >> 11, sB = mB & 2047;
                store_split2((char*)outH, (char*)outL,
                    ((size_t)((bA*HH + hh_)*SS + sA)*DHD + dd_)*2, c0+bx, c1+by);
                store_split2((char*)outH, (char*)outL,
                    ((size_t)((bB*HH + hh_)*SS + sB)*DHD + dd_)*2, c2+bx, c3+by);
            } else if (MODE == 1) {
                float2 rA = *(const float2*)(res + (size_t)mA*Ntot + n);
                float2 rB = *(const float2*)(res + (size_t)mB*Ntot + n);
                *(float2*)(out + (size_t)mA*Ntot + n) = make_float2(c0+bx+rA.x, c1+by+rA.y);
                *(float2*)(out + (size_t)mB*Ntot + n) = make_float2(c2+bx+rB.x, c3+by+rB.y);
            } else if (MODE == 3) {
                *(float2*)(out + (size_t)mA*Ntot + n) = make_float2(c0+bx, c1+by);
                *(float2*)(out + (size_t)mB*Ntot + n) = make_float2(c2+bx, c3+by);
            } else {
                float twx = ttcW[n], twy = ttcW[n+1];
                float tbx = ttcb[n], tby = ttcb[n+1];
                float cfA = g_chordf[mA], cfB = g_chordf[mB];
                float v0 = fmaxf(c0+bx, 0.f) + cfA*twx + tbx;
                float v1 = fmaxf(c1+by, 0.f) + cfA*twy + tby;
                float v2 = fmaxf(c2+bx, 0.f) + cfB*twx + tbx;
                float v3 = fmaxf(c3+by, 0.f) + cfB*twy + tby;
                store_split2((char*)outH, (char*)outL, ((size_t)mA*Ntot + n)*2, v0, v1);
                store_split2((char*)outH, (char*)outL, ((size_t)mB*Ntot + n)*2, v2, v3);
            }
        }
    }
}

// ---------------- layernorm ---------------------------------------------------
__global__ void k_ln(const float* __restrict__ in, float* __restrict__ out,
                     const float* __restrict__ g, const float* __restrict__ bb,
                     __nv_bfloat16* __restrict__ oh, __nv_bfloat16* __restrict__ ol) {
    int r = blockIdx.x, t = threadIdx.x;
    float4 v = *(const float4*)(in + (size_t)r*DD + t*4);
    float s  = v.x + v.y + v.z + v.w;
    float ss = v.x*v.x + v.y*v.y + v.z*v.z + v.w*v.w;
    for (int m = 16; m; m >>= 1) {
        s  += __shfl_xor_sync(0xffffffffu, s,  m);
        ss += __shfl_xor_sync(0xffffffffu, ss, m);
    }
    __shared__ float sm[4], sm2[4];
    if ((t & 31) == 0) { sm[t>>5] = s; sm2[t>>5] = ss; }
    __syncthreads();
    s  = sm[0]  + sm[1]  + sm[2]  + sm[3];
    ss = sm2[0] + sm2[1] + sm2[2] + sm2[3];
    float mu  = s * (1.0f/DD);
    float var = ss * (1.0f/DD) - mu*mu;
    float inv = rsqrtf(var + 1e-6f);
    float4 gg = *(const float4*)(g  + t*4);
    float4 bv = *(const float4*)(bb + t*4);
    float4 o;
    o.x = (v.x - mu)*inv*gg.x + bv.x;
    o.y = (v.y - mu)*inv*gg.y + bv.y;
    o.z = (v.z - mu)*inv*gg.z + bv.z;
    o.w = (v.w - mu)*inv*gg.w + bv.w;
    *(float4*)(out + (size_t)r*DD + t*4) = o;
    store_split4((char*)oh, (char*)ol, ((size_t)r*DD + t*4)*2, o.x, o.y, o.z, o.w);
}

// ---------------- tensor-core rel-pos flash attention (pipelined) -------------
// smem: K double-buf (2x36864) | E ring 256 rows hi/lo (73728) | S fp32 (67584) | kp (512)
#define AOFF_K  0
#define AOFF_E  73728
#define AOFF_S  147456
#define AOFF_KP 215040
#define ATT_SMEM 215552

__global__ __launch_bounds__(256, 1)
void k_attn_tc(const __nv_bfloat16* __restrict__ eh, const __nv_bfloat16* __restrict__ el) {
    extern __shared__ char sm[];
    int tid = threadIdx.x, w = tid >> 5, lane = tid & 31;
    int g = lane >> 2, t4 = lane & 3;
    int itile = (int)gridDim.x - 1 - (int)blockIdx.x;   // heavy first
    int i0 = itile * 128;
    int h = blockIdx.y, b = blockIdx.z, bh = b*HH + h;
    uint32_t sA = smem_u32(sm);
    int* kps = (int*)(sm + AOFF_KP);
    int r_ = 16*w + g;

    // Q fragments in registers
    uint32_t qfh[4][4], qfl[4][4];
    {
        const char* qh_ = (const char*)g_qbh + ((size_t)bh*SS*DHD)*2;
        const char* ql_ = (const char*)g_qbl + ((size_t)bh*SS*DHD)*2;
        #pragma unroll
        for (int ks = 0; ks < 4; ks++){
            size_t o0 = ((size_t)(i0 + r_)*DHD + ks*16 + 2*t4)*2;
            qfh[ks][0] = *(const uint32_t*)(qh_ + o0);
            qfh[ks][1] = *(const uint32_t*)(qh_ + o0 + 8*DHD*2);
            qfh[ks][2] = *(const uint32_t*)(qh_ + o0 + 16);
            qfh[ks][3] = *(const uint32_t*)(qh_ + o0 + 8*DHD*2 + 16);
            qfl[ks][0] = *(const uint32_t*)(ql_ + o0);
            qfl[ks][1] = *(const uint32_t*)(ql_ + o0 + 8*DHD*2);
            qfl[ks][2] = *(const uint32_t*)(ql_ + o0 + 16);
            qfl[ks][3] = *(const uint32_t*)(ql_ + o0 + 8*DHD*2 + 16);
        }
    }

    // pre-load: K(0) + full E band (one group)
    {
        #pragma unroll
        for (int i = 0; i < 8; i++){
            int idx = tid + 256*i;
            int mat = idx >> 10, r = (idx & 1023) >> 3, ch = idx & 7;
            const char* src = (const char*)(mat ? g_kbl : g_kbh)
                + ((size_t)(bh*SS + r)*DHD + ch*8)*2;
            cp_async16(sA + AOFF_K + mat*18432 + r*144 + ch*16, src);
        }
        int e00 = (itile & 1) ? 0 : 128;
        int ebase0 = 1920 - 128*itile;
        #pragma unroll
        for (int i = 0; i < 16; i++){
            int idx = tid + 256*i;
            int mat = idx >> 11, r = (idx & 2047) >> 3, ch = idx & 7;
            int m = ebase0 + r; if (m > SS-1) m = SS-1;
            int slot = r ^ e00;
            const char* src = (const char*)(mat ? el : eh) + ((size_t)m*DHD + ch*8)*2;
            cp_async16(sA + AOFF_E + mat*36864 + slot*144 + ch*16, src);
        }
        CP_COMMIT();
    }

    float oac[8][4] = {};
    float mrow[2] = {-1e30f, -1e30f};
    float lrow[2] = {0.f, 0.f};

    for (int kt = 0; kt <= itile; kt++){
        int j0 = kt*128;
        int e0 = ((kt - itile) & 1) ? 0 : 128;
        __syncthreads();   // protect V(kt-1)/S reuse
        if (tid < 128) kps[tid] = g_keypad[b*SS + j0 + tid];
        if (kt < itile){
            // prefetch K(kt+1) into other buffer
            uint32_t kb = sA + AOFF_K + ((kt+1)&1)*36864;
            #pragma unroll
            for (int i = 0; i < 8; i++){
                int idx = tid + 256*i;
                int mat = idx >> 10, r = (idx & 1023) >> 3, ch = idx & 7;
                const char* src = (const char*)(mat ? g_kbl : g_kbh)
                    + ((size_t)(bh*SS + j0 + 128 + r)*DHD + ch*8)*2;
                cp_async16(kb + mat*18432 + r*144 + ch*16, src);
            }
            CP_COMMIT();
            CP_WAIT1();
        } else {
            CP_WAIT0();
        }
        __syncthreads();

        // ---- S = Q K^T (3-term)
        const char* kbase = sm + AOFF_K + (kt&1)*36864;
        float sacc[16][4] = {};
        #pragma unroll
        for (int ks = 0; ks < 4; ks++){
            int cb = (ks*16 + 2*t4)*2;
            #pragma unroll
            for (int nf = 0; nf < 16; nf++){
                const char* kb = kbase + (nf*8+g)*144 + cb;
                uint32_t b0 = *(const uint32_t*)kb, b1 = *(const uint32_t*)(kb+16);
                uint32_t c0 = *(const uint32_t*)(kb+18432), c1 = *(const uint32_t*)(kb+18432+16);
                mma16816(sacc[nf], qfh[ks][0], qfh[ks][1], qfh[ks][2], qfh[ks][3], b0, b1);
                mma16816(sacc[nf], qfh[ks][0], qfh[ks][1], qfh[ks][2], qfh[ks][3], c0, c1);
                mma16816(sacc[nf], qfl[ks][0], qfl[ks][1], qfl[ks][2], qfl[ks][3], b0, b1);
            }
        }
        #pragma unroll
        for (int nf = 0; nf < 16; nf++){
            *(float2*)(sm + AOFF_S + r_*528 + (nf*8 + 2*t4)*4)     = make_float2(sacc[nf][0], sacc[nf][1]);
            *(float2*)(sm + AOFF_S + (r_+8)*528 + (nf*8 + 2*t4)*4) = make_float2(sacc[nf][2], sacc[nf][3]);
        }
        __syncthreads();

        // V(kt) into same buffer (K consumed)
        {
            uint32_t vb = sA + AOFF_K + (kt&1)*36864;
            #pragma unroll
            for (int i = 0; i < 8; i++){
                int idx = tid + 256*i;
                int mat = idx >> 10, r = (idx & 1023) >> 4, ch = idx & 15;
                const char* src = (const char*)(mat ? g_vbl : g_vbh)
                    + ((size_t)(bh*DHD + r)*SS + j0 + ch*8)*2;
                cp_async16(vb + mat*18432 + r*272 + ch*16, src);
            }
            CP_COMMIT();
        }

        // ---- Z = Q E^T (3-term), 3 needed chunks, scatter-add into S
        int cstart = (w < 4) ? 1 : 0;
        #pragma unroll 1
        for (int ci = 0; ci < 3; ci++){
            int chunk = cstart + ci;
            float zac[8][4] = {};
            #pragma unroll
            for (int ks = 0; ks < 4; ks++){
                int cb = (ks*16 + 2*t4)*2;
                #pragma unroll
                for (int jf = 0; jf < 8; jf++){
                    int slot = (((chunk*8+jf)*8) + g) ^ e0;
                    const char* eb = sm + AOFF_E + slot*144 + cb;
                    uint32_t b0 = *(const uint32_t*)eb, b1 = *(const uint32_t*)(eb+16);
                    uint32_t c0 = *(const uint32_t*)(eb+36864), c1 = *(const uint32_t*)(eb+36864+16);
                    mma16816(zac[jf], qfh[ks][0], qfh[ks][1], qfh[ks][2], qfh[ks][3], b0, b1);
                    mma16816(zac[jf], qfh[ks][0], qfh[ks][1], qfh[ks][2], qfh[ks][3], c0, c1);
                    mma16816(zac[jf], qfl[ks][0], qfl[ks][1], qfl[ks][2], qfl[ks][3], b0, b1);
                }
            }
            float* S0 = (float*)(sm + AOFF_S + r_*528);
            float* S1 = (float*)(sm + AOFF_S + (r_+8)*528);
            #pragma unroll
            for (int jf = 0; jf < 8; jf++){
                int u = (chunk*8+jf)*8 + 2*t4;
                int c0 = r_ + u - 127;
                if (c0 >= 0   && c0   < 128) S0[c0]   += zac[jf][0];
                if (c0+1 >= 0 && c0+1 < 128) S0[c0+1] += zac[jf][1];
                int c2 = r_ + 8 + u - 127;
                if (c2 >= 0   && c2   < 128) S1[c2]   += zac[jf][2];
                if (c2+1 >= 0 && c2+1 < 128) S1[c2+1] += zac[jf][3];
            }
        }
        __syncthreads();

        // prefetch E half for tile kt+1 (overwrites the half just consumed)
        if (kt < itile){
            int ebn = 1920 + 128*(kt - itile) + 256;
            #pragma unroll
            for (int i = 0; i < 8; i++){
                int idx = tid + 256*i;
                int mat = idx >> 10, rj = (idx & 1023) >> 3, ch = idx & 7;
                int m = ebn + rj; if (m > SS-1) m = SS-1;
                int slot = rj ^ e0;
                const char* src = (const char*)(mat ? el : eh) + ((size_t)m*DHD + ch*8)*2;
                cp_async16(sA + AOFF_E + mat*36864 + slot*144 + ch*16, src);
            }
            CP_COMMIT();
        }

        // ---- online softmax; P stays in registers (A-fragment layout == C-fragment layout)
        uint32_t pA[16], pAl[16], pB[16], pBl[16];
        #pragma unroll
        for (int mi = 0; mi < 2; mi++){
            int rr = r_ + 8*mi;
            int i = i0 + rr;
            float lv[32];
            float tm = -1e30f;
            #pragma unroll
            for (int k16 = 0; k16 < 16; k16++){
                int c = k16*8 + 2*t4;
                float2 sv = *(const float2*)(sm + AOFF_S + rr*528 + c*4);
                int j = j0 + c;
                float a = (j   <= i && kps[c]   == 0) ? sv.x*0.125f : -1e30f;
                float d = (j+1 <= i && kps[c+1] == 0) ? sv.y*0.125f : -1e30f;
                lv[2*k16] = a; lv[2*k16+1] = d;
                tm = fmaxf(tm, fmaxf(a, d));
            }
            tm = fmaxf(tm, __shfl_xor_sync(0xffffffffu, tm, 1));
            tm = fmaxf(tm, __shfl_xor_sync(0xffffffffu, tm, 2));
            float mn = fmaxf(mrow[mi], tm);
            float corr = __expf(mrow[mi] - mn);
            float rs = 0.f;
            #pragma unroll
            for (int k16 = 0; k16 < 16; k16++){
                float p0 = __expf(lv[2*k16]   - mn);
                float p1 = __expf(lv[2*k16+1] - mn);
                rs += p0 + p1;
                __nv_bfloat16 h0,l0,h1,l1;
                split1(p0,h0,l0); split1(p1,h1,l1);
                if (mi == 0){ pA[k16] = pkb(h0,h1); pAl[k16] = pkb(l0,l1); }
                else        { pB[k16] = pkb(h0,h1); pBl[k16] = pkb(l0,l1); }
            }
            rs += __shfl_xor_sync(0xffffffffu, rs, 1);
            rs += __shfl_xor_sync(0xffffffffu, rs, 2);
            lrow[mi] = lrow[mi]*corr + rs;
            mrow[mi] = mn;
            #pragma unroll
            for (int nf = 0; nf < 8; nf++){
                oac[nf][2*mi]   *= corr;
                oac[nf][2*mi+1] *= corr;
            }
        }
        if (kt < itile) CP_WAIT1(); else CP_WAIT0();
        __syncthreads();

        // ---- O += P V (3-term), P from registers
        const char* vbase = sm + AOFF_K + (kt&1)*36864;
        #pragma unroll
        for (int ks = 0; ks < 8; ks++){
            int cb = (ks*16 + 2*t4)*2;
            uint32_t a0h = pA[2*ks],  a1h = pB[2*ks],  a2h = pA[2*ks+1],  a3h = pB[2*ks+1];
            uint32_t a0l = pAl[2*ks], a1l = pBl[2*ks], a2l = pAl[2*ks+1], a3l = pBl[2*ks+1];
            #pragma unroll
            for (int nf = 0; nf < 8; nf++){
                const char* vb = vbase + (nf*8+g)*272 + cb;
                uint32_t b0 = *(const uint32_t*)vb, b1 = *(const uint32_t*)(vb+16);
                uint32_t c0 = *(const uint32_t*)(vb+18432), c1 = *(const uint32_t*)(vb+18432+16);
                mma16816(oac[nf], a0h, a1h, a2h, a3h, b0, b1);
                mma16816(oac[nf], a0l, a1l, a2l, a3l, b0, b1);
                mma16816(oac[nf], a0h, a1h, a2h, a3h, c0, c1);
            }
        }
    }

    float inv0 = 1.0f / lrow[0], inv1 = 1.0f / lrow[1];
    #pragma unroll
    for (int nf = 0; nf < 8; nf++){
        int col = h*DHD + nf*8 + 2*t4;
        size_t row0 = (size_t)(b*SS + i0 + r_);
        store_split2((char*)g_ah, (char*)g_al, (row0*DD + col)*2,
                     oac[nf][0]*inv0, oac[nf][1]*inv0);
        store_split2((char*)g_ah, (char*)g_al, ((row0+8)*DD + col)*2,
                     oac[nf][2]*inv1, oac[nf][3]*inv1);
    }
}

// ---------------- host orchestration ------------------------------------------
extern "C" void kernel_launch(void* const* d_in, const int* in_sizes, int n_in,
                              void* d_out, int out_size) {
    const int*   toks   = (const int*)  d_in[0];
    const float* cond   = (const float*)d_in[1];
    const float* ttc    = (const float*)d_in[2];
    const float* emb    = (const float*)d_in[3];
    const float* pos    = (const float*)d_in[4];
    const float* cW1    = (const float*)d_in[5];
    const float* cb1    = (const float*)d_in[6];
    const float* cW2    = (const float*)d_in[7];
    const float* cb2    = (const float*)d_in[8];
    const float* nullc  = (const float*)d_in[9];
    const float* ttcW   = (const float*)d_in[10];
    const float* ttcb   = (const float*)d_in[11];
    const float* Wq     = (const float*)d_in[12];
    const float* Wk     = (const float*)d_in[13];
    const float* Wv     = (const float*)d_in[14];
    const float* Wo     = (const float*)d_in[15];
    const float* bq     = (const float*)d_in[16];
    const float* bk     = (const float*)d_in[17];
    const float* bv     = (const float*)d_in[18];
    const float* bo     = (const float*)d_in[19];
    const float* E      = (const float*)d_in[20];
    const float* fW1    = (const float*)d_in[21];
    const float* fb1    = (const float*)d_in[22];
    const float* fW2    = (const float*)d_in[23];
    const float* fb2    = (const float*)d_in[24];
    const float* ln1g   = (const float*)d_in[25];
    const float* ln1b   = (const float*)d_in[26];
    const float* ln2g   = (const float*)d_in[27];
    const float* ln2b   = (const float*)d_in[28];
    const float* fcW    = (const float*)d_in[29];
    const float* fcb    = (const float*)d_in[30];
    float* out = (float*)d_out;

    float *px, *pres, *pout1;
    cudaGetSymbolAddress((void**)&px,    g_x);
    cudaGetSymbolAddress((void**)&pres,  g_res);
    cudaGetSymbolAddress((void**)&pout1, g_out1);
    __nv_bfloat16 *xh,*xl,*o1h,*o1l,*ah,*al,*hh,*hl;
    __nv_bfloat16 *qbh,*qbl,*kbh,*kbl,*vbh,*vbl,*peh,*pel;
    __nv_bfloat16 *qh,*ql,*kh,*kl,*vh,*vl,*oh,*ol,*f1h,*f1l,*f2h,*f2l,*fch,*fcl;
    cudaGetSymbolAddress((void**)&xh,  g_xh);  cudaGetSymbolAddress((void**)&xl,  g_xl);
    cudaGetSymbolAddress((void**)&o1h, g_o1h); cudaGetSymbolAddress((void**)&o1l, g_o1l);
    cudaGetSymbolAddress((void**)&ah,  g_ah);  cudaGetSymbolAddress((void**)&al,  g_al);
    cudaGetSymbolAddress((void**)&hh,  g_hh);  cudaGetSymbolAddress((void**)&hl,  g_hl);
    cudaGetSymbolAddress((void**)&qbh, g_qbh); cudaGetSymbolAddress((void**)&qbl, g_qbl);
    cudaGetSymbolAddress((void**)&kbh, g_kbh); cudaGetSymbolAddress((void**)&kbl, g_kbl);
    cudaGetSymbolAddress((void**)&vbh, g_vbh); cudaGetSymbolAddress((void**)&vbl, g_vbl);
    cudaGetSymbolAddress((void**)&peh, g_eh);  cudaGetSymbolAddress((void**)&pel, g_el);
    cudaGetSymbolAddress((void**)&qh,  w_qh);  cudaGetSymbolAddress((void**)&ql,  w_ql);
    cudaGetSymbolAddress((void**)&kh,  w_kh);  cudaGetSymbolAddress((void**)&kl,  w_kl);
    cudaGetSymbolAddress((void**)&vh,  w_vh);  cudaGetSymbolAddress((void**)&vl,  w_vl);
    cudaGetSymbolAddress((void**)&oh,  w_oh);  cudaGetSymbolAddress((void**)&ol,  w_ol);
    cudaGetSymbolAddress((void**)&f1h, w_f1h); cudaGetSymbolAddress((void**)&f1l, w_f1l);
    cudaGetSymbolAddress((void**)&f2h, w_f2h); cudaGetSymbolAddress((void**)&f2l, w_f2l);
    cudaGetSymbolAddress((void**)&fch, w_fch); cudaGetSymbolAddress((void**)&fcl, w_fcl);

    cudaFuncSetAttribute(k_attn_tc,   cudaFuncAttributeMaxDynamicSharedMemorySize, ATT_SMEM);
    cudaFuncSetAttribute(mma_gemm<0>, cudaFuncAttributeMaxDynamicSharedMemorySize, GEMM_SMEM);
    cudaFuncSetAttribute(mma_gemm<1>, cudaFuncAttributeMaxDynamicSharedMemorySize, GEMM_SMEM);
    cudaFuncSetAttribute(mma_gemm<2>, cudaFuncAttributeMaxDynamicSharedMemorySize, GEMM_SMEM);
    cudaFuncSetAttribute(mma_gemm<3>, cudaFuncAttributeMaxDynamicSharedMemorySize, GEMM_SMEM);
    cudaFuncSetAttribute(mma_gemm<4>, cudaFuncAttributeMaxDynamicSharedMemorySize, GEMM_SMEM);

    k_misc<<<(BS + 255)/256, 256>>>(toks, ttc);
    k_build_x<<<BS, 128>>>(toks, cond, emb, pos, cW1, cb1, cW2, cb2, nullc);

    cvt_w<<<dim3(8, 4, NL),  256>>>(Wq,  qh,  ql,  DD, DD);
    cvt_w<<<dim3(8, 4, NL),  256>>>(Wk,  kh,  kl,  DD, DD);
    cvt_w<<<dim3(8, 4, NL),  256>>>(Wv,  vh,  vl,  DD, DD);
    cvt_w<<<dim3(8, 4, NL),  256>>>(Wo,  oh,  ol,  DD, DD);
    cvt_w<<<dim3(8, 16, NL), 256>>>(fW1, f1h, f1l, DD, DI);
    cvt_w<<<dim3(32, 4, NL), 256>>>(fW2, f2h, f2l, DI, DD);
    cvt_w<<<dim3(8, 4, 1),   256>>>(fcW, fch, fcl, DD, VV);
    cvt_e<<<(NL*SS*DHD/4 + 255)/256, 256>>>(E);

    dim3 gP(DD/128, BS/128);    // (4, 32)
    dim3 gF1(DI/128, BS/128);   // (16, 32)
    dim3 gA(SS/128, HH, BB);    // (16, 8, 2)

    for (int l = 0; l < NL; l++) {
        size_t wo = (size_t)l*DD*DD, w1 = (size_t)l*DD*DI;
        mma_gemm<0><<<gP, 256, GEMM_SMEM>>>(xh, xl, qh+wo, ql+wo, bq+l*DD, nullptr, nullptr, qbh, qbl, DD, DD, nullptr, nullptr);
        mma_gemm<0><<<gP, 256, GEMM_SMEM>>>(xh, xl, kh+wo, kl+wo, bk+l*DD, nullptr, nullptr, kbh, kbl, DD, DD, nullptr, nullptr);
        mma_gemm<4><<<gP, 256, GEMM_SMEM>>>(xh, xl, vh+wo, vl+wo, bv+l*DD, nullptr, nullptr, vbh, vbl, DD, DD, nullptr, nullptr);
        k_attn_tc<<<gA, 256, ATT_SMEM>>>(peh + (size_t)l*SS*DHD, pel + (size_t)l*SS*DHD);
        mma_gemm<1><<<gP, 256, GEMM_SMEM>>>(ah, al, oh+wo, ol+wo, bo+l*DD, px, pres, nullptr, nullptr, DD, DD, nullptr, nullptr);
        k_ln<<<BS, 128>>>(pres, pout1, ln1g + l*DD, ln1b + l*DD, o1h, o1l);
        mma_gemm<2><<<gF1, 256, GEMM_SMEM>>>(o1h, o1l, f1h+w1, f1l+w1, fb1+l*DI, nullptr, nullptr, hh, hl, DD, DI, ttcW, ttcb);
        mma_gemm<1><<<gP, 256, GEMM_SMEM>>>(hh, hl, f2h+w1, f2l+w1, fb2+l*DD, pout1, pres, nullptr, nullptr, DI, DD, nullptr, nullptr);
        k_ln<<<BS, 128>>>(pres, px, ln2g + l*DD, ln2b + l*DD, xh, xl);
    }
    mma_gemm<3><<<dim3(VV/128, BS/128), 256, GEMM_SMEM>>>(xh, xl, fch, fcl, fcb, nullptr, out, nullptr, nullptr, DD, VV, nullptr, nullptr);
}

// round 9
// speedup vs baseline: 3.2257x; 1.0507x over previous
#include <cuda_runtime.h>
#include <cuda_bf16.h>
#include <math.h>
#include <stdint.h>

#define BB 2
#define SS 2048
#define NCOND 2
#define STOK 2046
#define DD 512
#define HH 8
#define DHD 64
#define DI 2048
#define NL 6
#define VV 512
#define BS (BB*SS)   // 4096
#define NBH (BB*HH)  // 16

// ---------------- scratch (device globals) -----------------------------------
__device__ float g_x[BS*DD];
__device__ float g_res[BS*DD];
__device__ float g_out1[BS*DD];
__device__ float g_chordf[BS];
__device__ int   g_keypad[BS];

__device__ __align__(256) __nv_bfloat16 g_xh[BS*DD],  g_xl[BS*DD];
__device__ __align__(256) __nv_bfloat16 g_o1h[BS*DD], g_o1l[BS*DD];
__device__ __align__(256) __nv_bfloat16 g_ah[BS*DD],  g_al[BS*DD];
__device__ __align__(256) __nv_bfloat16 g_hh[(size_t)BS*DI], g_hl[(size_t)BS*DI];

// attention operands: q,k head-major [bh][s][64]; v transposed [bh][64][s]
__device__ __align__(256) __nv_bfloat16 g_qbh[(size_t)NBH*SS*DHD], g_qbl[(size_t)NBH*SS*DHD];
__device__ __align__(256) __nv_bfloat16 g_kbh[(size_t)NBH*SS*DHD], g_kbl[(size_t)NBH*SS*DHD];
__device__ __align__(256) __nv_bfloat16 g_vbh[(size_t)NBH*SS*DHD], g_vbl[(size_t)NBH*SS*DHD];
__device__ __align__(256) __nv_bfloat16 g_eh[(size_t)NL*SS*DHD],   g_el[(size_t)NL*SS*DHD];

__device__ __align__(256) __nv_bfloat16 w_qh[(size_t)NL*DD*DD], w_ql[(size_t)NL*DD*DD];
__device__ __align__(256) __nv_bfloat16 w_kh[(size_t)NL*DD*DD], w_kl[(size_t)NL*DD*DD];
__device__ __align__(256) __nv_bfloat16 w_vh[(size_t)NL*DD*DD], w_vl[(size_t)NL*DD*DD];
__device__ __align__(256) __nv_bfloat16 w_oh[(size_t)NL*DD*DD], w_ol[(size_t)NL*DD*DD];
__device__ __align__(256) __nv_bfloat16 w_f1h[(size_t)NL*DD*DI], w_f1l[(size_t)NL*DD*DI];
__device__ __align__(256) __nv_bfloat16 w_f2h[(size_t)NL*DI*DD], w_f2l[(size_t)NL*DI*DD];
__device__ __align__(256) __nv_bfloat16 w_fch[(size_t)DD*VV],    w_fcl[(size_t)DD*VV];

// ---------------- helpers -----------------------------------------------------
__device__ __forceinline__ uint32_t smem_u32(const void* p){
    uint32_t a;
    asm("{ .reg .u64 t; cvta.to.shared.u64 t, %1; cvt.u32.u64 %0, t; }" : "=r"(a) : "l"(p));
    return a;
}
__device__ __forceinline__ void cp_async16(uint32_t s, const void* g){
    asm volatile("cp.async.cg.shared.global [%0], [%1], 16;\n"
        :: "r"(s), "l"(__cvta_generic_to_global(g)) : "memory");
}
#define CP_COMMIT() asm volatile("cp.async.commit_group;\n":::"memory")
#define CP_WAIT1()  asm volatile("cp.async.wait_group 1;\n":::"memory")
#define CP_WAIT0()  asm volatile("cp.async.wait_group 0;\n":::"memory")

__device__ __forceinline__ void mma16816(float* c, uint32_t a0, uint32_t a1, uint32_t a2, uint32_t a3,
                                         uint32_t b0, uint32_t b1){
    asm volatile(
        "mma.sync.aligned.m16n8k16.row.col.f32.bf16.bf16.f32 "
        "{%0,%1,%2,%3}, {%4,%5,%6,%7}, {%8,%9}, {%0,%1,%2,%3};"
        : "+f"(c[0]), "+f"(c[1]), "+f"(c[2]), "+f"(c[3])
        : "r"(a0), "r"(a1), "r"(a2), "r"(a3), "r"(b0), "r"(b1));
}
__device__ __forceinline__ unsigned pkb(__nv_bfloat16 a, __nv_bfloat16 b){
    __nv_bfloat162 t(a, b);
    return *reinterpret_cast<unsigned*>(&t);
}
__device__ __forceinline__ void split1(float v, __nv_bfloat16& h, __nv_bfloat16& l){
    h = __float2bfloat16(v);
    l = __float2bfloat16(v - __bfloat162float(h));
}
__device__ __forceinline__ void store_split4(char* ph, char* pl, size_t boff,
                                             float v0, float v1, float v2, float v3){
    __nv_bfloat16 h0,h1,h2,h3,l0,l1,l2,l3;
    split1(v0,h0,l0); split1(v1,h1,l1); split1(v2,h2,l2); split1(v3,h3,l3);
    uint2 uh; uh.x = pkb(h0,h1); uh.y = pkb(h2,h3);
    uint2 ul; ul.x = pkb(l0,l1); ul.y = pkb(l2,l3);
    *(uint2*)(ph + boff) = uh;
    *(uint2*)(pl + boff) = ul;
}
__device__ __forceinline__ void store_split2(char* ph, char* pl, size_t boff, float v0, float v1){
    __nv_bfloat16 h0,h1,l0,l1;
    split1(v0,h0,l0); split1(v1,h1,l1);
    *(unsigned*)(ph + boff) = pkb(h0,h1);
    *(unsigned*)(pl + boff) = pkb(l0,l1);
}

// ---------------- misc --------------------------------------------------------
__global__ void k_misc(const int* __restrict__ toks, const float* __restrict__ ttc) {
    int idx = blockIdx.x * 256 + threadIdx.x;
    if (idx >= BS) return;
    int b = idx / SS, s = idx % SS;
    g_keypad[idx] = (s >= NCOND && toks[b*STOK + s - NCOND] == 0) ? 1 : 0;
    float t = (s < NCOND) ? ttc[b*STOK] : ttc[b*STOK + s - NCOND];
    g_chordf[idx] = 8.0f - t;
}

__global__ void k_build_x(const int* __restrict__ toks, const float* __restrict__ cond,
                          const float* __restrict__ emb, const float* __restrict__ pos,
                          const float* __restrict__ W1, const float* __restrict__ b1,
                          const float* __restrict__ W2, const float* __restrict__ b2,
                          const float* __restrict__ nullc) {
    int blk = blockIdx.x;
    int b = blk / SS, s = blk % SS;
    int t = threadIdx.x;
    int d0 = t*4;
    float v[4];
    if (s < NCOND) {
        __shared__ float h1[256];
        float c = cond[b*NCOND + s];
        bool isn = isnan(c);
        if (!isn) {
            for (int o = t; o < 256; o += 128)
                h1[o] = fmaxf(c * W1[s*256 + o] + b1[s*256 + o], 0.f);
        }
        __syncthreads();
        #pragma unroll
        for (int j = 0; j < 4; j++) {
            int d = d0 + j;
            float ce;
            if (isn) ce = nullc[s*DD + d];
            else {
                float acc = b2[s*DD + d];
                #pragma unroll 8
                for (int o = 0; o < 256; o++) acc += h1[o] * W2[(s*256 + o)*DD + d];
                ce = acc;
            }
            v[j] = ce + pos[s*DD + d];
        }
    } else {
        int tok = toks[b*STOK + s - NCOND];
        float4 e = *(const float4*)(emb + (size_t)tok*DD + d0);
        float4 p = *(const float4*)(pos + (size_t)s*DD + d0);
        const float SC = 22.62741699796952f;
        v[0] = e.x*SC + p.x; v[1] = e.y*SC + p.y; v[2] = e.z*SC + p.z; v[3] = e.w*SC + p.w;
    }
    *(float4*)(&g_x[(size_t)blk*DD + d0]) = make_float4(v[0], v[1], v[2], v[3]);
    store_split4((char*)g_xh, (char*)g_xl, ((size_t)blk*DD + d0)*2, v[0], v[1], v[2], v[3]);
}

// fp32 weight [K][N] -> row-major [N][K] hi/lo (generic, single weight)
__global__ void cvt_w(const float* __restrict__ W, __nv_bfloat16* __restrict__ Bh,
                      __nv_bfloat16* __restrict__ Bl, int K, int N) {
    int kt = blockIdx.x, nt = blockIdx.y, l = blockIdx.z;
    const float* Wl = W + (size_t)l*K*N;
    char* ph = (char*)Bh + (size_t)l*N*K*2;
    char* pl = (char*)Bl + (size_t)l*N*K*2;
    __shared__ float ts[64][129];
    int tid = threadIdx.x;
    int k0 = kt*64, n0 = nt*128;
    #pragma unroll
    for (int r = 0; r < 8; r++) {
        int i = tid + r*256;
        int kl = i >> 5, n4 = (i & 31) * 4;
        float4 x = *(const float4*)(Wl + (size_t)(k0 + kl)*N + n0 + n4);
        ts[kl][n4] = x.x; ts[kl][n4+1] = x.y; ts[kl][n4+2] = x.z; ts[kl][n4+3] = x.w;
    }
    __syncthreads();
    #pragma unroll
    for (int r = 0; r < 8; r++) {
        int i = tid + r*256;
        int nl = i >> 4, kc = (i & 15) * 4;
        size_t boff = ((size_t)(n0 + nl)*K + k0 + kc)*2;
        store_split4(ph, pl, boff, ts[kc][nl], ts[kc+1][nl], ts[kc+2][nl], ts[kc+3][nl]);
    }
}

// merged q/k/v weight convert: z = l*3 + which
__global__ void cvt_w3(const float* __restrict__ Wq, const float* __restrict__ Wk,
                       const float* __restrict__ Wv) {
    int kt = blockIdx.x, nt = blockIdx.y;
    int which = blockIdx.z % 3, l = blockIdx.z / 3;
    const float* W = (which == 0) ? Wq : (which == 1) ? Wk : Wv;
    __nv_bfloat16* Bh = (which == 0) ? w_qh : (which == 1) ? w_kh : w_vh;
    __nv_bfloat16* Bl = (which == 0) ? w_ql : (which == 1) ? w_kl : w_vl;
    const float* Wl = W + (size_t)l*DD*DD;
    char* ph = (char*)Bh + (size_t)l*DD*DD*2;
    char* pl = (char*)Bl + (size_t)l*DD*DD*2;
    __shared__ float ts[64][129];
    int tid = threadIdx.x;
    int k0 = kt*64, n0 = nt*128;
    #pragma unroll
    for (int r = 0; r < 8; r++) {
        int i = tid + r*256;
        int kl = i >> 5, n4 = (i & 31) * 4;
        float4 x = *(const float4*)(Wl + (size_t)(k0 + kl)*DD + n0 + n4);
        ts[kl][n4] = x.x; ts[kl][n4+1] = x.y; ts[kl][n4+2] = x.z; ts[kl][n4+3] = x.w;
    }
    __syncthreads();
    #pragma unroll
    for (int r = 0; r < 8; r++) {
        int i = tid + r*256;
        int nl = i >> 4, kc = (i & 15) * 4;
        size_t boff = ((size_t)(n0 + nl)*DD + k0 + kc)*2;
        store_split4(ph, pl, boff, ts[kc][nl], ts[kc+1][nl], ts[kc+2][nl], ts[kc+3][nl]);
    }
}

// E fp32 [NL][2048][64] -> hi/lo elementwise
__global__ void cvt_e(const float* __restrict__ E) {
    size_t i = ((size_t)blockIdx.x*256 + threadIdx.x)*4;
    if (i >= (size_t)NL*SS*DHD) return;
    float4 v = *(const float4*)(E + i);
    store_split4((char*)g_eh, (char*)g_el, i*2, v.x, v.y, v.z, v.w);
}

// ---------------- mma.sync GEMM (3-term bf16 split) ---------------------------
#define GPITCH 144
#define GMAT   18432
#define GSTAGE 73728
#define GEMM_SMEM (2*GSTAGE)

// merged QKV projection: z=0 q (head-major), z=1 k (head-major), z=2 v (transposed)
__global__ __launch_bounds__(256, 1)
void gemm_qkv(const float* __restrict__ bq, const float* __restrict__ bk,
              const float* __restrict__ bv, int l)
{
    extern __shared__ char smem[];
    const int K = DD, KT = 8;
    uint32_t sbase = smem_u32(smem);
    int tid = threadIdx.x, wid = tid >> 5, lane = tid & 31;
    int g = lane >> 2, t4 = lane & 3;
    int wm = wid & 3, wn = wid >> 2;
    int mt = blockIdx.y, nt = blockIdx.x, z = blockIdx.z;
    int mG = mt*128, nG = nt*128;
    size_t wo = (size_t)l*DD*DD;
    const __nv_bfloat16* Bh = ((z == 0) ? w_qh : (z == 1) ? w_kh : w_vh) + wo;
    const __nv_bfloat16* Bl = ((z == 0) ? w_ql : (z == 1) ? w_kl : w_vl) + wo;
    const float* bias = ((z == 0) ? bq : (z == 1) ? bk : bv) + l*DD;

    int mymat = tid >> 6, sub = tid & 63;
    int lr0 = sub >> 3, lch = sub & 7;
    const char* matp = (mymat == 0) ? (const char*)g_xh : (mymat == 1) ? (const char*)g_xl
                     : (mymat == 2) ? (const char*)Bh : (const char*)Bl;
    int rowG = (mymat < 2) ? mG : nG;
    const char* srcbase = matp + ((size_t)(rowG + lr0) * K + lch*8) * 2;
    uint32_t dstbase = sbase + mymat*GMAT + lr0*GPITCH + lch*16;
    size_t srcstep = (size_t)8*K*2;

    auto load_stage = [&](int kb){
        uint32_t d = dstbase + (kb&1)*GSTAGE;
        const char* s = srcbase + (size_t)kb*128;
        #pragma unroll
        for (int i = 0; i < 16; i++){
            cp_async16(d, s);
            d += 8*GPITCH; s += srcstep;
        }
        CP_COMMIT();
    };
    load_stage(0);
    load_stage(1);

    float acc[2][8][4] = {};
    int ar0 = wm*32, bn0 = wn*64;

    for (int kb = 0; kb < KT; kb++){
        if (kb + 1 < KT) CP_WAIT1(); else CP_WAIT0();
        __syncthreads();
        const char* st = smem + (size_t)(kb&1)*GSTAGE;
        const char* sAh = st;
        const char* sAl = st + GMAT;
        const char* sBh = st + 2*GMAT;
        const char* sBl = st + 3*GMAT;
        #pragma unroll
        for (int ks = 0; ks < 4; ks++){
            int cw  = (ks*8 + t4)*4;
            int cw4 = cw + 16;
            uint32_t bh0[8], bh1[8], bl0[8], bl1[8];
            #pragma unroll
            for (int j = 0; j < 8; j++){
                int nr = (bn0 + j*8 + g)*GPITCH;
                bh0[j] = *(const uint32_t*)(sBh + nr + cw);
                bh1[j] = *(const uint32_t*)(sBh + nr + cw4);
                bl0[j] = *(const uint32_t*)(sBl + nr + cw);
                bl1[j] = *(const uint32_t*)(sBl + nr + cw4);
            }
            #pragma unroll
            for (int mi = 0; mi < 2; mi++){
                int r0 = (ar0 + mi*16 + g)*GPITCH;
                int r8 = r0 + 8*GPITCH;
                uint32_t ah0 = *(const uint32_t*)(sAh + r0 + cw);
                uint32_t ah1 = *(const uint32_t*)(sAh + r8 + cw);
                uint32_t ah2 = *(const uint32_t*)(sAh + r0 + cw4);
                uint32_t ah3 = *(const uint32_t*)(sAh + r8 + cw4);
                uint32_t al0 = *(const uint32_t*)(sAl + r0 + cw);
                uint32_t al1 = *(const uint32_t*)(sAl + r8 + cw);
                uint32_t al2 = *(const uint32_t*)(sAl + r0 + cw4);
                uint32_t al3 = *(const uint32_t*)(sAl + r8 + cw4);
                #pragma unroll
                for (int j = 0; j < 8; j++){
                    mma16816(acc[mi][j], ah0, ah1, ah2, ah3, bh0[j], bh1[j]);
                    mma16816(acc[mi][j], ah0, ah1, ah2, ah3, bl0[j], bl1[j]);
                    mma16816(acc[mi][j], al0, al1, al2, al3, bh0[j], bh1[j]);
                }
            }
        }
        __syncthreads();
        if (kb + 2 < KT) load_stage(kb + 2);
    }

    if (z < 2) {
        __nv_bfloat16* outH = (z == 0) ? g_qbh : g_kbh;
        __nv_bfloat16* outL = (z == 0) ? g_qbl : g_kbl;
        #pragma unroll
        for (int mi = 0; mi < 2; mi++){
            #pragma unroll
            for (int j = 0; j < 8; j++){
                int n = nG + bn0 + j*8 + 2*t4;
                int mA = mG + ar0 + mi*16 + g;
                int mB = mA + 8;
                float bx = bias[n], by = bias[n+1];
                int hh_ = n >> 6, dd_ = n & 63;
                int bA = mA >> 11, sA = mA & 2047;
                int bB = mB >> 11, sB = mB & 2047;
                store_split2((char*)outH, (char*)outL,
                    ((size_t)((bA*HH + hh_)*SS + sA)*DHD + dd_)*2,
                    acc[mi][j][0]+bx, acc[mi][j][1]+by);
                store_split2((char*)outH, (char*)outL,
                    ((size_t)((bB*HH + hh_)*SS + sB)*DHD + dd_)*2,
                    acc[mi][j][2]+bx, acc[mi][j][3]+by);
            }
        }
    } else {
        // smem-staged transpose -> g_vbh/g_vbl [bh][d][s]
        char* T = smem;
        int bA = mG >> 11;
        int sBase = mG & 2047;
        #pragma unroll 1
        for (int part = 0; part < 2; part++){
            __syncthreads();
            #pragma unroll
            for (int mi = 0; mi < 2; mi++){
                #pragma unroll
                for (int j = 0; j < 8; j++){
                    int n = bn0 + j*8 + 2*t4;
                    int mAl = ar0 + mi*16 + g, mBl = mAl + 8;
                    float bx = bias[nG + n], by = bias[nG + n + 1];
                    float v0 = acc[mi][j][0] + bx, v1 = acc[mi][j][1] + by;
                    float v2 = acc[mi][j][2] + bx, v3 = acc[mi][j][3] + by;
                    __nv_bfloat16 h, l;
                    split1(v0,h,l); *(__nv_bfloat16*)(T + n*272 + mAl*2)     = part ? l : h;
                    split1(v1,h,l); *(__nv_bfloat16*)(T + (n+1)*272 + mAl*2) = part ? l : h;
                    split1(v2,h,l); *(__nv_bfloat16*)(T + n*272 + mBl*2)     = part ? l : h;
                    split1(v3,h,l); *(__nv_bfloat16*)(T + (n+1)*272 + mBl*2) = part ? l : h;
                }
            }
            __syncthreads();
            __nv_bfloat16* dst = part ? g_vbl : g_vbh;
            #pragma unroll
            for (int i = 0; i < 8; i++){
                int idx = tid + 256*i;
                int row = idx >> 4, ch = idx & 15;
                int ng = nG + row;
                int head = ng >> 6, dd = ng & 63;
                uint4 val = *(const uint4*)(T + row*272 + ch*16);
                *(uint4*)((char*)dst + (((size_t)(bA*HH + head)*DHD + dd)*SS + sBase + ch*8)*2) = val;
            }
        }
    }
}

// generic GEMM. MODE 1: acc+bias+res fp32. 2: relu+chord split. 3: acc+bias fp32.
template<int MODE>
__global__ __launch_bounds__(256, 1)
void mma_gemm(const __nv_bfloat16* __restrict__ Ah, const __nv_bfloat16* __restrict__ Al,
              const __nv_bfloat16* __restrict__ Bh, const __nv_bfloat16* __restrict__ Bl,
              const float* __restrict__ bias, const float* __restrict__ res,
              float* __restrict__ out, __nv_bfloat16* __restrict__ outH,
              __nv_bfloat16* __restrict__ outL,
              int K, int Ntot, const float* __restrict__ ttcW, const float* __restrict__ ttcb)
{
    extern __shared__ char smem[];
    uint32_t sbase = smem_u32(smem);
    int tid = threadIdx.x, wid = tid >> 5, lane = tid & 31;
    int g = lane >> 2, t4 = lane & 3;
    int wm = wid & 3, wn = wid >> 2;
    int mt = blockIdx.y, nt = blockIdx.x;
    int mG = mt*128, nG = nt*128;
    int KT = K >> 6;

    int mymat = tid >> 6, sub = tid & 63;
    int lr0 = sub >> 3, lch = sub & 7;
    const char* matp = (mymat == 0) ? (const char*)Ah : (mymat == 1) ? (const char*)Al
                     : (mymat == 2) ? (const char*)Bh : (const char*)Bl;
    int rowG = (mymat < 2) ? mG : nG;
    const char* srcbase = matp + ((size_t)(rowG + lr0) * K + lch*8) * 2;
    uint32_t dstbase = sbase + mymat*GMAT + lr0*GPITCH + lch*16;
    size_t srcstep = (size_t)8*K*2;

    auto load_stage = [&](int kb){
        uint32_t d = dstbase + (kb&1)*GSTAGE;
        const char* s = srcbase + (size_t)kb*128;
        #pragma unroll
        for (int i = 0; i < 16; i++){
            cp_async16(d, s);
            d += 8*GPITCH; s += srcstep;
        }
        CP_COMMIT();
    };
    load_stage(0);
    if (KT > 1) load_stage(1);

    float acc[2][8][4] = {};
    int ar0 = wm*32, bn0 = wn*64;

    for (int kb = 0; kb < KT; kb++){
        if (kb + 1 < KT) CP_WAIT1(); else CP_WAIT0();
        __syncthreads();
        const char* st = smem + (size_t)(kb&1)*GSTAGE;
        const char* sAh = st;
        const char* sAl = st + GMAT;
        const char* sBh = st + 2*GMAT;
        const char* sBl = st + 3*GMAT;
        #pragma unroll
        for (int ks = 0; ks < 4; ks++){
            int cw  = (ks*8 + t4)*4;
            int cw4 = cw + 16;
            uint32_t bh0[8], bh1[8], bl0[8], bl1[8];
            #pragma unroll
            for (int j = 0; j < 8; j++){
                int nr = (bn0 + j*8 + g)*GPITCH;
                bh0[j] = *(const uint32_t*)(sBh + nr + cw);
                bh1[j] = *(const uint32_t*)(sBh + nr + cw4);
                bl0[j] = *(const uint32_t*)(sBl + nr + cw);
                bl1[j] = *(const uint32_t*)(sBl + nr + cw4);
            }
            #pragma unroll
            for (int mi = 0; mi < 2; mi++){
                int r0 = (ar0 + mi*16 + g)*GPITCH;
                int r8 = r0 + 8*GPITCH;
                uint32_t ah0 = *(const uint32_t*)(sAh + r0 + cw);
                uint32_t ah1 = *(const uint32_t*)(sAh + r8 + cw);
                uint32_t ah2 = *(const uint32_t*)(sAh + r0 + cw4);
                uint32_t ah3 = *(const uint32_t*)(sAh + r8 + cw4);
                uint32_t al0 = *(const uint32_t*)(sAl + r0 + cw);
                uint32_t al1 = *(const uint32_t*)(sAl + r8 + cw);
                uint32_t al2 = *(const uint32_t*)(sAl + r0 + cw4);
                uint32_t al3 = *(const uint32_t*)(sAl + r8 + cw4);
                #pragma unroll
                for (int j = 0; j < 8; j++){
                    mma16816(acc[mi][j], ah0, ah1, ah2, ah3, bh0[j], bh1[j]);
                    mma16816(acc[mi][j], ah0, ah1, ah2, ah3, bl0[j], bl1[j]);
                    mma16816(acc[mi][j], al0, al1, al2, al3, bh0[j], bh1[j]);
                }
            }
        }
        __syncthreads();
        if (kb + 2 < KT) load_stage(kb + 2);
    }

    #pragma unroll
    for (int mi = 0; mi < 2; mi++){
        #pragma unroll
        for (int j = 0; j < 8; j++){
            int n = nG + bn0 + j*8 + 2*t4;
            int mA = mG + ar0 + mi*16 + g;
            int mB = mA + 8;
            float c0 = acc[mi][j][0], c1 = acc[mi][j][1];
            float c2 = acc[mi][j][2], c3 = acc[mi][j][3];
            float bx = bias[n], by = bias[n+1];
            if (MODE == 1) {
                float2 rA = *(const float2*)(res + (size_t)mA*Ntot + n);
                float2 rB = *(const float2*)(res + (size_t)mB*Ntot + n);
                *(float2*)(out + (size_t)mA*Ntot + n) = make_float2(c0+bx+rA.x, c1+by+rA.y);
                *(float2*)(out + (size_t)mB*Ntot + n) = make_float2(c2+bx+rB.x, c3+by+rB.y);
            } else if (MODE == 3) {
                *(float2*)(out + (size_t)mA*Ntot + n) = make_float2(c0+bx, c1+by);
                *(float2*)(out + (size_t)mB*Ntot + n) = make_float2(c2+bx, c3+by);
            } else {
                float twx = ttcW[n], twy = ttcW[n+1];
                float tbx = ttcb[n], tby = ttcb[n+1];
                float cfA = g_chordf[mA], cfB = g_chordf[mB];
                float v0 = fmaxf(c0+bx, 0.f) + cfA*twx + tbx;
                float v1 = fmaxf(c1+by, 0.f) + cfA*twy + tby;
                float v2 = fmaxf(c2+bx, 0.f) + cfB*twx + tbx;
                float v3 = fmaxf(c3+by, 0.f) + cfB*twy + tby;
                store_split2((char*)outH, (char*)outL, ((size_t)mA*Ntot + n)*2, v0, v1);
                store_split2((char*)outH, (char*)outL, ((size_t)mB*Ntot + n)*2, v2, v3);
            }
        }
    }
}

// ---------------- layernorm ---------------------------------------------------
__global__ void k_ln(const float* __restrict__ in, float* __restrict__ out,
                     const float* __restrict__ g, const float* __restrict__ bb,
                     __nv_bfloat16* __restrict__ oh, __nv_bfloat16* __restrict__ ol) {
    int r = blockIdx.x, t = threadIdx.x;
    float4 v = *(const float4*)(in + (size_t)r*DD + t*4);
    float s  = v.x + v.y + v.z + v.w;
    float ss = v.x*v.x + v.y*v.y + v.z*v.z + v.w*v.w;
    for (int m = 16; m; m >>= 1) {
        s  += __shfl_xor_sync(0xffffffffu, s,  m);
        ss += __shfl_xor_sync(0xffffffffu, ss, m);
    }
    __shared__ float sm[4], sm2[4];
    if ((t & 31) == 0) { sm[t>>5] = s; sm2[t>>5] = ss; }
    __syncthreads();
    s  = sm[0]  + sm[1]  + sm[2]  + sm[3];
    ss = sm2[0] + sm2[1] + sm2[2] + sm2[3];
    float mu  = s * (1.0f/DD);
    float var = ss * (1.0f/DD) - mu*mu;
    float inv = rsqrtf(var + 1e-6f);
    float4 gg = *(const float4*)(g  + t*4);
    float4 bv = *(const float4*)(bb + t*4);
    float4 o;
    o.x = (v.x - mu)*inv*gg.x + bv.x;
    o.y = (v.y - mu)*inv*gg.y + bv.y;
    o.z = (v.z - mu)*inv*gg.z + bv.z;
    o.w = (v.w - mu)*inv*gg.w + bv.w;
    *(float4*)(out + (size_t)r*DD + t*4) = o;
    store_split4((char*)oh, (char*)ol, ((size_t)r*DD + t*4)*2, o.x, o.y, o.z, o.w);
}

// ---------------- tensor-core rel-pos flash attention (pipelined) -------------
// smem: K double-buf (2x36864) | E ring 256 rows hi/lo (73728) | S fp32 (67584) | kp (512)
#define AOFF_K  0
#define AOFF_E  73728
#define AOFF_S  147456
#define AOFF_KP 215040
#define ATT_SMEM 215552

__global__ __launch_bounds__(256, 1)
void k_attn_tc(const __nv_bfloat16* __restrict__ eh, const __nv_bfloat16* __restrict__ el) {
    extern __shared__ char sm[];
    int tid = threadIdx.x, w = tid >> 5, lane = tid & 31;
    int g = lane >> 2, t4 = lane & 3;
    int itile = (int)gridDim.x - 1 - (int)blockIdx.x;   // heavy first
    int i0 = itile * 128;
    int h = blockIdx.y, b = blockIdx.z, bh = b*HH + h;
    uint32_t sA = smem_u32(sm);
    int* kps = (int*)(sm + AOFF_KP);
    int r_ = 16*w + g;

    // Q fragments in registers
    uint32_t qfh[4][4], qfl[4][4];
    {
        const char* qh_ = (const char*)g_qbh + ((size_t)bh*SS*DHD)*2;
        const char* ql_ = (const char*)g_qbl + ((size_t)bh*SS*DHD)*2;
        #pragma unroll
        for (int ks = 0; ks < 4; ks++){
            size_t o0 = ((size_t)(i0 + r_)*DHD + ks*16 + 2*t4)*2;
            qfh[ks][0] = *(const uint32_t*)(qh_ + o0);
            qfh[ks][1] = *(const uint32_t*)(qh_ + o0 + 8*DHD*2);
            qfh[ks][2] = *(const uint32_t*)(qh_ + o0 + 16);
            qfh[ks][3] = *(const uint32_t*)(qh_ + o0 + 8*DHD*2 + 16);
            qfl[ks][0] = *(const uint32_t*)(ql_ + o0);
            qfl[ks][1] = *(const uint32_t*)(ql_ + o0 + 8*DHD*2);
            qfl[ks][2] = *(const uint32_t*)(ql_ + o0 + 16);
            qfl[ks][3] = *(const uint32_t*)(ql_ + o0 + 8*DHD*2 + 16);
        }
    }

    // pre-load: K(0) + full E band
    {
        #pragma unroll
        for (int i = 0; i < 8; i++){
            int idx = tid + 256*i;
            int mat = idx >> 10, r = (idx & 1023) >> 3, ch = idx & 7;
            const char* src = (const char*)(mat ? g_kbl : g_kbh)
                + ((size_t)(bh*SS + r)*DHD + ch*8)*2;
            cp_async16(sA + AOFF_K + mat*18432 + r*144 + ch*16, src);
        }
        int e00 = (itile & 1) ? 0 : 128;
        int ebase0 = 1920 - 128*itile;
        #pragma unroll
        for (int i = 0; i < 16; i++){
            int idx = tid + 256*i;
            int mat = idx >> 11, r = (idx & 2047) >> 3, ch = idx & 7;
            int m = ebase0 + r; if (m > SS-1) m = SS-1;
            int slot = r ^ e00;
            const char* src = (const char*)(mat ? el : eh) + ((size_t)m*DHD + ch*8)*2;
            cp_async16(sA + AOFF_E + mat*36864 + slot*144 + ch*16, src);
        }
        CP_COMMIT();
    }

    float oac[8][4] = {};
    float mrow[2] = {-1e30f, -1e30f};
    float lrow[2] = {0.f, 0.f};

    for (int kt = 0; kt <= itile; kt++){
        int j0 = kt*128;
        int e0 = ((kt - itile) & 1) ? 0 : 128;
        __syncthreads();
        if (tid < 128) kps[tid] = g_keypad[b*SS + j0 + tid];
        if (kt < itile){
            uint32_t kb = sA + AOFF_K + ((kt+1)&1)*36864;
            #pragma unroll
            for (int i = 0; i < 8; i++){
                int idx = tid + 256*i;
                int mat = idx >> 10, r = (idx & 1023) >> 3, ch = idx & 7;
                const char* src = (const char*)(mat ? g_kbl : g_kbh)
                    + ((size_t)(bh*SS + j0 + 128 + r)*DHD + ch*8)*2;
                cp_async16(kb + mat*18432 + r*144 + ch*16, src);
            }
            CP_COMMIT();
            CP_WAIT1();
        } else {
            CP_WAIT0();
        }
        __syncthreads();

        // ---- S = Q K^T (3-term)
        const char* kbase = sm + AOFF_K + (kt&1)*36864;
        float sacc[16][4] = {};
        #pragma unroll
        for (int ks = 0; ks < 4; ks++){
            int cb = (ks*16 + 2*t4)*2;
            #pragma unroll
            for (int nf = 0; nf < 16; nf++){
                const char* kb = kbase + (nf*8+g)*144 + cb;
                uint32_t b0 = *(const uint32_t*)kb, b1 = *(const uint32_t*)(kb+16);
                uint32_t c0 = *(const uint32_t*)(kb+18432), c1 = *(const uint32_t*)(kb+18432+16);
                mma16816(sacc[nf], qfh[ks][0], qfh[ks][1], qfh[ks][2], qfh[ks][3], b0, b1);
                mma16816(sacc[nf], qfh[ks][0], qfh[ks][1], qfh[ks][2], qfh[ks][3], c0, c1);
                mma16816(sacc[nf], qfl[ks][0], qfl[ks][1], qfl[ks][2], qfl[ks][3], b0, b1);
            }
        }
        #pragma unroll
        for (int nf = 0; nf < 16; nf++){
            *(float2*)(sm + AOFF_S + r_*528 + (nf*8 + 2*t4)*4)     = make_float2(sacc[nf][0], sacc[nf][1]);
            *(float2*)(sm + AOFF_S + (r_+8)*528 + (nf*8 + 2*t4)*4) = make_float2(sacc[nf][2], sacc[nf][3]);
        }
        __syncthreads();

        // V(kt) into same buffer (K consumed)
        {
            uint32_t vb = sA + AOFF_K + (kt&1)*36864;
            #pragma unroll
            for (int i = 0; i < 8; i++){
                int idx = tid + 256*i;
                int mat = idx >> 10, r = (idx & 1023) >> 4, ch = idx & 15;
                const char* src = (const char*)(mat ? g_vbl : g_vbh)
                    + ((size_t)(bh*DHD + r)*SS + j0 + ch*8)*2;
                cp_async16(vb + mat*18432 + r*272 + ch*16, src);
            }
            CP_COMMIT();
        }

        // ---- Z = Q E^T (3-term), exact 18-fragment band per warp, scatter-add into S
        {
            int f0 = 14 - 2*w;
            #pragma unroll 1
            for (int ci = 0; ci < 3; ci++){
                float zac[6][4] = {};
                #pragma unroll
                for (int ks = 0; ks < 4; ks++){
                    int cb = (ks*16 + 2*t4)*2;
                    #pragma unroll
                    for (int jf = 0; jf < 6; jf++){
                        int frag = f0 + ci*6 + jf;
                        int slot = (frag*8 + g) ^ e0;
                        const char* eb = sm + AOFF_E + slot*144 + cb;
                        uint32_t b0 = *(const uint32_t*)eb, b1 = *(const uint32_t*)(eb+16);
                        uint32_t c0 = *(const uint32_t*)(eb+36864), c1 = *(const uint32_t*)(eb+36864+16);
                        mma16816(zac[jf], qfh[ks][0], qfh[ks][1], qfh[ks][2], qfh[ks][3], b0, b1);
                        mma16816(zac[jf], qfh[ks][0], qfh[ks][1], qfh[ks][2], qfh[ks][3], c0, c1);
                        mma16816(zac[jf], qfl[ks][0], qfl[ks][1], qfl[ks][2], qfl[ks][3], b0, b1);
                    }
                }
                float* S0 = (float*)(sm + AOFF_S + r_*528);
                float* S1 = (float*)(sm + AOFF_S + (r_+8)*528);
                #pragma unroll
                for (int jf = 0; jf < 6; jf++){
                    int u = (f0 + ci*6 + jf)*8 + 2*t4;
                    int c0 = r_ + u - 127;
                    if (c0 >= 0   && c0   < 128) S0[c0]   += zac[jf][0];
                    if (c0+1 >= 0 && c0+1 < 128) S0[c0+1] += zac[jf][1];
                    int c2 = r_ + 8 + u - 127;
                    if (c2 >= 0   && c2   < 128) S1[c2]   += zac[jf][2];
                    if (c2+1 >= 0 && c2+1 < 128) S1[c2+1] += zac[jf][3];
                }
            }
        }
        __syncthreads();

        // prefetch E half for tile kt+1
        if (kt < itile){
            int ebn = 1920 + 128*(kt - itile) + 256;
            #pragma unroll
            for (int i = 0; i < 8; i++){
                int idx = tid + 256*i;
                int mat = idx >> 10, rj = (idx & 1023) >> 3, ch = idx & 7;
                int m = ebn + rj; if (m > SS-1) m = SS-1;
                int slot = rj ^ e0;
                const char* src = (const char*)(mat ? el : eh) + ((size_t)m*DHD + ch*8)*2;
                cp_async16(sA + AOFF_E + mat*36864 + slot*144 + ch*16, src);
            }
            CP_COMMIT();
        }

        // ---- online softmax; P stays in registers
        uint32_t pA[16], pAl[16], pB[16], pBl[16];
        #pragma unroll
        for (int mi = 0; mi < 2; mi++){
            int rr = r_ + 8*mi;
            int i = i0 + rr;
            float lv[32];
            float tm = -1e30f;
            #pragma unroll
            for (int k16 = 0; k16 < 16; k16++){
                int c = k16*8 + 2*t4;
                float2 sv = *(const float2*)(sm + AOFF_S + rr*528 + c*4);
                int j = j0 + c;
                float a = (j   <= i && kps[c]   == 0) ? sv.x*0.125f : -1e30f;
                float d = (j+1 <= i && kps[c+1] == 0) ? sv.y*0.125f : -1e30f;
                lv[2*k16] = a; lv[2*k16+1] = d;
                tm = fmaxf(tm, fmaxf(a, d));
            }
            tm = fmaxf(tm, __shfl_xor_sync(0xffffffffu, tm, 1));
            tm = fmaxf(tm, __shfl_xor_sync(0xffffffffu, tm, 2));
            float mn = fmaxf(mrow[mi], tm);
            float corr = __expf(mrow[mi] - mn);
            float rs = 0.f;
            #pragma unroll
            for (int k16 = 0; k16 < 16; k16++){
                float p0 = __expf(lv[2*k16]   - mn);
                float p1 = __expf(lv[2*k16+1] - mn);
                rs += p0 + p1;
                __nv_bfloat16 h0,l0,h1,l1;
                split1(p0,h0,l0); split1(p1,h1,l1);
                if (mi == 0){ pA[k16] = pkb(h0,h1); pAl[k16] = pkb(l0,l1); }
                else        { pB[k16] = pkb(h0,h1); pBl[k16] = pkb(l0,l1); }
            }
            rs += __shfl_xor_sync(0xffffffffu, rs, 1);
            rs += __shfl_xor_sync(0xffffffffu, rs, 2);
            lrow[mi] = lrow[mi]*corr + rs;
            mrow[mi] = mn;
            #pragma unroll
            for (int nf = 0; nf < 8; nf++){
                oac[nf][2*mi]   *= corr;
                oac[nf][2*mi+1] *= corr;
            }
        }
        if (kt < itile) CP_WAIT1(); else CP_WAIT0();
        __syncthreads();

        // ---- O += P V (3-term), P from registers
        const char* vbase = sm + AOFF_K + (kt&1)*36864;
        #pragma unroll
        for (int ks = 0; ks < 8; ks++){
            int cb = (ks*16 + 2*t4)*2;
            uint32_t a0h = pA[2*ks],  a1h = pB[2*ks],  a2h = pA[2*ks+1],  a3h = pB[2*ks+1];
            uint32_t a0l = pAl[2*ks], a1l = pBl[2*ks], a2l = pAl[2*ks+1], a3l = pBl[2*ks+1];
            #pragma unroll
            for (int nf = 0; nf < 8; nf++){
                const char* vb = vbase + (nf*8+g)*272 + cb;
                uint32_t b0 = *(const uint32_t*)vb, b1 = *(const uint32_t*)(vb+16);
                uint32_t c0 = *(const uint32_t*)(vb+18432), c1 = *(const uint32_t*)(vb+18432+16);
                mma16816(oac[nf], a0h, a1h, a2h, a3h, b0, b1);
                mma16816(oac[nf], a0l, a1l, a2l, a3l, b0, b1);
                mma16816(oac[nf], a0h, a1h, a2h, a3h, c0, c1);
            }
        }
    }

    float inv0 = 1.0f / lrow[0], inv1 = 1.0f / lrow[1];
    #pragma unroll
    for (int nf = 0; nf < 8; nf++){
        int col = h*DHD + nf*8 + 2*t4;
        size_t row0 = (size_t)(b*SS + i0 + r_);
        store_split2((char*)g_ah, (char*)g_al, (row0*DD + col)*2,
                     oac[nf][0]*inv0, oac[nf][1]*inv0);
        store_split2((char*)g_ah, (char*)g_al, ((row0+8)*DD + col)*2,
                     oac[nf][2]*inv1, oac[nf][3]*inv1);
    }
}

// ---------------- host orchestration ------------------------------------------
extern "C" void kernel_launch(void* const* d_in, const int* in_sizes, int n_in,
                              void* d_out, int out_size) {
    const int*   toks   = (const int*)  d_in[0];
    const float* cond   = (const float*)d_in[1];
    const float* ttc    = (const float*)d_in[2];
    const float* emb    = (const float*)d_in[3];
    const float* pos    = (const float*)d_in[4];
    const float* cW1    = (const float*)d_in[5];
    const float* cb1    = (const float*)d_in[6];
    const float* cW2    = (const float*)d_in[7];
    const float* cb2    = (const float*)d_in[8];
    const float* nullc  = (const float*)d_in[9];
    const float* ttcW   = (const float*)d_in[10];
    const float* ttcb   = (const float*)d_in[11];
    const float* Wq     = (const float*)d_in[12];
    const float* Wk     = (const float*)d_in[13];
    const float* Wv     = (const float*)d_in[14];
    const float* Wo     = (const float*)d_in[15];
    const float* bq     = (const float*)d_in[16];
    const float* bk     = (const float*)d_in[17];
    const float* bv     = (const float*)d_in[18];
    const float* bo     = (const float*)d_in[19];
    const float* E      = (const float*)d_in[20];
    const float* fW1    = (const float*)d_in[21];
    const float* fb1    = (const float*)d_in[22];
    const float* fW2    = (const float*)d_in[23];
    const float* fb2    = (const float*)d_in[24];
    const float* ln1g   = (const float*)d_in[25];
    const float* ln1b   = (const float*)d_in[26];
    const float* ln2g   = (const float*)d_in[27];
    const float* ln2b   = (const float*)d_in[28];
    const float* fcW    = (const float*)d_in[29];
    const float* fcb    = (const float*)d_in[30];
    float* out = (float*)d_out;

    float *px, *pres, *pout1;
    cudaGetSymbolAddress((void**)&px,    g_x);
    cudaGetSymbolAddress((void**)&pres,  g_res);
    cudaGetSymbolAddress((void**)&pout1, g_out1);
    __nv_bfloat16 *xh,*xl,*o1h,*o1l,*ah,*al,*hh,*hl,*peh,*pel;
    __nv_bfloat16 *oh,*ol,*f1h,*f1l,*f2h,*f2l,*fch,*fcl;
    cudaGetSymbolAddress((void**)&xh,  g_xh);  cudaGetSymbolAddress((void**)&xl,  g_xl);
    cudaGetSymbolAddress((void**)&o1h, g_o1h); cudaGetSymbolAddress((void**)&o1l, g_o1l);
    cudaGetSymbolAddress((void**)&ah,  g_ah);  cudaGetSymbolAddress((void**)&al,  g_al);
    cudaGetSymbolAddress((void**)&hh,  g_hh);  cudaGetSymbolAddress((void**)&hl,  g_hl);
    cudaGetSymbolAddress((void**)&peh, g_eh);  cudaGetSymbolAddress((void**)&pel, g_el);
    cudaGetSymbolAddress((void**)&oh,  w_oh);  cudaGetSymbolAddress((void**)&ol,  w_ol);
    cudaGetSymbolAddress((void**)&f1h, w_f1h); cudaGetSymbolAddress((void**)&f1l, w_f1l);
    cudaGetSymbolAddress((void**)&f2h, w_f2h); cudaGetSymbolAddress((void**)&f2l, w_f2l);
    cudaGetSymbolAddress((void**)&fch, w_fch); cudaGetSymbolAddress((void**)&fcl, w_fcl);

    cudaFuncSetAttribute(k_attn_tc,   cudaFuncAttributeMaxDynamicSharedMemorySize, ATT_SMEM);
    cudaFuncSetAttribute(gemm_qkv,    cudaFuncAttributeMaxDynamicSharedMemorySize, GEMM_SMEM);
    cudaFuncSetAttribute(mma_gemm<1>, cudaFuncAttributeMaxDynamicSharedMemorySize, GEMM_SMEM);
    cudaFuncSetAttribute(mma_gemm<2>, cudaFuncAttributeMaxDynamicSharedMemorySize, GEMM_SMEM);
    cudaFuncSetAttribute(mma_gemm<3>, cudaFuncAttributeMaxDynamicSharedMemorySize, GEMM_SMEM);

    dim3 gP(DD/128, BS/128);    // (4, 32)
    dim3 gQKV(DD/128, BS/128, 3);
    dim3 gF1(DI/128, BS/128);   // (16, 32)
    dim3 gA(SS/128, HH, BB);    // (16, 8, 2)

    // launches 1-5, so launch #6 (ncu -s 5 -c 1 capture target) is k_attn_tc
    k_misc<<<(BS + 255)/256, 256>>>(toks, ttc);                              // 1
    k_build_x<<<BS, 128>>>(toks, cond, emb, pos, cW1, cb1, cW2, cb2, nullc); // 2
    cvt_w3<<<dim3(8, 4, NL*3), 256>>>(Wq, Wk, Wv);                           // 3
    cvt_e<<<(NL*SS*DHD/4 + 255)/256, 256>>>(E);                              // 4

    for (int l = 0; l < NL; l++) {
        size_t wo = (size_t)l*DD*DD, w1 = (size_t)l*DD*DI;
        gemm_qkv<<<gQKV, 256, GEMM_SMEM>>>(bq, bk, bv, l);                   // 5 (l=0)
        k_attn_tc<<<gA, 256, ATT_SMEM>>>(peh + (size_t)l*SS*DHD, pel + (size_t)l*SS*DHD); // 6 (l=0)
        if (l == 0) {
            cvt_w<<<dim3(8, 4, NL),  256>>>(Wo,  oh,  ol,  DD, DD);
            cvt_w<<<dim3(8, 16, NL), 256>>>(fW1, f1h, f1l, DD, DI);
            cvt_w<<<dim3(32, 4, NL), 256>>>(fW2, f2h, f2l, DI, DD);
            cvt_w<<<dim3(8, 4, 1),   256>>>(fcW, fch, fcl, DD, VV);
        }
        mma_gemm<1><<<gP, 256, GEMM_SMEM>>>(ah, al, oh+wo, ol+wo, bo+l*DD, px, pres, nullptr, nullptr, DD, DD, nullptr, nullptr);
        k_ln<<<BS, 128>>>(pres, pout1, ln1g + l*DD, ln1b + l*DD, o1h, o1l);
        mma_gemm<2><<<gF1, 256, GEMM_SMEM>>>(o1h, o1l, f1h+w1, f1l+w1, fb1+l*DI, nullptr, nullptr, hh, hl, DD, DI, ttcW, ttcb);
        mma_gemm<1><<<gP, 256, GEMM_SMEM>>>(hh, hl, f2h+w1, f2l+w1, fb2+l*DD, pout1, pres, nullptr, nullptr, DI, DD, nullptr, nullptr);
        k_ln<<<BS, 128>>>(pres, px, ln2g + l*DD, ln2b + l*DD, xh, xl);
    }
    mma_gemm<3><<<dim3(VV/128, BS/128), 256, GEMM_SMEM>>>(xh, xl, fch, fcl, fcb, nullptr, out, nullptr, nullptr, DD, VV, nullptr, nullptr);
}

// round 10
// speedup vs baseline: 3.7895x; 1.1748x over previous
#include <cuda_runtime.h>
#include <cuda_bf16.h>
#include <math.h>
#include <stdint.h>

#define BB 2
#define SS 2048
#define NCOND 2
#define STOK 2046
#define DD 512
#define HH 8
#define DHD 64
#define DI 2048
#define NL 6
#define VV 512
#define BS (BB*SS)   // 4096
#define NBH (BB*HH)  // 16

// ---------------- scratch (device globals) -----------------------------------
__device__ float g_x[BS*DD];
__device__ float g_res[BS*DD];
__device__ float g_out1[BS*DD];
__device__ float g_chordf[BS];
__device__ int   g_keypad[BS];
__device__ int   g_wk[NL];     // persistent-attention work counters (self-reset)
__device__ int   g_done[NL];

__device__ __align__(256) __nv_bfloat16 g_xh[BS*DD],  g_xl[BS*DD];
__device__ __align__(256) __nv_bfloat16 g_o1h[BS*DD], g_o1l[BS*DD];
__device__ __align__(256) __nv_bfloat16 g_ah[BS*DD],  g_al[BS*DD];
__device__ __align__(256) __nv_bfloat16 g_hh[(size_t)BS*DI], g_hl[(size_t)BS*DI];

// attention operands: q,k head-major [bh][s][64]; v transposed [bh][64][s]
__device__ __align__(256) __nv_bfloat16 g_qbh[(size_t)NBH*SS*DHD], g_qbl[(size_t)NBH*SS*DHD];
__device__ __align__(256) __nv_bfloat16 g_kbh[(size_t)NBH*SS*DHD], g_kbl[(size_t)NBH*SS*DHD];
__device__ __align__(256) __nv_bfloat16 g_vbh[(size_t)NBH*SS*DHD], g_vbl[(size_t)NBH*SS*DHD];
__device__ __align__(256) __nv_bfloat16 g_eh[(size_t)NL*SS*DHD],   g_el[(size_t)NL*SS*DHD];

__device__ __align__(256) __nv_bfloat16 w_qh[(size_t)NL*DD*DD], w_ql[(size_t)NL*DD*DD];
__device__ __align__(256) __nv_bfloat16 w_kh[(size_t)NL*DD*DD], w_kl[(size_t)NL*DD*DD];
__device__ __align__(256) __nv_bfloat16 w_vh[(size_t)NL*DD*DD], w_vl[(size_t)NL*DD*DD];
__device__ __align__(256) __nv_bfloat16 w_oh[(size_t)NL*DD*DD], w_ol[(size_t)NL*DD*DD];
__device__ __align__(256) __nv_bfloat16 w_f1h[(size_t)NL*DD*DI], w_f1l[(size_t)NL*DD*DI];
__device__ __align__(256) __nv_bfloat16 w_f2h[(size_t)NL*DI*DD], w_f2l[(size_t)NL*DI*DD];
__device__ __align__(256) __nv_bfloat16 w_fch[(size_t)DD*VV],    w_fcl[(size_t)DD*VV];

// ---------------- helpers -----------------------------------------------------
__device__ __forceinline__ uint32_t smem_u32(const void* p){
    uint32_t a;
    asm("{ .reg .u64 t; cvta.to.shared.u64 t, %1; cvt.u32.u64 %0, t; }" : "=r"(a) : "l"(p));
    return a;
}
__device__ __forceinline__ void cp_async16(uint32_t s, const void* g){
    asm volatile("cp.async.cg.shared.global [%0], [%1], 16;\n"
        :: "r"(s), "l"(__cvta_generic_to_global(g)) : "memory");
}
#define CP_COMMIT() asm volatile("cp.async.commit_group;\n":::"memory")
#define CP_WAIT1()  asm volatile("cp.async.wait_group 1;\n":::"memory")
#define CP_WAIT0()  asm volatile("cp.async.wait_group 0;\n":::"memory")

__device__ __forceinline__ void mma16816(float* c, uint32_t a0, uint32_t a1, uint32_t a2, uint32_t a3,
                                         uint32_t b0, uint32_t b1){
    asm volatile(
        "mma.sync.aligned.m16n8k16.row.col.f32.bf16.bf16.f32 "
        "{%0,%1,%2,%3}, {%4,%5,%6,%7}, {%8,%9}, {%0,%1,%2,%3};"
        : "+f"(c[0]), "+f"(c[1]), "+f"(c[2]), "+f"(c[3])
        : "r"(a0), "r"(a1), "r"(a2), "r"(a3), "r"(b0), "r"(b1));
}
__device__ __forceinline__ unsigned pkb(__nv_bfloat16 a, __nv_bfloat16 b){
    __nv_bfloat162 t(a, b);
    return *reinterpret_cast<unsigned*>(&t);
}
__device__ __forceinline__ void split1(float v, __nv_bfloat16& h, __nv_bfloat16& l){
    h = __float2bfloat16(v);
    l = __float2bfloat16(v - __bfloat162float(h));
}
__device__ __forceinline__ void store_split4(char* ph, char* pl, size_t boff,
                                             float v0, float v1, float v2, float v3){
    __nv_bfloat16 h0,h1,h2,h3,l0,l1,l2,l3;
    split1(v0,h0,l0); split1(v1,h1,l1); split1(v2,h2,l2); split1(v3,h3,l3);
    uint2 uh; uh.x = pkb(h0,h1); uh.y = pkb(h2,h3);
    uint2 ul; ul.x = pkb(l0,l1); ul.y = pkb(l2,l3);
    *(uint2*)(ph + boff) = uh;
    *(uint2*)(pl + boff) = ul;
}
__device__ __forceinline__ void store_split2(char* ph, char* pl, size_t boff, float v0, float v1){
    __nv_bfloat16 h0,h1,l0,l1;
    split1(v0,h0,l0); split1(v1,h1,l1);
    *(unsigned*)(ph + boff) = pkb(h0,h1);
    *(unsigned*)(pl + boff) = pkb(l0,l1);
}

// ---------------- build x (+ fused keypad/chord) ------------------------------
__global__ void k_build_x(const int* __restrict__ toks, const float* __restrict__ cond,
                          const float* __restrict__ emb, const float* __restrict__ pos,
                          const float* __restrict__ W1, const float* __restrict__ b1,
                          const float* __restrict__ W2, const float* __restrict__ b2,
                          const float* __restrict__ nullc, const float* __restrict__ ttc) {
    int blk = blockIdx.x;
    int b = blk / SS, s = blk % SS;
    int t = threadIdx.x;
    if (t == 0) {
        g_keypad[blk] = (s >= NCOND && toks[b*STOK + s - NCOND] == 0) ? 1 : 0;
        float tt = (s < NCOND) ? ttc[b*STOK] : ttc[b*STOK + s - NCOND];
        g_chordf[blk] = 8.0f - tt;
    }
    int d0 = t*4;
    float v[4];
    if (s < NCOND) {
        __shared__ float h1[256];
        float c = cond[b*NCOND + s];
        bool isn = isnan(c);
        if (!isn) {
            for (int o = t; o < 256; o += 128)
                h1[o] = fmaxf(c * W1[s*256 + o] + b1[s*256 + o], 0.f);
        }
        __syncthreads();
        #pragma unroll
        for (int j = 0; j < 4; j++) {
            int d = d0 + j;
            float ce;
            if (isn) ce = nullc[s*DD + d];
            else {
                float acc = b2[s*DD + d];
                #pragma unroll 8
                for (int o = 0; o < 256; o++) acc += h1[o] * W2[(s*256 + o)*DD + d];
                ce = acc;
            }
            v[j] = ce + pos[s*DD + d];
        }
    } else {
        int tok = toks[b*STOK + s - NCOND];
        float4 e = *(const float4*)(emb + (size_t)tok*DD + d0);
        float4 p = *(const float4*)(pos + (size_t)s*DD + d0);
        const float SC = 22.62741699796952f;
        v[0] = e.x*SC + p.x; v[1] = e.y*SC + p.y; v[2] = e.z*SC + p.z; v[3] = e.w*SC + p.w;
    }
    *(float4*)(&g_x[(size_t)blk*DD + d0]) = make_float4(v[0], v[1], v[2], v[3]);
    store_split4((char*)g_xh, (char*)g_xl, ((size_t)blk*DD + d0)*2, v[0], v[1], v[2], v[3]);
}

// fp32 weight [K][N] -> row-major [N][K] hi/lo (generic, single weight)
__global__ void cvt_w(const float* __restrict__ W, __nv_bfloat16* __restrict__ Bh,
                      __nv_bfloat16* __restrict__ Bl, int K, int N) {
    int kt = blockIdx.x, nt = blockIdx.y, l = blockIdx.z;
    const float* Wl = W + (size_t)l*K*N;
    char* ph = (char*)Bh + (size_t)l*N*K*2;
    char* pl = (char*)Bl + (size_t)l*N*K*2;
    __shared__ float ts[64][129];
    int tid = threadIdx.x;
    int k0 = kt*64, n0 = nt*128;
    #pragma unroll
    for (int r = 0; r < 8; r++) {
        int i = tid + r*256;
        int kl = i >> 5, n4 = (i & 31) * 4;
        float4 x = *(const float4*)(Wl + (size_t)(k0 + kl)*N + n0 + n4);
        ts[kl][n4] = x.x; ts[kl][n4+1] = x.y; ts[kl][n4+2] = x.z; ts[kl][n4+3] = x.w;
    }
    __syncthreads();
    #pragma unroll
    for (int r = 0; r < 8; r++) {
        int i = tid + r*256;
        int nl = i >> 4, kc = (i & 15) * 4;
        size_t boff = ((size_t)(n0 + nl)*K + k0 + kc)*2;
        store_split4(ph, pl, boff, ts[kc][nl], ts[kc+1][nl], ts[kc+2][nl], ts[kc+3][nl]);
    }
}

// merged q/k/v weight convert + E convert. z < NL*3: weights; z >= NL*3: E elementwise.
__global__ void cvt_all(const float* __restrict__ Wq, const float* __restrict__ Wk,
                        const float* __restrict__ Wv, const float* __restrict__ E) {
    int zz = blockIdx.z;
    int tid = threadIdx.x;
    if (zz >= NL*3) {
        int eb = (zz - NL*3)*32 + blockIdx.y*8 + blockIdx.x;  // 0..767
        size_t i = ((size_t)eb*256 + tid)*4;
        float4 v = *(const float4*)(E + i);
        store_split4((char*)g_eh, (char*)g_el, i*2, v.x, v.y, v.z, v.w);
        return;
    }
    int kt = blockIdx.x, nt = blockIdx.y;
    int which = zz % 3, l = zz / 3;
    const float* W = (which == 0) ? Wq : (which == 1) ? Wk : Wv;
    __nv_bfloat16* Bh = (which == 0) ? w_qh : (which == 1) ? w_kh : w_vh;
    __nv_bfloat16* Bl = (which == 0) ? w_ql : (which == 1) ? w_kl : w_vl;
    const float* Wl = W + (size_t)l*DD*DD;
    char* ph = (char*)Bh + (size_t)l*DD*DD*2;
    char* pl = (char*)Bl + (size_t)l*DD*DD*2;
    __shared__ float ts[64][129];
    int k0 = kt*64, n0 = nt*128;
    #pragma unroll
    for (int r = 0; r < 8; r++) {
        int i = tid + r*256;
        int kl = i >> 5, n4 = (i & 31) * 4;
        float4 x = *(const float4*)(Wl + (size_t)(k0 + kl)*DD + n0 + n4);
        ts[kl][n4] = x.x; ts[kl][n4+1] = x.y; ts[kl][n4+2] = x.z; ts[kl][n4+3] = x.w;
    }
    __syncthreads();
    #pragma unroll
    for (int r = 0; r < 8; r++) {
        int i = tid + r*256;
        int nl = i >> 4, kc = (i & 15) * 4;
        size_t boff = ((size_t)(n0 + nl)*DD + k0 + kc)*2;
        store_split4(ph, pl, boff, ts[kc][nl], ts[kc+1][nl], ts[kc+2][nl], ts[kc+3][nl]);
    }
}

// ---------------- mma.sync GEMM (3-term bf16 split) ---------------------------
#define GPITCH 144
#define GMAT   18432
#define GSTAGE 73728
#define GEMM_SMEM (2*GSTAGE)

// merged QKV projection: z=0 q (head-major), z=1 k (head-major), z=2 v (transposed)
__global__ __launch_bounds__(256, 1)
void gemm_qkv(const float* __restrict__ bq, const float* __restrict__ bk,
              const float* __restrict__ bv, int l)
{
    extern __shared__ char smem[];
    const int K = DD, KT = 8;
    uint32_t sbase = smem_u32(smem);
    int tid = threadIdx.x, wid = tid >> 5, lane = tid & 31;
    int g = lane >> 2, t4 = lane & 3;
    int wm = wid & 3, wn = wid >> 2;
    int mt = blockIdx.y, nt = blockIdx.x, z = blockIdx.z;
    int mG = mt*128, nG = nt*128;
    size_t wo = (size_t)l*DD*DD;
    const __nv_bfloat16* Bh = ((z == 0) ? w_qh : (z == 1) ? w_kh : w_vh) + wo;
    const __nv_bfloat16* Bl = ((z == 0) ? w_ql : (z == 1) ? w_kl : w_vl) + wo;
    const float* bias = ((z == 0) ? bq : (z == 1) ? bk : bv) + l*DD;

    int mymat = tid >> 6, sub = tid & 63;
    int lr0 = sub >> 3, lch = sub & 7;
    const char* matp = (mymat == 0) ? (const char*)g_xh : (mymat == 1) ? (const char*)g_xl
                     : (mymat == 2) ? (const char*)Bh : (const char*)Bl;
    int rowG = (mymat < 2) ? mG : nG;
    const char* srcbase = matp + ((size_t)(rowG + lr0) * K + lch*8) * 2;
    uint32_t dstbase = sbase + mymat*GMAT + lr0*GPITCH + lch*16;
    size_t srcstep = (size_t)8*K*2;

    auto load_stage = [&](int kb){
        uint32_t d = dstbase + (kb&1)*GSTAGE;
        const char* s = srcbase + (size_t)kb*128;
        #pragma unroll
        for (int i = 0; i < 16; i++){
            cp_async16(d, s);
            d += 8*GPITCH; s += srcstep;
        }
        CP_COMMIT();
    };
    load_stage(0);
    load_stage(1);

    float acc[2][8][4] = {};
    int ar0 = wm*32, bn0 = wn*64;

    for (int kb = 0; kb < KT; kb++){
        if (kb + 1 < KT) CP_WAIT1(); else CP_WAIT0();
        __syncthreads();
        const char* st = smem + (size_t)(kb&1)*GSTAGE;
        const char* sAh = st;
        const char* sAl = st + GMAT;
        const char* sBh = st + 2*GMAT;
        const char* sBl = st + 3*GMAT;
        #pragma unroll
        for (int ks = 0; ks < 4; ks++){
            int cw  = (ks*8 + t4)*4;
            int cw4 = cw + 16;
            uint32_t bh0[8], bh1[8], bl0[8], bl1[8];
            #pragma unroll
            for (int j = 0; j < 8; j++){
                int nr = (bn0 + j*8 + g)*GPITCH;
                bh0[j] = *(const uint32_t*)(sBh + nr + cw);
                bh1[j] = *(const uint32_t*)(sBh + nr + cw4);
                bl0[j] = *(const uint32_t*)(sBl + nr + cw);
                bl1[j] = *(const uint32_t*)(sBl + nr + cw4);
            }
            #pragma unroll
            for (int mi = 0; mi < 2; mi++){
                int r0 = (ar0 + mi*16 + g)*GPITCH;
                int r8 = r0 + 8*GPITCH;
                uint32_t ah0 = *(const uint32_t*)(sAh + r0 + cw);
                uint32_t ah1 = *(const uint32_t*)(sAh + r8 + cw);
                uint32_t ah2 = *(const uint32_t*)(sAh + r0 + cw4);
                uint32_t ah3 = *(const uint32_t*)(sAh + r8 + cw4);
                uint32_t al0 = *(const uint32_t*)(sAl + r0 + cw);
                uint32_t al1 = *(const uint32_t*)(sAl + r8 + cw);
                uint32_t al2 = *(const uint32_t*)(sAl + r0 + cw4);
                uint32_t al3 = *(const uint32_t*)(sAl + r8 + cw4);
                #pragma unroll
                for (int j = 0; j < 8; j++){
                    mma16816(acc[mi][j], ah0, ah1, ah2, ah3, bh0[j], bh1[j]);
                    mma16816(acc[mi][j], ah0, ah1, ah2, ah3, bl0[j], bl1[j]);
                    mma16816(acc[mi][j], al0, al1, al2, al3, bh0[j], bh1[j]);
                }
            }
        }
        __syncthreads();
        if (kb + 2 < KT) load_stage(kb + 2);
    }

    if (z < 2) {
        __nv_bfloat16* outH = (z == 0) ? g_qbh : g_kbh;
        __nv_bfloat16* outL = (z == 0) ? g_qbl : g_kbl;
        #pragma unroll
        for (int mi = 0; mi < 2; mi++){
            #pragma unroll
            for (int j = 0; j < 8; j++){
                int n = nG + bn0 + j*8 + 2*t4;
                int mA = mG + ar0 + mi*16 + g;
                int mB = mA + 8;
                float bx = bias[n], by = bias[n+1];
                int hh_ = n >> 6, dd_ = n & 63;
                int bA = mA >> 11, sA = mA & 2047;
                int bB = mB >> 11, sB = mB & 2047;
                store_split2((char*)outH, (char*)outL,
                    ((size_t)((bA*HH + hh_)*SS + sA)*DHD + dd_)*2,
                    acc[mi][j][0]+bx, acc[mi][j][1]+by);
                store_split2((char*)outH, (char*)outL,
                    ((size_t)((bB*HH + hh_)*SS + sB)*DHD + dd_)*2,
                    acc[mi][j][2]+bx, acc[mi][j][3]+by);
            }
        }
    } else {
        // smem-staged transpose -> g_vbh/g_vbl [bh][d][s]
        char* T = smem;
        int bA = mG >> 11;
        int sBase = mG & 2047;
        #pragma unroll 1
        for (int part = 0; part < 2; part++){
            __syncthreads();
            #pragma unroll
            for (int mi = 0; mi < 2; mi++){
                #pragma unroll
                for (int j = 0; j < 8; j++){
                    int n = bn0 + j*8 + 2*t4;
                    int mAl = ar0 + mi*16 + g, mBl = mAl + 8;
                    float bx = bias[nG + n], by = bias[nG + n + 1];
                    float v0 = acc[mi][j][0] + bx, v1 = acc[mi][j][1] + by;
                    float v2 = acc[mi][j][2] + bx, v3 = acc[mi][j][3] + by;
                    __nv_bfloat16 h, l;
                    split1(v0,h,l); *(__nv_bfloat16*)(T + n*272 + mAl*2)     = part ? l : h;
                    split1(v1,h,l); *(__nv_bfloat16*)(T + (n+1)*272 + mAl*2) = part ? l : h;
                    split1(v2,h,l); *(__nv_bfloat16*)(T + n*272 + mBl*2)     = part ? l : h;
                    split1(v3,h,l); *(__nv_bfloat16*)(T + (n+1)*272 + mBl*2) = part ? l : h;
                }
            }
            __syncthreads();
            __nv_bfloat16* dst = part ? g_vbl : g_vbh;
            #pragma unroll
            for (int i = 0; i < 8; i++){
                int idx = tid + 256*i;
                int row = idx >> 4, ch = idx & 15;
                int ng = nG + row;
                int head = ng >> 6, dd = ng & 63;
                uint4 val = *(const uint4*)(T + row*272 + ch*16);
                *(uint4*)((char*)dst + (((size_t)(bA*HH + head)*DHD + dd)*SS + sBase + ch*8)*2) = val;
            }
        }
    }
}

// generic GEMM. MODE 1: acc+bias+res fp32. 2: relu+chord split. 3: acc+bias fp32.
template<int MODE>
__global__ __launch_bounds__(256, 1)
void mma_gemm(const __nv_bfloat16* __restrict__ Ah, const __nv_bfloat16* __restrict__ Al,
              const __nv_bfloat16* __restrict__ Bh, const __nv_bfloat16* __restrict__ Bl,
              const float* __restrict__ bias, const float* __restrict__ res,
              float* __restrict__ out, __nv_bfloat16* __restrict__ outH,
              __nv_bfloat16* __restrict__ outL,
              int K, int Ntot, const float* __restrict__ ttcW, const float* __restrict__ ttcb)
{
    extern __shared__ char smem[];
    uint32_t sbase = smem_u32(smem);
    int tid = threadIdx.x, wid = tid >> 5, lane = tid & 31;
    int g = lane >> 2, t4 = lane & 3;
    int wm = wid & 3, wn = wid >> 2;
    int mt = blockIdx.y, nt = blockIdx.x;
    int mG = mt*128, nG = nt*128;
    int KT = K >> 6;

    int mymat = tid >> 6, sub = tid & 63;
    int lr0 = sub >> 3, lch = sub & 7;
    const char* matp = (mymat == 0) ? (const char*)Ah : (mymat == 1) ? (const char*)Al
                     : (mymat == 2) ? (const char*)Bh : (const char*)Bl;
    int rowG = (mymat < 2) ? mG : nG;
    const char* srcbase = matp + ((size_t)(rowG + lr0) * K + lch*8) * 2;
    uint32_t dstbase = sbase + mymat*GMAT + lr0*GPITCH + lch*16;
    size_t srcstep = (size_t)8*K*2;

    auto load_stage = [&](int kb){
        uint32_t d = dstbase + (kb&1)*GSTAGE;
        const char* s = srcbase + (size_t)kb*128;
        #pragma unroll
        for (int i = 0; i < 16; i++){
            cp_async16(d, s);
            d += 8*GPITCH; s += srcstep;
        }
        CP_COMMIT();
    };
    load_stage(0);
    if (KT > 1) load_stage(1);

    float acc[2][8][4] = {};
    int ar0 = wm*32, bn0 = wn*64;

    for (int kb = 0; kb < KT; kb++){
        if (kb + 1 < KT) CP_WAIT1(); else CP_WAIT0();
        __syncthreads();
        const char* st = smem + (size_t)(kb&1)*GSTAGE;
        const char* sAh = st;
        const char* sAl = st + GMAT;
        const char* sBh = st + 2*GMAT;
        const char* sBl = st + 3*GMAT;
        #pragma unroll
        for (int ks = 0; ks < 4; ks++){
            int cw  = (ks*8 + t4)*4;
            int cw4 = cw + 16;
            uint32_t bh0[8], bh1[8], bl0[8], bl1[8];
            #pragma unroll
            for (int j = 0; j < 8; j++){
                int nr = (bn0 + j*8 + g)*GPITCH;
                bh0[j] = *(const uint32_t*)(sBh + nr + cw);
                bh1[j] = *(const uint32_t*)(sBh + nr + cw4);
                bl0[j] = *(const uint32_t*)(sBl + nr + cw);
                bl1[j] = *(const uint32_t*)(sBl + nr + cw4);
            }
            #pragma unroll
            for (int mi = 0; mi < 2; mi++){
                int r0 = (ar0 + mi*16 + g)*GPITCH;
                int r8 = r0 + 8*GPITCH;
                uint32_t ah0 = *(const uint32_t*)(sAh + r0 + cw);
                uint32_t ah1 = *(const uint32_t*)(sAh + r8 + cw);
                uint32_t ah2 = *(const uint32_t*)(sAh + r0 + cw4);
                uint32_t ah3 = *(const uint32_t*)(sAh + r8 + cw4);
                uint32_t al0 = *(const uint32_t*)(sAl + r0 + cw);
                uint32_t al1 = *(const uint32_t*)(sAl + r8 + cw);
                uint32_t al2 = *(const uint32_t*)(sAl + r0 + cw4);
                uint32_t al3 = *(const uint32_t*)(sAl + r8 + cw4);
                #pragma unroll
                for (int j = 0; j < 8; j++){
                    mma16816(acc[mi][j], ah0, ah1, ah2, ah3, bh0[j], bh1[j]);
                    mma16816(acc[mi][j], ah0, ah1, ah2, ah3, bl0[j], bl1[j]);
                    mma16816(acc[mi][j], al0, al1, al2, al3, bh0[j], bh1[j]);
                }
            }
        }
        __syncthreads();
        if (kb + 2 < KT) load_stage(kb + 2);
    }

    #pragma unroll
    for (int mi = 0; mi < 2; mi++){
        #pragma unroll
        for (int j = 0; j < 8; j++){
            int n = nG + bn0 + j*8 + 2*t4;
            int mA = mG + ar0 + mi*16 + g;
            int mB = mA + 8;
            float c0 = acc[mi][j][0], c1 = acc[mi][j][1];
            float c2 = acc[mi][j][2], c3 = acc[mi][j][3];
            float bx = bias[n], by = bias[n+1];
            if (MODE == 1) {
                float2 rA = *(const float2*)(res + (size_t)mA*Ntot + n);
                float2 rB = *(const float2*)(res + (size_t)mB*Ntot + n);
                *(float2*)(out + (size_t)mA*Ntot + n) = make_float2(c0+bx+rA.x, c1+by+rA.y);
                *(float2*)(out + (size_t)mB*Ntot + n) = make_float2(c2+bx+rB.x, c3+by+rB.y);
            } else if (MODE == 3) {
                *(float2*)(out + (size_t)mA*Ntot + n) = make_float2(c0+bx, c1+by);
                *(float2*)(out + (size_t)mB*Ntot + n) = make_float2(c2+bx, c3+by);
            } else {
                float twx = ttcW[n], twy = ttcW[n+1];
                float tbx = ttcb[n], tby = ttcb[n+1];
                float cfA = g_chordf[mA], cfB = g_chordf[mB];
                float v0 = fmaxf(c0+bx, 0.f) + cfA*twx + tbx;
                float v1 = fmaxf(c1+by, 0.f) + cfA*twy + tby;
                float v2 = fmaxf(c2+bx, 0.f) + cfB*twx + tbx;
                float v3 = fmaxf(c3+by, 0.f) + cfB*twy + tby;
                store_split2((char*)outH, (char*)outL, ((size_t)mA*Ntot + n)*2, v0, v1);
                store_split2((char*)outH, (char*)outL, ((size_t)mB*Ntot + n)*2, v2, v3);
            }
        }
    }
}

// ---------------- layernorm ---------------------------------------------------
__global__ void k_ln(const float* __restrict__ in, float* __restrict__ out,
                     const float* __restrict__ g, const float* __restrict__ bb,
                     __nv_bfloat16* __restrict__ oh, __nv_bfloat16* __restrict__ ol) {
    int r = blockIdx.x, t = threadIdx.x;
    float4 v = *(const float4*)(in + (size_t)r*DD + t*4);
    float s  = v.x + v.y + v.z + v.w;
    float ss = v.x*v.x + v.y*v.y + v.z*v.z + v.w*v.w;
    for (int m = 16; m; m >>= 1) {
        s  += __shfl_xor_sync(0xffffffffu, s,  m);
        ss += __shfl_xor_sync(0xffffffffu, ss, m);
    }
    __shared__ float sm[4], sm2[4];
    if ((t & 31) == 0) { sm[t>>5] = s; sm2[t>>5] = ss; }
    __syncthreads();
    s  = sm[0]  + sm[1]  + sm[2]  + sm[3];
    ss = sm2[0] + sm2[1] + sm2[2] + sm2[3];
    float mu  = s * (1.0f/DD);
    float var = ss * (1.0f/DD) - mu*mu;
    float inv = rsqrtf(var + 1e-6f);
    float4 gg = *(const float4*)(g  + t*4);
    float4 bv = *(const float4*)(bb + t*4);
    float4 o;
    o.x = (v.x - mu)*inv*gg.x + bv.x;
    o.y = (v.y - mu)*inv*gg.y + bv.y;
    o.z = (v.z - mu)*inv*gg.z + bv.z;
    o.w = (v.w - mu)*inv*gg.w + bv.w;
    *(float4*)(out + (size_t)r*DD + t*4) = o;
    store_split4((char*)oh, (char*)ol, ((size_t)r*DD + t*4)*2, o.x, o.y, o.z, o.w);
}

// ---------------- persistent tensor-core rel-pos flash attention --------------
// smem: K double-buf (2x36864) | E ring 256 rows hi/lo (73728) | S fp32 (67584) | kp (512)
#define AOFF_K  0
#define AOFF_E  73728
#define AOFF_S  147456
#define AOFF_KP 215040
#define ATT_SMEM 215552
#define ATT_CTAS 148
#define ATT_ITEMS 256

__global__ __launch_bounds__(256, 1)
void k_attn_tc(const __nv_bfloat16* __restrict__ eh, const __nv_bfloat16* __restrict__ el, int l) {
    extern __shared__ char sm[];
    int tid = threadIdx.x, w = tid >> 5, lane = tid & 31;
    int g = lane >> 2, t4 = lane & 3;
    uint32_t sA = smem_u32(sm);
    int* kps = (int*)(sm + AOFF_KP);
    int r_ = 16*w + g;
    __shared__ int s_item;

    for (;;) {
        if (tid == 0) s_item = atomicAdd(&g_wk[l], 1);
        __syncthreads();
        int item = s_item;
        if (item >= ATT_ITEMS) break;
        int itile = 15 - (item >> 4);       // heavy first
        int bh = item & 15;
        int b = bh >> 3, h = bh & 7;
        int i0 = itile * 128;

        // Q fragments in registers
        uint32_t qfh[4][4], qfl[4][4];
        {
            const char* qh_ = (const char*)g_qbh + ((size_t)bh*SS*DHD)*2;
            const char* ql_ = (const char*)g_qbl + ((size_t)bh*SS*DHD)*2;
            #pragma unroll
            for (int ks = 0; ks < 4; ks++){
                size_t o0 = ((size_t)(i0 + r_)*DHD + ks*16 + 2*t4)*2;
                qfh[ks][0] = *(const uint32_t*)(qh_ + o0);
                qfh[ks][1] = *(const uint32_t*)(qh_ + o0 + 8*DHD*2);
                qfh[ks][2] = *(const uint32_t*)(qh_ + o0 + 16);
                qfh[ks][3] = *(const uint32_t*)(qh_ + o0 + 8*DHD*2 + 16);
                qfl[ks][0] = *(const uint32_t*)(ql_ + o0);
                qfl[ks][1] = *(const uint32_t*)(ql_ + o0 + 8*DHD*2);
                qfl[ks][2] = *(const uint32_t*)(ql_ + o0 + 16);
                qfl[ks][3] = *(const uint32_t*)(ql_ + o0 + 8*DHD*2 + 16);
            }
        }

        // pre-load: K(0) + full E band
        {
            #pragma unroll
            for (int i = 0; i < 8; i++){
                int idx = tid + 256*i;
                int mat = idx >> 10, r = (idx & 1023) >> 3, ch = idx & 7;
                const char* src = (const char*)(mat ? g_kbl : g_kbh)
                    + ((size_t)(bh*SS + r)*DHD + ch*8)*2;
                cp_async16(sA + AOFF_K + mat*18432 + r*144 + ch*16, src);
            }
            int e00 = (itile & 1) ? 0 : 128;
            int ebase0 = 1920 - 128*itile;
            #pragma unroll
            for (int i = 0; i < 16; i++){
                int idx = tid + 256*i;
                int mat = idx >> 11, r = (idx & 2047) >> 3, ch = idx & 7;
                int m = ebase0 + r; if (m > SS-1) m = SS-1;
                int slot = r ^ e00;
                const char* src = (const char*)(mat ? el : eh) + ((size_t)m*DHD + ch*8)*2;
                cp_async16(sA + AOFF_E + mat*36864 + slot*144 + ch*16, src);
            }
            CP_COMMIT();
        }

        float oac[8][4] = {};
        float mrow[2] = {-1e30f, -1e30f};
        float lrow[2] = {0.f, 0.f};

        for (int kt = 0; kt <= itile; kt++){
            int j0 = kt*128;
            int e0 = ((kt - itile) & 1) ? 0 : 128;
            __syncthreads();
            if (tid < 128) kps[tid] = g_keypad[b*SS + j0 + tid];
            if (kt < itile){
                uint32_t kb = sA + AOFF_K + ((kt+1)&1)*36864;
                #pragma unroll
                for (int i = 0; i < 8; i++){
                    int idx = tid + 256*i;
                    int mat = idx >> 10, r = (idx & 1023) >> 3, ch = idx & 7;
                    const char* src = (const char*)(mat ? g_kbl : g_kbh)
                        + ((size_t)(bh*SS + j0 + 128 + r)*DHD + ch*8)*2;
                    cp_async16(kb + mat*18432 + r*144 + ch*16, src);
                }
                CP_COMMIT();
                CP_WAIT1();
            } else {
                CP_WAIT0();
            }
            __syncthreads();

            // ---- S = Q K^T (3-term)
            const char* kbase = sm + AOFF_K + (kt&1)*36864;
            float sacc[16][4] = {};
            #pragma unroll
            for (int ks = 0; ks < 4; ks++){
                int cb = (ks*16 + 2*t4)*2;
                #pragma unroll
                for (int nf = 0; nf < 16; nf++){
                    const char* kb = kbase + (nf*8+g)*144 + cb;
                    uint32_t b0 = *(const uint32_t*)kb, b1 = *(const uint32_t*)(kb+16);
                    uint32_t c0 = *(const uint32_t*)(kb+18432), c1 = *(const uint32_t*)(kb+18432+16);
                    mma16816(sacc[nf], qfh[ks][0], qfh[ks][1], qfh[ks][2], qfh[ks][3], b0, b1);
                    mma16816(sacc[nf], qfh[ks][0], qfh[ks][1], qfh[ks][2], qfh[ks][3], c0, c1);
                    mma16816(sacc[nf], qfl[ks][0], qfl[ks][1], qfl[ks][2], qfl[ks][3], b0, b1);
                }
            }
            #pragma unroll
            for (int nf = 0; nf < 16; nf++){
                *(float2*)(sm + AOFF_S + r_*528 + (nf*8 + 2*t4)*4)     = make_float2(sacc[nf][0], sacc[nf][1]);
                *(float2*)(sm + AOFF_S + (r_+8)*528 + (nf*8 + 2*t4)*4) = make_float2(sacc[nf][2], sacc[nf][3]);
            }
            __syncthreads();

            // V(kt) into same buffer (K consumed)
            {
                uint32_t vb = sA + AOFF_K + (kt&1)*36864;
                #pragma unroll
                for (int i = 0; i < 8; i++){
                    int idx = tid + 256*i;
                    int mat = idx >> 10, r = (idx & 1023) >> 4, ch = idx & 15;
                    const char* src = (const char*)(mat ? g_vbl : g_vbh)
                        + ((size_t)(bh*DHD + r)*SS + j0 + ch*8)*2;
                    cp_async16(vb + mat*18432 + r*272 + ch*16, src);
                }
                CP_COMMIT();
            }

            // ---- Z = Q E^T (3-term), exact 18-fragment band per warp
            {
                int f0 = 14 - 2*w;
                #pragma unroll 1
                for (int ci = 0; ci < 3; ci++){
                    float zac[6][4] = {};
                    #pragma unroll
                    for (int ks = 0; ks < 4; ks++){
                        int cb = (ks*16 + 2*t4)*2;
                        #pragma unroll
                        for (int jf = 0; jf < 6; jf++){
                            int frag = f0 + ci*6 + jf;
                            int slot = (frag*8 + g) ^ e0;
                            const char* eb = sm + AOFF_E + slot*144 + cb;
                            uint32_t b0 = *(const uint32_t*)eb, b1 = *(const uint32_t*)(eb+16);
                            uint32_t c0 = *(const uint32_t*)(eb+36864), c1 = *(const uint32_t*)(eb+36864+16);
                            mma16816(zac[jf], qfh[ks][0], qfh[ks][1], qfh[ks][2], qfh[ks][3], b0, b1);
                            mma16816(zac[jf], qfh[ks][0], qfh[ks][1], qfh[ks][2], qfh[ks][3], c0, c1);
                            mma16816(zac[jf], qfl[ks][0], qfl[ks][1], qfl[ks][2], qfl[ks][3], b0, b1);
                        }
                    }
                    float* S0 = (float*)(sm + AOFF_S + r_*528);
                    float* S1 = (float*)(sm + AOFF_S + (r_+8)*528);
                    #pragma unroll
                    for (int jf = 0; jf < 6; jf++){
                        int u = (f0 + ci*6 + jf)*8 + 2*t4;
                        int c0 = r_ + u - 127;
                        if (c0 >= 0   && c0   < 128) S0[c0]   += zac[jf][0];
                        if (c0+1 >= 0 && c0+1 < 128) S0[c0+1] += zac[jf][1];
                        int c2 = r_ + 8 + u - 127;
                        if (c2 >= 0   && c2   < 128) S1[c2]   += zac[jf][2];
                        if (c2+1 >= 0 && c2+1 < 128) S1[c2+1] += zac[jf][3];
                    }
                }
            }
            __syncthreads();

            // prefetch E half for tile kt+1
            if (kt < itile){
                int ebn = 1920 + 128*(kt - itile) + 256;
                #pragma unroll
                for (int i = 0; i < 8; i++){
                    int idx = tid + 256*i;
                    int mat = idx >> 10, rj = (idx & 1023) >> 3, ch = idx & 7;
                    int m = ebn + rj; if (m > SS-1) m = SS-1;
                    int slot = rj ^ e0;
                    const char* src = (const char*)(mat ? el : eh) + ((size_t)m*DHD + ch*8)*2;
                    cp_async16(sA + AOFF_E + mat*36864 + slot*144 + ch*16, src);
                }
                CP_COMMIT();
            }

            // ---- online softmax; P in registers
            uint32_t pA[16], pAl[16], pB[16], pBl[16];
            #pragma unroll
            for (int mi = 0; mi < 2; mi++){
                int rr = r_ + 8*mi;
                int i = i0 + rr;
                float lv[32];
                float tm = -1e30f;
                #pragma unroll
                for (int k16 = 0; k16 < 16; k16++){
                    int c = k16*8 + 2*t4;
                    float2 sv = *(const float2*)(sm + AOFF_S + rr*528 + c*4);
                    int j = j0 + c;
                    float a = (j   <= i && kps[c]   == 0) ? sv.x*0.125f : -1e30f;
                    float d = (j+1 <= i && kps[c+1] == 0) ? sv.y*0.125f : -1e30f;
                    lv[2*k16] = a; lv[2*k16+1] = d;
                    tm = fmaxf(tm, fmaxf(a, d));
                }
                tm = fmaxf(tm, __shfl_xor_sync(0xffffffffu, tm, 1));
                tm = fmaxf(tm, __shfl_xor_sync(0xffffffffu, tm, 2));
                float mn = fmaxf(mrow[mi], tm);
                float corr = __expf(mrow[mi] - mn);
                float rs = 0.f;
                #pragma unroll
                for (int k16 = 0; k16 < 16; k16++){
                    float p0 = __expf(lv[2*k16]   - mn);
                    float p1 = __expf(lv[2*k16+1] - mn);
                    rs += p0 + p1;
                    __nv_bfloat16 h0,l0,h1,l1;
                    split1(p0,h0,l0); split1(p1,h1,l1);
                    if (mi == 0){ pA[k16] = pkb(h0,h1); pAl[k16] = pkb(l0,l1); }
                    else        { pB[k16] = pkb(h0,h1); pBl[k16] = pkb(l0,l1); }
                }
                rs += __shfl_xor_sync(0xffffffffu, rs, 1);
                rs += __shfl_xor_sync(0xffffffffu, rs, 2);
                lrow[mi] = lrow[mi]*corr + rs;
                mrow[mi] = mn;
                #pragma unroll
                for (int nf = 0; nf < 8; nf++){
                    oac[nf][2*mi]   *= corr;
                    oac[nf][2*mi+1] *= corr;
                }
            }
            if (kt < itile) CP_WAIT1(); else CP_WAIT0();
            __syncthreads();

            // ---- O += P V (3-term), P from registers
            const char* vbase = sm + AOFF_K + (kt&1)*36864;
            #pragma unroll
            for (int ks = 0; ks < 8; ks++){
                int cb = (ks*16 + 2*t4)*2;
                uint32_t a0h = pA[2*ks],  a1h = pB[2*ks],  a2h = pA[2*ks+1],  a3h = pB[2*ks+1];
                uint32_t a0l = pAl[2*ks], a1l = pBl[2*ks], a2l = pAl[2*ks+1], a3l = pBl[2*ks+1];
                #pragma unroll
                for (int nf = 0; nf < 8; nf++){
                    const char* vb = vbase + (nf*8+g)*272 + cb;
                    uint32_t b0 = *(const uint32_t*)vb, b1 = *(const uint32_t*)(vb+16);
                    uint32_t c0 = *(const uint32_t*)(vb+18432), c1 = *(const uint32_t*)(vb+18432+16);
                    mma16816(oac[nf], a0h, a1h, a2h, a3h, b0, b1);
                    mma16816(oac[nf], a0l, a1l, a2l, a3l, b0, b1);
                    mma16816(oac[nf], a0h, a1h, a2h, a3h, c0, c1);
                }
            }
        }

        float inv0 = 1.0f / lrow[0], inv1 = 1.0f / lrow[1];
        #pragma unroll
        for (int nf = 0; nf < 8; nf++){
            int col = h*DHD + nf*8 + 2*t4;
            size_t row0 = (size_t)(b*SS + i0 + r_);
            store_split2((char*)g_ah, (char*)g_al, (row0*DD + col)*2,
                         oac[nf][0]*inv0, oac[nf][1]*inv0);
            store_split2((char*)g_ah, (char*)g_al, ((row0+8)*DD + col)*2,
                         oac[nf][2]*inv1, oac[nf][3]*inv1);
        }
    }

    // self-reset counters for next launch / graph replay
    if (tid == 0) {
        int d = atomicAdd(&g_done[l], 1);
        if (d == (int)gridDim.x - 1) { g_wk[l] = 0; g_done[l] = 0; }
    }
}

// ---------------- host orchestration ------------------------------------------
extern "C" void kernel_launch(void* const* d_in, const int* in_sizes, int n_in,
                              void* d_out, int out_size) {
    const int*   toks   = (const int*)  d_in[0];
    const float* cond   = (const float*)d_in[1];
    const float* ttc    = (const float*)d_in[2];
    const float* emb    = (const float*)d_in[3];
    const float* pos    = (const float*)d_in[4];
    const float* cW1    = (const float*)d_in[5];
    const float* cb1    = (const float*)d_in[6];
    const float* cW2    = (const float*)d_in[7];
    const float* cb2    = (const float*)d_in[8];
    const float* nullc  = (const float*)d_in[9];
    const float* ttcW   = (const float*)d_in[10];
    const float* ttcb   = (const float*)d_in[11];
    const float* Wq     = (const float*)d_in[12];
    const float* Wk     = (const float*)d_in[13];
    const float* Wv     = (const float*)d_in[14];
    const float* Wo     = (const float*)d_in[15];
    const float* bq     = (const float*)d_in[16];
    const float* bk     = (const float*)d_in[17];
    const float* bv     = (const float*)d_in[18];
    const float* bo     = (const float*)d_in[19];
    const float* E      = (const float*)d_in[20];
    const float* fW1    = (const float*)d_in[21];
    const float* fb1    = (const float*)d_in[22];
    const float* fW2    = (const float*)d_in[23];
    const float* fb2    = (const float*)d_in[24];
    const float* ln1g   = (const float*)d_in[25];
    const float* ln1b   = (const float*)d_in[26];
    const float* ln2g   = (const float*)d_in[27];
    const float* ln2b   = (const float*)d_in[28];
    const float* fcW    = (const float*)d_in[29];
    const float* fcb    = (const float*)d_in[30];
    float* out = (float*)d_out;

    float *px, *pres, *pout1;
    cudaGetSymbolAddress((void**)&px,    g_x);
    cudaGetSymbolAddress((void**)&pres,  g_res);
    cudaGetSymbolAddress((void**)&pout1, g_out1);
    __nv_bfloat16 *xh,*xl,*o1h,*o1l,*ah,*al,*hh,*hl,*peh,*pel;
    __nv_bfloat16 *oh,*ol,*f1h,*f1l,*f2h,*f2l,*fch,*fcl;
    cudaGetSymbolAddress((void**)&xh,  g_xh);  cudaGetSymbolAddress((void**)&xl,  g_xl);
    cudaGetSymbolAddress((void**)&o1h, g_o1h); cudaGetSymbolAddress((void**)&o1l, g_o1l);
    cudaGetSymbolAddress((void**)&ah,  g_ah);  cudaGetSymbolAddress((void**)&al,  g_al);
    cudaGetSymbolAddress((void**)&hh,  g_hh);  cudaGetSymbolAddress((void**)&hl,  g_hl);
    cudaGetSymbolAddress((void**)&peh, g_eh);  cudaGetSymbolAddress((void**)&pel, g_el);
    cudaGetSymbolAddress((void**)&oh,  w_oh);  cudaGetSymbolAddress((void**)&ol,  w_ol);
    cudaGetSymbolAddress((void**)&f1h, w_f1h); cudaGetSymbolAddress((void**)&f1l, w_f1l);
    cudaGetSymbolAddress((void**)&f2h, w_f2h); cudaGetSymbolAddress((void**)&f2l, w_f2l);
    cudaGetSymbolAddress((void**)&fch, w_fch); cudaGetSymbolAddress((void**)&fcl, w_fcl);

    cudaFuncSetAttribute(k_attn_tc,   cudaFuncAttributeMaxDynamicSharedMemorySize, ATT_SMEM);
    cudaFuncSetAttribute(gemm_qkv,    cudaFuncAttributeMaxDynamicSharedMemorySize, GEMM_SMEM);
    cudaFuncSetAttribute(mma_gemm<1>, cudaFuncAttributeMaxDynamicSharedMemorySize, GEMM_SMEM);
    cudaFuncSetAttribute(mma_gemm<2>, cudaFuncAttributeMaxDynamicSharedMemorySize, GEMM_SMEM);
    cudaFuncSetAttribute(mma_gemm<3>, cudaFuncAttributeMaxDynamicSharedMemorySize, GEMM_SMEM);

    dim3 gP(DD/128, BS/128);    // (4, 32)
    dim3 gQKV(DD/128, BS/128, 3);
    dim3 gF1(DI/128, BS/128);   // (16, 32)

    // launch order: build_x(1), cvt_all(2), gemm_qkv(3), k_attn_tc(4) <- ncu capture slot
    k_build_x<<<BS, 128>>>(toks, cond, emb, pos, cW1, cb1, cW2, cb2, nullc, ttc);
    cvt_all<<<dim3(8, 4, NL*3 + 24), 256>>>(Wq, Wk, Wv, E);

    for (int l = 0; l < NL; l++) {
        size_t wo = (size_t)l*DD*DD, w1 = (size_t)l*DD*DI;
        gemm_qkv<<<gQKV, 256, GEMM_SMEM>>>(bq, bk, bv, l);
        k_attn_tc<<<ATT_CTAS, 256, ATT_SMEM>>>(peh + (size_t)l*SS*DHD, pel + (size_t)l*SS*DHD, l);
        if (l == 0) {
            cvt_w<<<dim3(8, 4, NL),  256>>>(Wo,  oh,  ol,  DD, DD);
            cvt_w<<<dim3(8, 16, NL), 256>>>(fW1, f1h, f1l, DD, DI);
            cvt_w<<<dim3(32, 4, NL), 256>>>(fW2, f2h, f2l, DI, DD);
            cvt_w<<<dim3(8, 4, 1),   256>>>(fcW, fch, fcl, DD, VV);
        }
        mma_gemm<1><<<gP, 256, GEMM_SMEM>>>(ah, al, oh+wo, ol+wo, bo+l*DD, px, pres, nullptr, nullptr, DD, DD, nullptr, nullptr);
        k_ln<<<BS, 128>>>(pres, pout1, ln1g + l*DD, ln1b + l*DD, o1h, o1l);
        mma_gemm<2><<<gF1, 256, GEMM_SMEM>>>(o1h, o1l, f1h+w1, f1l+w1, fb1+l*DI, nullptr, nullptr, hh, hl, DD, DI, ttcW, ttcb);
        mma_gemm<1><<<gP, 256, GEMM_SMEM>>>(hh, hl, f2h+w1, f2l+w1, fb2+l*DD, pout1, pres, nullptr, nullptr, DI, DD, nullptr, nullptr);
        k_ln<<<BS, 128>>>(pres, px, ln2g + l*DD, ln2b + l*DD, xh, xl);
    }
    mma_gemm<3><<<dim3(VV/128, BS/128), 256, GEMM_SMEM>>>(xh, xl, fch, fcl, fcb, nullptr, out, nullptr, nullptr, DD, VV, nullptr, nullptr);
}